// round 1
// baseline (speedup 1.0000x reference)
#include <cuda_runtime.h>
#include <cstdint>
#include <math.h>

// ---------------------------------------------------------------------------
// Problem constants
// ---------------------------------------------------------------------------
#define BB 8192
#define NN 64
#define CC 8
#define DD (NN * CC)        // 512
#define HP 1024
#define HS 512
#define BD_ELEMS (BB * DD)  // 4,194,304
#define BN_ELEMS (BB * NN)  // 524,288

// Scratch (allocation-free: __device__ globals)
__device__ float g_bufA[BB * HP];
__device__ float g_bufB[BB * HP];

// ---------------------------------------------------------------------------
// Threefry-2x32-20 (JAX), usable at compile time (host) and runtime (device)
// ---------------------------------------------------------------------------
struct TFK { unsigned a, b; };

__host__ __device__ constexpr unsigned tf_rotl(unsigned v, int r) {
    return (v << r) | (v >> (32 - r));
}

__host__ __device__ constexpr TFK tf2x32(unsigned k0, unsigned k1,
                                         unsigned x0, unsigned x1) {
    unsigned k2 = k0 ^ k1 ^ 0x1BD11BDAu;
    x0 += k0; x1 += k1;
    // group 1: rotations {13,15,26,6}
    x0 += x1; x1 = tf_rotl(x1, 13); x1 ^= x0;
    x0 += x1; x1 = tf_rotl(x1, 15); x1 ^= x0;
    x0 += x1; x1 = tf_rotl(x1, 26); x1 ^= x0;
    x0 += x1; x1 = tf_rotl(x1,  6); x1 ^= x0;
    x0 += k1; x1 += k2 + 1u;
    // group 2: {17,29,16,24}
    x0 += x1; x1 = tf_rotl(x1, 17); x1 ^= x0;
    x0 += x1; x1 = tf_rotl(x1, 29); x1 ^= x0;
    x0 += x1; x1 = tf_rotl(x1, 16); x1 ^= x0;
    x0 += x1; x1 = tf_rotl(x1, 24); x1 ^= x0;
    x0 += k2; x1 += k0 + 2u;
    // group 3
    x0 += x1; x1 = tf_rotl(x1, 13); x1 ^= x0;
    x0 += x1; x1 = tf_rotl(x1, 15); x1 ^= x0;
    x0 += x1; x1 = tf_rotl(x1, 26); x1 ^= x0;
    x0 += x1; x1 = tf_rotl(x1,  6); x1 ^= x0;
    x0 += k0; x1 += k1 + 3u;
    // group 4
    x0 += x1; x1 = tf_rotl(x1, 17); x1 ^= x0;
    x0 += x1; x1 = tf_rotl(x1, 29); x1 ^= x0;
    x0 += x1; x1 = tf_rotl(x1, 16); x1 ^= x0;
    x0 += x1; x1 = tf_rotl(x1, 24); x1 ^= x0;
    x0 += k1; x1 += k2 + 4u;
    // group 5
    x0 += x1; x1 = tf_rotl(x1, 13); x1 ^= x0;
    x0 += x1; x1 = tf_rotl(x1, 15); x1 ^= x0;
    x0 += x1; x1 = tf_rotl(x1, 26); x1 ^= x0;
    x0 += x1; x1 = tf_rotl(x1,  6); x1 ^= x0;
    x0 += k2; x1 += k0 + 5u;
    return TFK{x0, x1};
}

// jax.random.key(42) -> (0, 42); split(key, 3) fold-like: key_i = threefry(key, [0, i])
constexpr unsigned KA0 = tf2x32(0u, 42u, 0u, 0u).a;
constexpr unsigned KA1 = tf2x32(0u, 42u, 0u, 0u).b;
constexpr unsigned KB0 = tf2x32(0u, 42u, 0u, 1u).a;
constexpr unsigned KB1 = tf2x32(0u, 42u, 0u, 1u).b;
constexpr unsigned KG0 = tf2x32(0u, 42u, 0u, 2u).a;
constexpr unsigned KG1 = tf2x32(0u, 42u, 0u, 2u).b;

// partitionable random_bits(32): element i -> x0f ^ x1f of threefry(key, [0, i])
// uniform(minval=1e-8, maxval=1.0): note (1.0f - 1e-8f) == 1.0f exactly in fp32
__device__ __forceinline__ float jax_u01(unsigned k0, unsigned k1, unsigned idx) {
    TFK r = tf2x32(k0, k1, 0u, idx);
    unsigned bits = r.a ^ r.b;
    float f = __uint_as_float((bits >> 9) | 0x3f800000u) - 1.0f;
    f = f + 1e-8f;                    // f * (maxval-minval) + minval, mm == 1.0f
    return fmaxf(1e-8f, f);
}

// ---------------------------------------------------------------------------
// SGEMM: C[M,N] = epi(A[M,K] @ B[K,N] + bias[N])
// BM=128, BN=64, BK=16, 256 threads, 8x4 register tile.
// All dims here are multiples of the tile sizes (no bounds checks needed).
// EPI: 0 = none, 1 = relu, 2 = sigmoid
// ---------------------------------------------------------------------------
template <int EPI>
__global__ void __launch_bounds__(256)
sgemm_kernel(const float* __restrict__ A, const float* __restrict__ B,
             const float* __restrict__ bias, float* __restrict__ C,
             int M, int N, int K) {
    __shared__ float As[16][128];
    __shared__ float Bs[16][64];

    const int tid = threadIdx.x;
    const int tx = tid & 15;   // 16 cols of threads (BN dir, TN=4)
    const int ty = tid >> 4;   // 16 rows of threads (BM dir, TM=8)
    const int bm0 = blockIdx.y * 128;
    const int bn0 = blockIdx.x * 64;

    float acc[8][4];
#pragma unroll
    for (int i = 0; i < 8; i++)
#pragma unroll
        for (int j = 0; j < 4; j++) acc[i][j] = 0.0f;

    const int nk = K >> 4;
    for (int kt = 0; kt < nk; kt++) {
        // Load A tile (128x16) transposed into As[16][128]
#pragma unroll
        for (int l = 0; l < 2; l++) {
            int f = tid + l * 256;            // float4 index in [0,512)
            int row = f >> 2;                 // [0,128)
            int c4 = (f & 3) << 2;            // {0,4,8,12}
            float4 v = *reinterpret_cast<const float4*>(
                A + (size_t)(bm0 + row) * K + (kt << 4) + c4);
            As[c4 + 0][row] = v.x;
            As[c4 + 1][row] = v.y;
            As[c4 + 2][row] = v.z;
            As[c4 + 3][row] = v.w;
        }
        // Load B tile (16x64)
        {
            int row = tid >> 4;               // [0,16)
            int col = (tid & 15) << 2;        // [0,64)
            float4 v = *reinterpret_cast<const float4*>(
                B + (size_t)((kt << 4) + row) * N + bn0 + col);
            *reinterpret_cast<float4*>(&Bs[row][col]) = v;
        }
        __syncthreads();

#pragma unroll
        for (int k = 0; k < 16; k++) {
            float4 a0 = *reinterpret_cast<const float4*>(&As[k][ty * 8]);
            float4 a1 = *reinterpret_cast<const float4*>(&As[k][ty * 8 + 4]);
            float4 bv = *reinterpret_cast<const float4*>(&Bs[k][tx * 4]);
            float a[8] = {a0.x, a0.y, a0.z, a0.w, a1.x, a1.y, a1.z, a1.w};
            float bb[4] = {bv.x, bv.y, bv.z, bv.w};
#pragma unroll
            for (int i = 0; i < 8; i++)
#pragma unroll
                for (int j = 0; j < 4; j++)
                    acc[i][j] = fmaf(a[i], bb[j], acc[i][j]);
        }
        __syncthreads();
    }

    float4 bvec = *reinterpret_cast<const float4*>(bias + bn0 + tx * 4);
    float bias4[4] = {bvec.x, bvec.y, bvec.z, bvec.w};
#pragma unroll
    for (int i = 0; i < 8; i++) {
        float4 v;
        float* vp = &v.x;
#pragma unroll
        for (int j = 0; j < 4; j++) {
            float c = acc[i][j] + bias4[j];
            if (EPI == 1) c = fmaxf(c, 0.0f);
            if (EPI == 2) c = 1.0f / (1.0f + expf(-c));
            vp[j] = c;
        }
        *reinterpret_cast<float4*>(
            C + (size_t)(bm0 + ty * 8 + i) * N + bn0 + tx * 4) = v;
    }
}

// ---------------------------------------------------------------------------
// Fused elementwise tail: probs (Bernoulli relax), gumbel-softmax, parent/child
// coupling, causal masks, final mixture. One block per b, one thread per n.
// ---------------------------------------------------------------------------
__device__ __forceinline__ void gs8(const float* l, const float* g, float* xt) {
    // pr = softmax(l); pr = 0.9*pr + 0.0125; xt = softmax((log(pr)+g)/0.7)
    float m = l[0];
#pragma unroll
    for (int c = 1; c < 8; c++) m = fmaxf(m, l[c]);
    float e[8], s = 0.0f;
#pragma unroll
    for (int c = 0; c < 8; c++) { e[c] = expf(l[c] - m); s += e[c]; }
    float t[8];
#pragma unroll
    for (int c = 0; c < 8; c++) {
        float pr = e[c] / s;
        pr = 0.9f * pr + 0.0125f;
        t[c] = (logf(pr) + g[c]) / 0.7f;
    }
    float m2 = t[0];
#pragma unroll
    for (int c = 1; c < 8; c++) m2 = fmaxf(m2, t[c]);
    float e2[8], s2 = 0.0f;
#pragma unroll
    for (int c = 0; c < 8; c++) { e2[c] = expf(t[c] - m2); s2 += e2[c]; }
#pragma unroll
    for (int c = 0; c < 8; c++) xt[c] = e2[c] / s2;
}

__global__ void finalize_kernel(const float* __restrict__ x,
                                const float* __restrict__ Pm,
                                const float* __restrict__ W,
                                float* __restrict__ xcf) {
    const int b = blockIdx.x;
    const int n = threadIdx.x;   // 64 threads
    __shared__ float sh_cst, sh_incr;

    const size_t base = (size_t)b * DD + n * CC;
    float4 xa = *reinterpret_cast<const float4*>(x + base);
    float4 xb = *reinterpret_cast<const float4*>(x + base + 4);
    float4 wa = *reinterpret_cast<const float4*>(W + base);
    float4 wb = *reinterpret_cast<const float4*>(W + base + 4);
    float xv[8] = {xa.x, xa.y, xa.z, xa.w, xb.x, xb.y, xb.z, xb.w};
    float Wv[8] = {wa.x, wa.y, wa.z, wa.w, wb.x, wb.y, wb.z, wb.w};

    const unsigned i = (unsigned)(b * NN + n);
    const float P = Pm[i];

    float ua = jax_u01(KA0, KA1, i);
    float ub = jax_u01(KB0, KB1, i);
    float ea = expf(-logf(-logf(ua)));
    float eb = expf(-logf(-logf(ub)));
    float no = P * ea / 0.7f;
    float de = no + (1.0f - P) * eb / 0.7f;
    float probs = no / de;

    float g[8];
#pragma unroll
    for (int c = 0; c < 8; c++) {
        float u = jax_u01(KG0, KG1, i * 8u + (unsigned)c);
        g[c] = -logf(-logf(u));
    }

    // curr = argmax over one-hot x row (first max)
    int curr = 0;
    {
        float m = xv[0];
#pragma unroll
        for (int c = 1; c < 8; c++)
            if (xv[c] > m) { m = xv[c]; curr = c; }
    }

    // --- Phase 1: PARENT (n==2) computes const/incr flags ---
    if (n == 2) {
        float xt_par[8];
        gs8(Wv, g, xt_par);   // addmask at PARENT row is 0
        int am = 0;
        float m = probs * xt_par[0] + (1.0f - probs) * xv[0];
#pragma unroll
        for (int c = 1; c < 8; c++) {
            float v = probs * xt_par[c] + (1.0f - probs) * xv[c];
            if (v > m) { m = v; am = c; }
        }
        int diff = am - curr;
        sh_cst  = (diff == 0) ? 1.0f : 0.0f;
        sh_incr = (diff >  0) ? 1.0f : 0.0f;
    }
    __syncthreads();
    const float cst = sh_cst;
    const float incr = sh_incr;

    // --- Phase 2: masks, gumbel-softmax, mixture ---
    float l[8];
    if (n == 0 || n == 5 || n == 10) {
#pragma unroll
        for (int c = 0; c < 8; c++) l[c] = Wv[c] + ((c < curr) ? -100.0f : 1.0f);
    } else if (n == 7) {
        const int thr = curr + 1;   // REL_TYPE == 0
        const bool inc = (incr > 0.5f);
#pragma unroll
        for (int c = 0; c < 8; c++)
            l[c] = Wv[c] + ((inc && c < thr) ? -100.0f : 1.0f);
    } else {
#pragma unroll
        for (int c = 0; c < 8; c++) l[c] = Wv[c];
    }

    float xt[8];
    gs8(l, g, xt);

    float p2 = probs;
    if (n == 7) {
        float pc = probs * (1.0f - cst);
        pc = pc + incr;
        p2 = fminf(fmaxf(pc, 0.0f), 1.0f);
    }

    float4 oa, ob;
    float* op = &oa.x;
#pragma unroll
    for (int c = 0; c < 4; c++) op[c] = p2 * xt[c] + (1.0f - p2) * xv[c];
    op = &ob.x;
#pragma unroll
    for (int c = 0; c < 4; c++) op[c] = p2 * xt[c + 4] + (1.0f - p2) * xv[c + 4];
    *reinterpret_cast<float4*>(xcf + base) = oa;
    *reinterpret_cast<float4*>(xcf + base + 4) = ob;
}

// ---------------------------------------------------------------------------
// Launch
// ---------------------------------------------------------------------------
extern "C" void kernel_launch(void* const* d_in, const int* in_sizes, int n_in,
                              void* d_out, int out_size) {
    const float* x     = (const float*)d_in[0];
    const float* truth = (const float*)d_in[1];
    const float* sw1   = (const float*)d_in[2];
    const float* sb1   = (const float*)d_in[3];
    const float* sw2   = (const float*)d_in[4];
    const float* sb2   = (const float*)d_in[5];
    const float* pw1   = (const float*)d_in[6];
    const float* pb1   = (const float*)d_in[7];
    const float* pw2   = (const float*)d_in[8];
    const float* pb2   = (const float*)d_in[9];
    const float* pw3   = (const float*)d_in[10];
    const float* pb3   = (const float*)d_in[11];
    const float* pw4   = (const float*)d_in[12];
    const float* pb4   = (const float*)d_in[13];

    float* out       = (float*)d_out;
    float* out_truth = out;
    float* out_xcf   = out + BD_ELEMS;
    float* out_P     = out + 2 * (size_t)BD_ELEMS;
    float* out_W     = out + 2 * (size_t)BD_ELEMS + BN_ELEMS;

    float *bufA = nullptr, *bufB = nullptr;
    cudaGetSymbolAddress((void**)&bufA, g_bufA);
    cudaGetSymbolAddress((void**)&bufB, g_bufB);

    const dim3 blk(256);
    // Selector path
    sgemm_kernel<1><<<dim3(HS / 64, BB / 128), blk>>>(x, sw1, sb1, bufA, BB, HS, DD);
    sgemm_kernel<2><<<dim3(NN / 64, BB / 128), blk>>>(bufA, sw2, sb2, out_P, BB, NN, HS);
    // MLP path
    sgemm_kernel<1><<<dim3(HP / 64, BB / 128), blk>>>(x,    pw1, pb1, bufB, BB, HP, DD);
    sgemm_kernel<1><<<dim3(HP / 64, BB / 128), blk>>>(bufB, pw2, pb2, bufA, BB, HP, HP);
    sgemm_kernel<1><<<dim3(HP / 64, BB / 128), blk>>>(bufA, pw3, pb3, bufB, BB, HP, HP);
    sgemm_kernel<0><<<dim3(DD / 64, BB / 128), blk>>>(bufB, pw4, pb4, out_W, BB, DD, HP);
    // truth_x passthrough
    cudaMemcpyAsync(out_truth, truth, (size_t)BD_ELEMS * sizeof(float),
                    cudaMemcpyDeviceToDevice);
    // Fused tail
    finalize_kernel<<<BB, NN>>>(x, out_P, out_W, out_xcf);
}

// round 2
// speedup vs baseline: 1.0169x; 1.0169x over previous
#include <cuda_runtime.h>
#include <cstdint>
#include <math.h>

// ---------------------------------------------------------------------------
// Problem constants
// ---------------------------------------------------------------------------
#define BB 8192
#define NN 64
#define CC 8
#define DD (NN * CC)        // 512
#define HP 1024
#define HS 512
#define BD_ELEMS (BB * DD)  // 4,194,304
#define BN_ELEMS (BB * NN)  // 524,288

// Scratch (allocation-free: __device__ globals)
__device__ float g_bufA[BB * HP];
__device__ float g_bufB[BB * HP];
__device__ unsigned char g_idx[BB * NN];

// ---------------------------------------------------------------------------
// Threefry-2x32-20 (JAX), usable at compile time (host) and runtime (device)
// ---------------------------------------------------------------------------
struct TFK { unsigned a, b; };

__host__ __device__ constexpr unsigned tf_rotl(unsigned v, int r) {
    return (v << r) | (v >> (32 - r));
}

__host__ __device__ constexpr TFK tf2x32(unsigned k0, unsigned k1,
                                         unsigned x0, unsigned x1) {
    unsigned k2 = k0 ^ k1 ^ 0x1BD11BDAu;
    x0 += k0; x1 += k1;
    x0 += x1; x1 = tf_rotl(x1, 13); x1 ^= x0;
    x0 += x1; x1 = tf_rotl(x1, 15); x1 ^= x0;
    x0 += x1; x1 = tf_rotl(x1, 26); x1 ^= x0;
    x0 += x1; x1 = tf_rotl(x1,  6); x1 ^= x0;
    x0 += k1; x1 += k2 + 1u;
    x0 += x1; x1 = tf_rotl(x1, 17); x1 ^= x0;
    x0 += x1; x1 = tf_rotl(x1, 29); x1 ^= x0;
    x0 += x1; x1 = tf_rotl(x1, 16); x1 ^= x0;
    x0 += x1; x1 = tf_rotl(x1, 24); x1 ^= x0;
    x0 += k2; x1 += k0 + 2u;
    x0 += x1; x1 = tf_rotl(x1, 13); x1 ^= x0;
    x0 += x1; x1 = tf_rotl(x1, 15); x1 ^= x0;
    x0 += x1; x1 = tf_rotl(x1, 26); x1 ^= x0;
    x0 += x1; x1 = tf_rotl(x1,  6); x1 ^= x0;
    x0 += k0; x1 += k1 + 3u;
    x0 += x1; x1 = tf_rotl(x1, 17); x1 ^= x0;
    x0 += x1; x1 = tf_rotl(x1, 29); x1 ^= x0;
    x0 += x1; x1 = tf_rotl(x1, 16); x1 ^= x0;
    x0 += x1; x1 = tf_rotl(x1, 24); x1 ^= x0;
    x0 += k1; x1 += k2 + 4u;
    x0 += x1; x1 = tf_rotl(x1, 13); x1 ^= x0;
    x0 += x1; x1 = tf_rotl(x1, 15); x1 ^= x0;
    x0 += x1; x1 = tf_rotl(x1, 26); x1 ^= x0;
    x0 += x1; x1 = tf_rotl(x1,  6); x1 ^= x0;
    x0 += k2; x1 += k0 + 5u;
    return TFK{x0, x1};
}

constexpr unsigned KA0 = tf2x32(0u, 42u, 0u, 0u).a;
constexpr unsigned KA1 = tf2x32(0u, 42u, 0u, 0u).b;
constexpr unsigned KB0 = tf2x32(0u, 42u, 0u, 1u).a;
constexpr unsigned KB1 = tf2x32(0u, 42u, 0u, 1u).b;
constexpr unsigned KG0 = tf2x32(0u, 42u, 0u, 2u).a;
constexpr unsigned KG1 = tf2x32(0u, 42u, 0u, 2u).b;

__device__ __forceinline__ float jax_u01(unsigned k0, unsigned k1, unsigned idx) {
    TFK r = tf2x32(k0, k1, 0u, idx);
    unsigned bits = r.a ^ r.b;
    float f = __uint_as_float((bits >> 9) | 0x3f800000u) - 1.0f;
    f = f + 1e-8f;
    return fmaxf(1e-8f, f);
}

// ---------------------------------------------------------------------------
// Packed f32x2 helpers (sm_103a)
// ---------------------------------------------------------------------------
typedef unsigned long long ull;

__device__ __forceinline__ ull pack2(float lo, float hi) {
    ull r;
    asm("mov.b64 %0, {%1, %2};" : "=l"(r) : "f"(lo), "f"(hi));
    return r;
}
__device__ __forceinline__ void unpack2(ull v, float& lo, float& hi) {
    asm("mov.b64 {%0, %1}, %2;" : "=f"(lo), "=f"(hi) : "l"(v));
}
__device__ __forceinline__ ull ffma2(ull a, ull b, ull c) {
    ull d;
    asm("fma.rn.f32x2 %0, %1, %2, %3;" : "=l"(d) : "l"(a), "l"(b), "l"(c));
    return d;
}

// ---------------------------------------------------------------------------
// FFMA2 SGEMM: C[M,N] = epi(A[M,K] @ B[K,N] + bias[N])
// BM=128, BN=128, BK=16, 256 threads, 8x8 register tile, accumulators packed
// as f32x2 pairs along M. Dims must be multiples of tile sizes.
// EPI: 0 = none, 1 = relu
// ---------------------------------------------------------------------------
template <int EPI>
__global__ void __launch_bounds__(256, 2)
sgemm2_kernel(const float* __restrict__ A, const float* __restrict__ B,
              const float* __restrict__ bias, float* __restrict__ C,
              int M, int N, int K) {
    __shared__ float As[16][128];   // As[k][m] (transposed)
    __shared__ float Bs[16][128];   // Bs[k][n]

    const int tid = threadIdx.x;
    const int tx = tid & 15;   // 16 thread-cols (N dir, TN=8)
    const int ty = tid >> 4;   // 16 thread-rows (M dir, TM=8 -> 4 m-pairs)
    const int bm0 = blockIdx.y * 128;
    const int bn0 = blockIdx.x * 128;

    ull acc[4][8];
#pragma unroll
    for (int p = 0; p < 4; p++)
#pragma unroll
        for (int j = 0; j < 8; j++) acc[p][j] = 0ull;

    const int nk = K >> 4;
    for (int kt = 0; kt < nk; kt++) {
        // Load A tile (128 rows x 16 k) transposed into As[16][128]
#pragma unroll
        for (int l = 0; l < 2; l++) {
            int f = tid + l * 256;            // float4 idx in [0,512)
            int row = f >> 2;                 // m in [0,128)
            int c4 = (f & 3) << 2;            // k base {0,4,8,12}
            float4 v = *reinterpret_cast<const float4*>(
                A + (size_t)(bm0 + row) * K + (kt << 4) + c4);
            As[c4 + 0][row] = v.x;
            As[c4 + 1][row] = v.y;
            As[c4 + 2][row] = v.z;
            As[c4 + 3][row] = v.w;
        }
        // Load B tile (16 k x 128 n)
#pragma unroll
        for (int l = 0; l < 2; l++) {
            int f = tid + l * 256;            // float4 idx in [0,512)
            int row = f >> 5;                 // k in [0,16)
            int col = (f & 31) << 2;          // n in [0,128)
            float4 v = *reinterpret_cast<const float4*>(
                B + (size_t)((kt << 4) + row) * N + bn0 + col);
            *reinterpret_cast<float4*>(&Bs[row][col]) = v;
        }
        __syncthreads();

#pragma unroll
        for (int k = 0; k < 16; k++) {
            const ulonglong2* ap2 =
                reinterpret_cast<const ulonglong2*>(&As[k][ty * 8]);
            ulonglong2 a01 = ap2[0];
            ulonglong2 a23 = ap2[1];
            ull ap[4] = {a01.x, a01.y, a23.x, a23.y};

            float4 bx = *reinterpret_cast<const float4*>(&Bs[k][tx * 8]);
            float4 by = *reinterpret_cast<const float4*>(&Bs[k][tx * 8 + 4]);
            ull bb[8];
            bb[0] = pack2(bx.x, bx.x); bb[1] = pack2(bx.y, bx.y);
            bb[2] = pack2(bx.z, bx.z); bb[3] = pack2(bx.w, bx.w);
            bb[4] = pack2(by.x, by.x); bb[5] = pack2(by.y, by.y);
            bb[6] = pack2(by.z, by.z); bb[7] = pack2(by.w, by.w);
#pragma unroll
            for (int p = 0; p < 4; p++)
#pragma unroll
                for (int j = 0; j < 8; j++)
                    acc[p][j] = ffma2(ap[p], bb[j], acc[p][j]);
        }
        __syncthreads();
    }

    // Epilogue: bias + activation, store. Pair p covers rows (2p, 2p+1).
    float4 bv0 = *reinterpret_cast<const float4*>(bias + bn0 + tx * 8);
    float4 bv1 = *reinterpret_cast<const float4*>(bias + bn0 + tx * 8 + 4);
    float bias8[8] = {bv0.x, bv0.y, bv0.z, bv0.w, bv1.x, bv1.y, bv1.z, bv1.w};
#pragma unroll
    for (int p = 0; p < 4; p++) {
        float lo[8], hi[8];
#pragma unroll
        for (int j = 0; j < 8; j++) {
            float l, h;
            unpack2(acc[p][j], l, h);
            l += bias8[j]; h += bias8[j];
            if (EPI == 1) { l = fmaxf(l, 0.0f); h = fmaxf(h, 0.0f); }
            lo[j] = l; hi[j] = h;
        }
        size_t r0 = (size_t)(bm0 + ty * 8 + 2 * p) * N + bn0 + tx * 8;
        size_t r1 = r0 + N;
        *reinterpret_cast<float4*>(C + r0)     = make_float4(lo[0], lo[1], lo[2], lo[3]);
        *reinterpret_cast<float4*>(C + r0 + 4) = make_float4(lo[4], lo[5], lo[6], lo[7]);
        *reinterpret_cast<float4*>(C + r1)     = make_float4(hi[0], hi[1], hi[2], hi[3]);
        *reinterpret_cast<float4*>(C + r1 + 4) = make_float4(hi[4], hi[5], hi[6], hi[7]);
    }
}

// ---------------------------------------------------------------------------
// Scalar SGEMM (round-1 kernel) kept for the small N=64 selector GEMM.
// BM=128, BN=64, BK=16, 256 threads, 8x4 tile. EPI: 2 = sigmoid
// ---------------------------------------------------------------------------
template <int EPI>
__global__ void __launch_bounds__(256)
sgemm_kernel(const float* __restrict__ A, const float* __restrict__ B,
             const float* __restrict__ bias, float* __restrict__ C,
             int M, int N, int K) {
    __shared__ float As[16][128];
    __shared__ float Bs[16][64];

    const int tid = threadIdx.x;
    const int tx = tid & 15;
    const int ty = tid >> 4;
    const int bm0 = blockIdx.y * 128;
    const int bn0 = blockIdx.x * 64;

    float acc[8][4];
#pragma unroll
    for (int i = 0; i < 8; i++)
#pragma unroll
        for (int j = 0; j < 4; j++) acc[i][j] = 0.0f;

    const int nk = K >> 4;
    for (int kt = 0; kt < nk; kt++) {
#pragma unroll
        for (int l = 0; l < 2; l++) {
            int f = tid + l * 256;
            int row = f >> 2;
            int c4 = (f & 3) << 2;
            float4 v = *reinterpret_cast<const float4*>(
                A + (size_t)(bm0 + row) * K + (kt << 4) + c4);
            As[c4 + 0][row] = v.x;
            As[c4 + 1][row] = v.y;
            As[c4 + 2][row] = v.z;
            As[c4 + 3][row] = v.w;
        }
        {
            int row = tid >> 4;
            int col = (tid & 15) << 2;
            float4 v = *reinterpret_cast<const float4*>(
                B + (size_t)((kt << 4) + row) * N + bn0 + col);
            *reinterpret_cast<float4*>(&Bs[row][col]) = v;
        }
        __syncthreads();

#pragma unroll
        for (int k = 0; k < 16; k++) {
            float4 a0 = *reinterpret_cast<const float4*>(&As[k][ty * 8]);
            float4 a1 = *reinterpret_cast<const float4*>(&As[k][ty * 8 + 4]);
            float4 bv = *reinterpret_cast<const float4*>(&Bs[k][tx * 4]);
            float a[8] = {a0.x, a0.y, a0.z, a0.w, a1.x, a1.y, a1.z, a1.w};
            float bbv[4] = {bv.x, bv.y, bv.z, bv.w};
#pragma unroll
            for (int i = 0; i < 8; i++)
#pragma unroll
                for (int j = 0; j < 4; j++)
                    acc[i][j] = fmaf(a[i], bbv[j], acc[i][j]);
        }
        __syncthreads();
    }

    float4 bvec = *reinterpret_cast<const float4*>(bias + bn0 + tx * 4);
    float bias4[4] = {bvec.x, bvec.y, bvec.z, bvec.w};
#pragma unroll
    for (int i = 0; i < 8; i++) {
        float4 v;
        float* vp = &v.x;
#pragma unroll
        for (int j = 0; j < 4; j++) {
            float c = acc[i][j] + bias4[j];
            if (EPI == 1) c = fmaxf(c, 0.0f);
            if (EPI == 2) c = 1.0f / (1.0f + expf(-c));
            vp[j] = c;
        }
        *reinterpret_cast<float4*>(
            C + (size_t)(bm0 + ty * 8 + i) * N + bn0 + tx * 4) = v;
    }
}

// ---------------------------------------------------------------------------
// One-hot exploitation: layer 1 of both paths is a gather-sum of weight rows.
// ---------------------------------------------------------------------------
__global__ void __launch_bounds__(256)
idx_kernel(const float* __restrict__ x, unsigned char* __restrict__ idx) {
    int t = blockIdx.x * 256 + threadIdx.x;   // (b*NN + n)
    if (t >= BB * NN) return;
    const float* xp = x + (size_t)t * 8;
    float4 xa = *reinterpret_cast<const float4*>(xp);
    float4 xb = *reinterpret_cast<const float4*>(xp + 4);
    // x group is exact one-hot -> index = dot with [0..7]
    float v = xa.y + 2.f * xa.z + 3.f * xa.w +
              4.f * xb.x + 5.f * xb.y + 6.f * xb.z + 7.f * xb.w;
    idx[t] = (unsigned char)(v + 0.5f);
}

#define G_TB 128
#define G_TW 16
#define G_PAD 20   // wsm row stride (floats): conflict-avoiding, 16B-aligned

__global__ void __launch_bounds__(256)
gather_l1_kernel(const unsigned char* __restrict__ idx,
                 const float* __restrict__ pw1, const float* __restrict__ pb1,
                 const float* __restrict__ sw1, const float* __restrict__ sb1,
                 float* __restrict__ h1, float* __restrict__ s1) {
    __shared__ unsigned char idx_sm[G_TB * 64];
    __shared__ float wsm[8 * G_PAD];

    const int tid = threadIdx.x;
    const int b0 = blockIdx.x * G_TB;
    const int cb = blockIdx.y;           // 0..63 -> pw1, 64..95 -> sel_w1
    const bool is_sel = (cb >= 64);
    const float* W   = is_sel ? sw1 : pw1;
    const float* bia = is_sel ? sb1 : pb1;
    const int ncols  = is_sel ? HS : HP;
    const int c0     = (is_sel ? (cb - 64) : cb) * G_TW;

    // stage idx block (128 rows x 64 n = 8KB) into smem
    {
        const uint4* src = reinterpret_cast<const uint4*>(idx + (size_t)b0 * NN);
        uint4* dst = reinterpret_cast<uint4*>(idx_sm);
        for (int t = tid; t < G_TB * NN / 16; t += 256) dst[t] = src[t];
    }

    const int r  = tid >> 1;             // row within block: 0..127
    const int cg = (tid & 1) * 8;        // col group: 0 or 8

    float acc[8] = {0.f, 0.f, 0.f, 0.f, 0.f, 0.f, 0.f, 0.f};
    __syncthreads();

    for (int n = 0; n < NN; n++) {
        // stage 8 candidate weight rows x 16 cols
        if (tid < 32) {
            int rr = tid >> 2;            // 0..7
            int cc = (tid & 3) * 4;       // 0,4,8,12
            *reinterpret_cast<float4*>(&wsm[rr * G_PAD + cc]) =
                *reinterpret_cast<const float4*>(
                    &W[(size_t)(n * 8 + rr) * ncols + c0 + cc]);
        }
        __syncthreads();
        int id = idx_sm[r * NN + n];
        const float* wp = &wsm[id * G_PAD + cg];
        float4 w0 = *reinterpret_cast<const float4*>(wp);
        float4 w1 = *reinterpret_cast<const float4*>(wp + 4);
        acc[0] += w0.x; acc[1] += w0.y; acc[2] += w0.z; acc[3] += w0.w;
        acc[4] += w1.x; acc[5] += w1.y; acc[6] += w1.z; acc[7] += w1.w;
        __syncthreads();
    }

    float* dst = is_sel ? s1 : h1;
    float4 bv0 = *reinterpret_cast<const float4*>(&bia[c0 + cg]);
    float4 bv1 = *reinterpret_cast<const float4*>(&bia[c0 + cg + 4]);
    float4 o0 = make_float4(fmaxf(acc[0] + bv0.x, 0.f), fmaxf(acc[1] + bv0.y, 0.f),
                            fmaxf(acc[2] + bv0.z, 0.f), fmaxf(acc[3] + bv0.w, 0.f));
    float4 o1 = make_float4(fmaxf(acc[4] + bv1.x, 0.f), fmaxf(acc[5] + bv1.y, 0.f),
                            fmaxf(acc[6] + bv1.z, 0.f), fmaxf(acc[7] + bv1.w, 0.f));
    size_t o = (size_t)(b0 + r) * ncols + c0 + cg;
    *reinterpret_cast<float4*>(dst + o)     = o0;
    *reinterpret_cast<float4*>(dst + o + 4) = o1;
}

// ---------------------------------------------------------------------------
// Fused elementwise tail (unchanged from round 1, verified correct)
// ---------------------------------------------------------------------------
__device__ __forceinline__ void gs8(const float* l, const float* g, float* xt) {
    float m = l[0];
#pragma unroll
    for (int c = 1; c < 8; c++) m = fmaxf(m, l[c]);
    float e[8], s = 0.0f;
#pragma unroll
    for (int c = 0; c < 8; c++) { e[c] = expf(l[c] - m); s += e[c]; }
    float t[8];
#pragma unroll
    for (int c = 0; c < 8; c++) {
        float pr = e[c] / s;
        pr = 0.9f * pr + 0.0125f;
        t[c] = (logf(pr) + g[c]) / 0.7f;
    }
    float m2 = t[0];
#pragma unroll
    for (int c = 1; c < 8; c++) m2 = fmaxf(m2, t[c]);
    float e2[8], s2 = 0.0f;
#pragma unroll
    for (int c = 0; c < 8; c++) { e2[c] = expf(t[c] - m2); s2 += e2[c]; }
#pragma unroll
    for (int c = 0; c < 8; c++) xt[c] = e2[c] / s2;
}

__global__ void finalize_kernel(const float* __restrict__ x,
                                const float* __restrict__ Pm,
                                const float* __restrict__ W,
                                float* __restrict__ xcf) {
    const int b = blockIdx.x;
    const int n = threadIdx.x;   // 64 threads
    __shared__ float sh_cst, sh_incr;

    const size_t base = (size_t)b * DD + n * CC;
    float4 xa = *reinterpret_cast<const float4*>(x + base);
    float4 xb = *reinterpret_cast<const float4*>(x + base + 4);
    float4 wa = *reinterpret_cast<const float4*>(W + base);
    float4 wb = *reinterpret_cast<const float4*>(W + base + 4);
    float xv[8] = {xa.x, xa.y, xa.z, xa.w, xb.x, xb.y, xb.z, xb.w};
    float Wv[8] = {wa.x, wa.y, wa.z, wa.w, wb.x, wb.y, wb.z, wb.w};

    const unsigned i = (unsigned)(b * NN + n);
    const float P = Pm[i];

    float ua = jax_u01(KA0, KA1, i);
    float ub = jax_u01(KB0, KB1, i);
    float ea = expf(-logf(-logf(ua)));
    float eb = expf(-logf(-logf(ub)));
    float no = P * ea / 0.7f;
    float de = no + (1.0f - P) * eb / 0.7f;
    float probs = no / de;

    float g[8];
#pragma unroll
    for (int c = 0; c < 8; c++) {
        float u = jax_u01(KG0, KG1, i * 8u + (unsigned)c);
        g[c] = -logf(-logf(u));
    }

    int curr = 0;
    {
        float m = xv[0];
#pragma unroll
        for (int c = 1; c < 8; c++)
            if (xv[c] > m) { m = xv[c]; curr = c; }
    }

    if (n == 2) {
        float xt_par[8];
        gs8(Wv, g, xt_par);
        int am = 0;
        float m = probs * xt_par[0] + (1.0f - probs) * xv[0];
#pragma unroll
        for (int c = 1; c < 8; c++) {
            float v = probs * xt_par[c] + (1.0f - probs) * xv[c];
            if (v > m) { m = v; am = c; }
        }
        int diff = am - curr;
        sh_cst  = (diff == 0) ? 1.0f : 0.0f;
        sh_incr = (diff >  0) ? 1.0f : 0.0f;
    }
    __syncthreads();
    const float cst = sh_cst;
    const float incr = sh_incr;

    float l[8];
    if (n == 0 || n == 5 || n == 10) {
#pragma unroll
        for (int c = 0; c < 8; c++) l[c] = Wv[c] + ((c < curr) ? -100.0f : 1.0f);
    } else if (n == 7) {
        const int thr = curr + 1;
        const bool inc = (incr > 0.5f);
#pragma unroll
        for (int c = 0; c < 8; c++)
            l[c] = Wv[c] + ((inc && c < thr) ? -100.0f : 1.0f);
    } else {
#pragma unroll
        for (int c = 0; c < 8; c++) l[c] = Wv[c];
    }

    float xt[8];
    gs8(l, g, xt);

    float p2 = probs;
    if (n == 7) {
        float pc = probs * (1.0f - cst);
        pc = pc + incr;
        p2 = fminf(fmaxf(pc, 0.0f), 1.0f);
    }

    float4 oa, ob;
    float* op = &oa.x;
#pragma unroll
    for (int c = 0; c < 4; c++) op[c] = p2 * xt[c] + (1.0f - p2) * xv[c];
    op = &ob.x;
#pragma unroll
    for (int c = 0; c < 4; c++) op[c] = p2 * xt[c + 4] + (1.0f - p2) * xv[c + 4];
    *reinterpret_cast<float4*>(xcf + base) = oa;
    *reinterpret_cast<float4*>(xcf + base + 4) = ob;
}

// ---------------------------------------------------------------------------
// Launch
// ---------------------------------------------------------------------------
extern "C" void kernel_launch(void* const* d_in, const int* in_sizes, int n_in,
                              void* d_out, int out_size) {
    const float* x     = (const float*)d_in[0];
    const float* truth = (const float*)d_in[1];
    const float* sw1   = (const float*)d_in[2];
    const float* sb1   = (const float*)d_in[3];
    const float* sw2   = (const float*)d_in[4];
    const float* sb2   = (const float*)d_in[5];
    const float* pw1   = (const float*)d_in[6];
    const float* pb1   = (const float*)d_in[7];
    const float* pw2   = (const float*)d_in[8];
    const float* pb2   = (const float*)d_in[9];
    const float* pw3   = (const float*)d_in[10];
    const float* pb3   = (const float*)d_in[11];
    const float* pw4   = (const float*)d_in[12];
    const float* pb4   = (const float*)d_in[13];

    float* out       = (float*)d_out;
    float* out_truth = out;
    float* out_xcf   = out + BD_ELEMS;
    float* out_P     = out + 2 * (size_t)BD_ELEMS;
    float* out_W     = out + 2 * (size_t)BD_ELEMS + BN_ELEMS;

    float *bufA = nullptr, *bufB = nullptr;
    unsigned char* idxp = nullptr;
    cudaGetSymbolAddress((void**)&bufA, g_bufA);
    cudaGetSymbolAddress((void**)&bufB, g_bufB);
    cudaGetSymbolAddress((void**)&idxp, g_idx);

    // Layer 1 (both paths) via one-hot gather: h1 -> bufB, s1 -> bufA
    idx_kernel<<<(BB * NN) / 256, 256>>>(x, idxp);
    gather_l1_kernel<<<dim3(BB / G_TB, (HP + HS) / G_TW), 256>>>(
        idxp, pw1, pb1, sw1, sb1, bufB, bufA);

    // Selector head: P = sigmoid(s1 @ sw2 + sb2)
    sgemm_kernel<2><<<dim3(NN / 64, BB / 128), 256>>>(bufA, sw2, sb2, out_P,
                                                      BB, NN, HS);
    // MLP layers 2-4 via packed f32x2 GEMM
    sgemm2_kernel<1><<<dim3(HP / 128, BB / 128), 256>>>(bufB, pw2, pb2, bufA,
                                                        BB, HP, HP);
    sgemm2_kernel<1><<<dim3(HP / 128, BB / 128), 256>>>(bufA, pw3, pb3, bufB,
                                                        BB, HP, HP);
    sgemm2_kernel<0><<<dim3(DD / 128, BB / 128), 256>>>(bufB, pw4, pb4, out_W,
                                                        BB, DD, HP);
    // truth_x passthrough
    cudaMemcpyAsync(out_truth, truth, (size_t)BD_ELEMS * sizeof(float),
                    cudaMemcpyDeviceToDevice);
    // Fused tail
    finalize_kernel<<<BB, NN>>>(x, out_P, out_W, out_xcf);
}

// round 4
// speedup vs baseline: 1.1816x; 1.1619x over previous
#include <cuda_runtime.h>
#include <cstdint>
#include <math.h>

// ---------------------------------------------------------------------------
// Problem constants
// ---------------------------------------------------------------------------
#define BB 8192
#define NN 64
#define CC 8
#define DD (NN * CC)        // 512
#define HP 1024
#define HS 512
#define BD_ELEMS (BB * DD)  // 4,194,304
#define BN_ELEMS (BB * NN)  // 524,288

// ---------------------------------------------------------------------------
// Scratch (allocation-free: __device__ globals)
// ---------------------------------------------------------------------------
__device__ float g_a_hi[BB * HP];
__device__ float g_a_lo[BB * HP];
__device__ float g_b_hi[BB * HP];
__device__ float g_b_lo[BB * HP];
__device__ float g_s1[BB * HS];

// Transposed + split weights, packed (Bt[n][k] layout):
#define OF_PW1 0
#define OF_SW1 524288
#define OF_PW2 786432
#define OF_PW3 1835008
#define OF_PW4 2883584
#define WT_TOTAL 3407872
__device__ float g_wt_hi[WT_TOTAL];
__device__ float g_wt_lo[WT_TOTAL];

// ---------------------------------------------------------------------------
// Threefry-2x32-20 (JAX)
// ---------------------------------------------------------------------------
struct TFK { unsigned a, b; };

__host__ __device__ constexpr unsigned tf_rotl(unsigned v, int r) {
    return (v << r) | (v >> (32 - r));
}

__host__ __device__ constexpr TFK tf2x32(unsigned k0, unsigned k1,
                                         unsigned x0, unsigned x1) {
    unsigned k2 = k0 ^ k1 ^ 0x1BD11BDAu;
    x0 += k0; x1 += k1;
    x0 += x1; x1 = tf_rotl(x1, 13); x1 ^= x0;
    x0 += x1; x1 = tf_rotl(x1, 15); x1 ^= x0;
    x0 += x1; x1 = tf_rotl(x1, 26); x1 ^= x0;
    x0 += x1; x1 = tf_rotl(x1,  6); x1 ^= x0;
    x0 += k1; x1 += k2 + 1u;
    x0 += x1; x1 = tf_rotl(x1, 17); x1 ^= x0;
    x0 += x1; x1 = tf_rotl(x1, 29); x1 ^= x0;
    x0 += x1; x1 = tf_rotl(x1, 16); x1 ^= x0;
    x0 += x1; x1 = tf_rotl(x1, 24); x1 ^= x0;
    x0 += k2; x1 += k0 + 2u;
    x0 += x1; x1 = tf_rotl(x1, 13); x1 ^= x0;
    x0 += x1; x1 = tf_rotl(x1, 15); x1 ^= x0;
    x0 += x1; x1 = tf_rotl(x1, 26); x1 ^= x0;
    x0 += x1; x1 = tf_rotl(x1,  6); x1 ^= x0;
    x0 += k0; x1 += k1 + 3u;
    x0 += x1; x1 = tf_rotl(x1, 17); x1 ^= x0;
    x0 += x1; x1 = tf_rotl(x1, 29); x1 ^= x0;
    x0 += x1; x1 = tf_rotl(x1, 16); x1 ^= x0;
    x0 += x1; x1 = tf_rotl(x1, 24); x1 ^= x0;
    x0 += k1; x1 += k2 + 4u;
    x0 += x1; x1 = tf_rotl(x1, 13); x1 ^= x0;
    x0 += x1; x1 = tf_rotl(x1, 15); x1 ^= x0;
    x0 += x1; x1 = tf_rotl(x1, 26); x1 ^= x0;
    x0 += x1; x1 = tf_rotl(x1,  6); x1 ^= x0;
    x0 += k2; x1 += k0 + 5u;
    return TFK{x0, x1};
}

constexpr unsigned KA0 = tf2x32(0u, 42u, 0u, 0u).a;
constexpr unsigned KA1 = tf2x32(0u, 42u, 0u, 0u).b;
constexpr unsigned KB0 = tf2x32(0u, 42u, 0u, 1u).a;
constexpr unsigned KB1 = tf2x32(0u, 42u, 0u, 1u).b;
constexpr unsigned KG0 = tf2x32(0u, 42u, 0u, 2u).a;
constexpr unsigned KG1 = tf2x32(0u, 42u, 0u, 2u).b;

__device__ __forceinline__ float jax_u01(unsigned k0, unsigned k1, unsigned idx) {
    TFK r = tf2x32(k0, k1, 0u, idx);
    unsigned bits = r.a ^ r.b;
    float f = __uint_as_float((bits >> 9) | 0x3f800000u) - 1.0f;
    f = f + 1e-8f;
    return fmaxf(1e-8f, f);
}

// ---------------------------------------------------------------------------
// Helpers
// ---------------------------------------------------------------------------
__device__ __forceinline__ uint32_t smem_u32(const void* p) {
    uint32_t a;
    asm("{ .reg .u64 t; cvta.to.shared.u64 t, %1; cvt.u32.u64 %0, t; }"
        : "=r"(a) : "l"(p));
    return a;
}

// round-to-tf32 (rna) — produces exactly-representable tf32 values
__device__ __forceinline__ float tf32r(float x) {
    unsigned u;
    asm("cvt.rna.tf32.f32 %0, %1;" : "=r"(u) : "f"(x));
    return __uint_as_float(u);
}

#define CP16(dst_u32, src_ptr) \
    asm volatile("cp.async.cg.shared.global [%0], [%1], 16;" \
                 :: "r"(dst_u32), "l"(src_ptr) : "memory")
#define CP_COMMIT() asm volatile("cp.async.commit_group;" ::: "memory")
#define CP_WAIT(n)  asm volatile("cp.async.wait_group %0;" :: "n"(n) : "memory")

// mma.sync m16n8k8 tf32: D += A*B (baseline PTX, no 'a' features)
__device__ __forceinline__ void mma8(float* d, const uint32_t* a,
                                     const uint32_t* b) {
    asm volatile(
        "mma.sync.aligned.m16n8k8.row.col.f32.tf32.tf32.f32 "
        "{%0,%1,%2,%3}, {%4,%5,%6,%7}, {%8,%9}, {%0,%1,%2,%3};"
        : "+f"(d[0]), "+f"(d[1]), "+f"(d[2]), "+f"(d[3])
        : "r"(a[0]), "r"(a[1]), "r"(a[2]), "r"(a[3]), "r"(b[0]), "r"(b[1]));
}

// ---------------------------------------------------------------------------
// mma.sync tf32 GEMM: O[M, Nout] = epi(A[M,K] @ Bt[Nout,K]^T + bias)
// BM=128, BN=128, BK=16, 256 threads, warp grid 2x4 (warp tile 64x32).
// A, B given as tf32-exact (hi, lo) pairs: O = Ah*Bh + Ah*Bl (+ Al*Bh).
//   AEX:   A exact in tf32 (one-hot x) -> no A_lo term
//   RELU:  relu epilogue
//   SPLIT: also emit tf32 (hi, lo) split of the output
// ---------------------------------------------------------------------------
#define PITCH 20                       // smem row pitch (floats): conflict-free
#define STAGE_F (4 * 128 * PITCH)      // 10240 floats / stage
#define OFF_AH 0
#define OFF_AL (128 * PITCH)
#define OFF_BH (2 * 128 * PITCH)
#define OFF_BL (3 * 128 * PITCH)
#define GEMM_SMEM (2 * STAGE_F * 4)    // 81920 bytes

template <bool AEX>
__device__ __forceinline__ void issue_chunk(
    uint32_t smb, int s, int c,
    const float* __restrict__ A_hi, const float* __restrict__ A_lo,
    const float* __restrict__ B_hi, const float* __restrict__ B_lo,
    int K, int bm0, int bn0, int tid) {
    const int k0 = c * 16;
    const uint32_t sb = smb + (uint32_t)(s * STAGE_F) * 4u;
#pragma unroll
    for (int i = 0; i < 2; i++) {
        const int f = tid + i * 256;       // float4 index in [0,512)
        const int row = f >> 2;
        const int q = f & 3;
        const uint32_t doff = (uint32_t)(row * PITCH + q * 4) * 4u;
        CP16(sb + OFF_AH * 4 + doff,
             A_hi + (size_t)(bm0 + row) * K + k0 + q * 4);
        if (!AEX)
            CP16(sb + OFF_AL * 4 + doff,
                 A_lo + (size_t)(bm0 + row) * K + k0 + q * 4);
        CP16(sb + OFF_BH * 4 + doff,
             B_hi + (size_t)(bn0 + row) * K + k0 + q * 4);
        CP16(sb + OFF_BL * 4 + doff,
             B_lo + (size_t)(bn0 + row) * K + k0 + q * 4);
    }
    CP_COMMIT();
}

template <bool AEX, bool RELU, bool SPLIT>
__global__ void __launch_bounds__(256)
gemm_mma(const float* __restrict__ A_hi, const float* __restrict__ A_lo,
         const float* __restrict__ Bt_hi, const float* __restrict__ Bt_lo,
         const float* __restrict__ bias,
         float* __restrict__ O_hi, float* __restrict__ O_lo,
         int K, int Nout) {
    extern __shared__ float sm[];
    const uint32_t smb = smem_u32(sm);
    const int tid = threadIdx.x;
    const int l = tid & 31;
    const int warp = tid >> 5;
    const int wm = warp >> 2;          // 0..1
    const int wn = warp & 3;           // 0..3
    const int bm0 = blockIdx.y * 128;
    const int bn0 = blockIdx.x * 128;
    const int NC = K >> 4;

    float acc[4][4][4];
#pragma unroll
    for (int mf = 0; mf < 4; mf++)
#pragma unroll
        for (int nf = 0; nf < 4; nf++)
#pragma unroll
            for (int r = 0; r < 4; r++) acc[mf][nf][r] = 0.0f;

    issue_chunk<AEX>(smb, 0, 0, A_hi, A_lo, Bt_hi, Bt_lo, K, bm0, bn0, tid);

    const int rA = l >> 2;             // groupID
    const int cK = l & 3;              // threadID in group

    for (int c = 0; c < NC; c++) {
        const int s = c & 1;
        if (c + 1 < NC) {
            issue_chunk<AEX>(smb, (c + 1) & 1, c + 1, A_hi, A_lo, Bt_hi,
                             Bt_lo, K, bm0, bn0, tid);
            CP_WAIT(1);
        } else {
            CP_WAIT(0);
        }
        __syncthreads();

        const float* st = sm + s * STAGE_F;
        const float* pAh = st + OFF_AH + (wm * 64 + rA) * PITCH;
        const float* pAl = st + OFF_AL + (wm * 64 + rA) * PITCH;
        const float* pBh = st + OFF_BH + (wn * 32 + rA) * PITCH;
        const float* pBl = st + OFF_BL + (wn * 32 + rA) * PITCH;

#pragma unroll
        for (int ks = 0; ks < 2; ks++) {
            const int kc = ks * 8 + cK;
            uint32_t ah[4][4], al[4][4], bh[4][2], bl[4][2];
#pragma unroll
            for (int mf = 0; mf < 4; mf++) {
                const float* p = pAh + mf * 16 * PITCH + kc;
                ah[mf][0] = __float_as_uint(p[0]);
                ah[mf][1] = __float_as_uint(p[8 * PITCH]);
                ah[mf][2] = __float_as_uint(p[4]);
                ah[mf][3] = __float_as_uint(p[8 * PITCH + 4]);
                if (!AEX) {
                    const float* q = pAl + mf * 16 * PITCH + kc;
                    al[mf][0] = __float_as_uint(q[0]);
                    al[mf][1] = __float_as_uint(q[8 * PITCH]);
                    al[mf][2] = __float_as_uint(q[4]);
                    al[mf][3] = __float_as_uint(q[8 * PITCH + 4]);
                }
            }
#pragma unroll
            for (int nf = 0; nf < 4; nf++) {
                const float* p = pBh + nf * 8 * PITCH + kc;
                bh[nf][0] = __float_as_uint(p[0]);
                bh[nf][1] = __float_as_uint(p[4]);
                const float* q = pBl + nf * 8 * PITCH + kc;
                bl[nf][0] = __float_as_uint(q[0]);
                bl[nf][1] = __float_as_uint(q[4]);
            }
            // term 1: Ah * Bh
#pragma unroll
            for (int mf = 0; mf < 4; mf++)
#pragma unroll
                for (int nf = 0; nf < 4; nf++)
                    mma8(acc[mf][nf], ah[mf], bh[nf]);
            // term 2: Ah * Bl
#pragma unroll
            for (int mf = 0; mf < 4; mf++)
#pragma unroll
                for (int nf = 0; nf < 4; nf++)
                    mma8(acc[mf][nf], ah[mf], bl[nf]);
            // term 3: Al * Bh
            if (!AEX) {
#pragma unroll
                for (int mf = 0; mf < 4; mf++)
#pragma unroll
                    for (int nf = 0; nf < 4; nf++)
                        mma8(acc[mf][nf], al[mf], bh[nf]);
            }
        }
        __syncthreads();
    }

    // ---- Epilogue ----
#pragma unroll
    for (int nf = 0; nf < 4; nf++) {
        const int col = bn0 + wn * 32 + nf * 8 + 2 * cK;
        const float2 bv = *reinterpret_cast<const float2*>(bias + col);
#pragma unroll
        for (int mf = 0; mf < 4; mf++) {
            const int ra = bm0 + wm * 64 + mf * 16 + rA;
            float y[4];
            y[0] = acc[mf][nf][0] + bv.x;
            y[1] = acc[mf][nf][1] + bv.y;
            y[2] = acc[mf][nf][2] + bv.x;
            y[3] = acc[mf][nf][3] + bv.y;
            if (RELU) {
#pragma unroll
                for (int r = 0; r < 4; r++) y[r] = fmaxf(y[r], 0.0f);
            }
            if (SPLIT) {
                float h[4], lo[4];
#pragma unroll
                for (int r = 0; r < 4; r++) {
                    h[r] = tf32r(y[r]);
                    lo[r] = tf32r(y[r] - h[r]);
                }
                *reinterpret_cast<float2*>(O_hi + (size_t)ra * Nout + col) =
                    make_float2(h[0], h[1]);
                *reinterpret_cast<float2*>(O_hi + (size_t)(ra + 8) * Nout + col) =
                    make_float2(h[2], h[3]);
                *reinterpret_cast<float2*>(O_lo + (size_t)ra * Nout + col) =
                    make_float2(lo[0], lo[1]);
                *reinterpret_cast<float2*>(O_lo + (size_t)(ra + 8) * Nout + col) =
                    make_float2(lo[2], lo[3]);
            } else {
                *reinterpret_cast<float2*>(O_hi + (size_t)ra * Nout + col) =
                    make_float2(y[0], y[1]);
                *reinterpret_cast<float2*>(O_hi + (size_t)(ra + 8) * Nout + col) =
                    make_float2(y[2], y[3]);
            }
        }
    }
}

// ---------------------------------------------------------------------------
// Weight transpose + tf32 split: Bt_hi/lo[n][k] = split(W[k][n])
// ---------------------------------------------------------------------------
__global__ void __launch_bounds__(256)
split_w_kernel(const float* __restrict__ W, float* __restrict__ bt_hi,
               float* __restrict__ bt_lo, int K, int N) {
    __shared__ float t[32][33];
    const int kb = blockIdx.x * 32;
    const int nb = blockIdx.y * 32;
    const int tx = threadIdx.x & 31;
    const int ty = threadIdx.x >> 5;
#pragma unroll
    for (int r = ty; r < 32; r += 8)
        t[r][tx] = W[(size_t)(kb + r) * N + nb + tx];
    __syncthreads();
#pragma unroll
    for (int r = ty; r < 32; r += 8) {
        float wv = t[tx][r];
        float hi = tf32r(wv);
        float lo = tf32r(wv - hi);
        size_t o = (size_t)(nb + r) * K + kb + tx;
        bt_hi[o] = hi;
        bt_lo[o] = lo;
    }
}

// ---------------------------------------------------------------------------
// Scalar SGEMM for the small selector head (N=64), sigmoid epilogue
// ---------------------------------------------------------------------------
__global__ void __launch_bounds__(256)
sgemm_sig_kernel(const float* __restrict__ A, const float* __restrict__ B,
                 const float* __restrict__ bias, float* __restrict__ C,
                 int M, int N, int K) {
    __shared__ float As[16][128];
    __shared__ float Bs[16][64];

    const int tid = threadIdx.x;
    const int tx = tid & 15;
    const int ty = tid >> 4;
    const int bm0 = blockIdx.y * 128;
    const int bn0 = blockIdx.x * 64;

    float acc[8][4];
#pragma unroll
    for (int i = 0; i < 8; i++)
#pragma unroll
        for (int j = 0; j < 4; j++) acc[i][j] = 0.0f;

    const int nk = K >> 4;
    for (int kt = 0; kt < nk; kt++) {
#pragma unroll
        for (int lq = 0; lq < 2; lq++) {
            int f = tid + lq * 256;
            int row = f >> 2;
            int c4 = (f & 3) << 2;
            float4 v = *reinterpret_cast<const float4*>(
                A + (size_t)(bm0 + row) * K + (kt << 4) + c4);
            As[c4 + 0][row] = v.x;
            As[c4 + 1][row] = v.y;
            As[c4 + 2][row] = v.z;
            As[c4 + 3][row] = v.w;
        }
        {
            int row = tid >> 4;
            int col = (tid & 15) << 2;
            float4 v = *reinterpret_cast<const float4*>(
                B + (size_t)((kt << 4) + row) * N + bn0 + col);
            *reinterpret_cast<float4*>(&Bs[row][col]) = v;
        }
        __syncthreads();

#pragma unroll
        for (int k = 0; k < 16; k++) {
            float4 a0 = *reinterpret_cast<const float4*>(&As[k][ty * 8]);
            float4 a1 = *reinterpret_cast<const float4*>(&As[k][ty * 8 + 4]);
            float4 bv = *reinterpret_cast<const float4*>(&Bs[k][tx * 4]);
            float a[8] = {a0.x, a0.y, a0.z, a0.w, a1.x, a1.y, a1.z, a1.w};
            float bbv[4] = {bv.x, bv.y, bv.z, bv.w};
#pragma unroll
            for (int i = 0; i < 8; i++)
#pragma unroll
                for (int j = 0; j < 4; j++)
                    acc[i][j] = fmaf(a[i], bbv[j], acc[i][j]);
        }
        __syncthreads();
    }

    float4 bvec = *reinterpret_cast<const float4*>(bias + bn0 + tx * 4);
    float bias4[4] = {bvec.x, bvec.y, bvec.z, bvec.w};
#pragma unroll
    for (int i = 0; i < 8; i++) {
        float4 v;
        float* vp = &v.x;
#pragma unroll
        for (int j = 0; j < 4; j++) {
            float c = acc[i][j] + bias4[j];
            vp[j] = 1.0f / (1.0f + expf(-c));
        }
        *reinterpret_cast<float4*>(
            C + (size_t)(bm0 + ty * 8 + i) * N + bn0 + tx * 4) = v;
    }
}

// ---------------------------------------------------------------------------
// Fused elementwise tail (verified rounds 1-2)
// ---------------------------------------------------------------------------
__device__ __forceinline__ void gs8(const float* l, const float* g, float* xt) {
    float m = l[0];
#pragma unroll
    for (int c = 1; c < 8; c++) m = fmaxf(m, l[c]);
    float e[8], s = 0.0f;
#pragma unroll
    for (int c = 0; c < 8; c++) { e[c] = expf(l[c] - m); s += e[c]; }
    float t[8];
#pragma unroll
    for (int c = 0; c < 8; c++) {
        float pr = e[c] / s;
        pr = 0.9f * pr + 0.0125f;
        t[c] = (logf(pr) + g[c]) / 0.7f;
    }
    float m2 = t[0];
#pragma unroll
    for (int c = 1; c < 8; c++) m2 = fmaxf(m2, t[c]);
    float e2[8], s2 = 0.0f;
#pragma unroll
    for (int c = 0; c < 8; c++) { e2[c] = expf(t[c] - m2); s2 += e2[c]; }
#pragma unroll
    for (int c = 0; c < 8; c++) xt[c] = e2[c] / s2;
}

__global__ void finalize_kernel(const float* __restrict__ x,
                                const float* __restrict__ Pm,
                                const float* __restrict__ W,
                                float* __restrict__ xcf) {
    const int b = blockIdx.x;
    const int n = threadIdx.x;   // 64 threads
    __shared__ float sh_cst, sh_incr;

    const size_t base = (size_t)b * DD + n * CC;
    float4 xa = *reinterpret_cast<const float4*>(x + base);
    float4 xb = *reinterpret_cast<const float4*>(x + base + 4);
    float4 wa = *reinterpret_cast<const float4*>(W + base);
    float4 wb = *reinterpret_cast<const float4*>(W + base + 4);
    float xv[8] = {xa.x, xa.y, xa.z, xa.w, xb.x, xb.y, xb.z, xb.w};
    float Wv[8] = {wa.x, wa.y, wa.z, wa.w, wb.x, wb.y, wb.z, wb.w};

    const unsigned i = (unsigned)(b * NN + n);
    const float P = Pm[i];

    float ua = jax_u01(KA0, KA1, i);
    float ub = jax_u01(KB0, KB1, i);
    float ea = expf(-logf(-logf(ua)));
    float eb = expf(-logf(-logf(ub)));
    float no = P * ea / 0.7f;
    float de = no + (1.0f - P) * eb / 0.7f;
    float probs = no / de;

    float g[8];
#pragma unroll
    for (int c = 0; c < 8; c++) {
        float u = jax_u01(KG0, KG1, i * 8u + (unsigned)c);
        g[c] = -logf(-logf(u));
    }

    int curr = 0;
    {
        float m = xv[0];
#pragma unroll
        for (int c = 1; c < 8; c++)
            if (xv[c] > m) { m = xv[c]; curr = c; }
    }

    if (n == 2) {
        float xt_par[8];
        gs8(Wv, g, xt_par);
        int am = 0;
        float m = probs * xt_par[0] + (1.0f - probs) * xv[0];
#pragma unroll
        for (int c = 1; c < 8; c++) {
            float v = probs * xt_par[c] + (1.0f - probs) * xv[c];
            if (v > m) { m = v; am = c; }
        }
        int diff = am - curr;
        sh_cst  = (diff == 0) ? 1.0f : 0.0f;
        sh_incr = (diff >  0) ? 1.0f : 0.0f;
    }
    __syncthreads();
    const float cst = sh_cst;
    const float incr = sh_incr;

    float l[8];
    if (n == 0 || n == 5 || n == 10) {
#pragma unroll
        for (int c = 0; c < 8; c++) l[c] = Wv[c] + ((c < curr) ? -100.0f : 1.0f);
    } else if (n == 7) {
        const int thr = curr + 1;
        const bool inc = (incr > 0.5f);
#pragma unroll
        for (int c = 0; c < 8; c++)
            l[c] = Wv[c] + ((inc && c < thr) ? -100.0f : 1.0f);
    } else {
#pragma unroll
        for (int c = 0; c < 8; c++) l[c] = Wv[c];
    }

    float xt[8];
    gs8(l, g, xt);

    float p2 = probs;
    if (n == 7) {
        float pc = probs * (1.0f - cst);
        pc = pc + incr;
        p2 = fminf(fmaxf(pc, 0.0f), 1.0f);
    }

    float4 oa, ob;
    float* op = &oa.x;
#pragma unroll
    for (int c = 0; c < 4; c++) op[c] = p2 * xt[c] + (1.0f - p2) * xv[c];
    op = &ob.x;
#pragma unroll
    for (int c = 0; c < 4; c++) op[c] = p2 * xt[c + 4] + (1.0f - p2) * xv[c + 4];
    *reinterpret_cast<float4*>(xcf + base) = oa;
    *reinterpret_cast<float4*>(xcf + base + 4) = ob;
}

// ---------------------------------------------------------------------------
// Launch
// ---------------------------------------------------------------------------
extern "C" void kernel_launch(void* const* d_in, const int* in_sizes, int n_in,
                              void* d_out, int out_size) {
    const float* x     = (const float*)d_in[0];
    const float* truth = (const float*)d_in[1];
    const float* sw1   = (const float*)d_in[2];
    const float* sb1   = (const float*)d_in[3];
    const float* sw2   = (const float*)d_in[4];
    const float* sb2   = (const float*)d_in[5];
    const float* pw1   = (const float*)d_in[6];
    const float* pb1   = (const float*)d_in[7];
    const float* pw2   = (const float*)d_in[8];
    const float* pb2   = (const float*)d_in[9];
    const float* pw3   = (const float*)d_in[10];
    const float* pb3   = (const float*)d_in[11];
    const float* pw4   = (const float*)d_in[12];
    const float* pb4   = (const float*)d_in[13];

    float* out       = (float*)d_out;
    float* out_truth = out;
    float* out_xcf   = out + BD_ELEMS;
    float* out_P     = out + 2 * (size_t)BD_ELEMS;
    float* out_W     = out + 2 * (size_t)BD_ELEMS + BN_ELEMS;

    float *a_hi, *a_lo, *b_hi, *b_lo, *s1, *wt_hi, *wt_lo;
    cudaGetSymbolAddress((void**)&a_hi, g_a_hi);
    cudaGetSymbolAddress((void**)&a_lo, g_a_lo);
    cudaGetSymbolAddress((void**)&b_hi, g_b_hi);
    cudaGetSymbolAddress((void**)&b_lo, g_b_lo);
    cudaGetSymbolAddress((void**)&s1,   g_s1);
    cudaGetSymbolAddress((void**)&wt_hi, g_wt_hi);
    cudaGetSymbolAddress((void**)&wt_lo, g_wt_lo);

    cudaFuncSetAttribute(gemm_mma<true, true, true>,
                         cudaFuncAttributeMaxDynamicSharedMemorySize, GEMM_SMEM);
    cudaFuncSetAttribute(gemm_mma<true, true, false>,
                         cudaFuncAttributeMaxDynamicSharedMemorySize, GEMM_SMEM);
    cudaFuncSetAttribute(gemm_mma<false, true, true>,
                         cudaFuncAttributeMaxDynamicSharedMemorySize, GEMM_SMEM);
    cudaFuncSetAttribute(gemm_mma<false, false, false>,
                         cudaFuncAttributeMaxDynamicSharedMemorySize, GEMM_SMEM);

    // Weight transpose + split
    split_w_kernel<<<dim3(512 / 32, 1024 / 32), 256>>>(pw1, wt_hi + OF_PW1, wt_lo + OF_PW1, 512, 1024);
    split_w_kernel<<<dim3(512 / 32,  512 / 32), 256>>>(sw1, wt_hi + OF_SW1, wt_lo + OF_SW1, 512, 512);
    split_w_kernel<<<dim3(1024 / 32, 1024 / 32), 256>>>(pw2, wt_hi + OF_PW2, wt_lo + OF_PW2, 1024, 1024);
    split_w_kernel<<<dim3(1024 / 32, 1024 / 32), 256>>>(pw3, wt_hi + OF_PW3, wt_lo + OF_PW3, 1024, 1024);
    split_w_kernel<<<dim3(1024 / 32,  512 / 32), 256>>>(pw4, wt_hi + OF_PW4, wt_lo + OF_PW4, 1024, 512);

    // MLP path on tensor cores (mma.sync tf32)
    gemm_mma<true, true, true><<<dim3(HP / 128, BB / 128), 256, GEMM_SMEM>>>(
        x, nullptr, wt_hi + OF_PW1, wt_lo + OF_PW1, pb1, a_hi, a_lo, DD, HP);
    gemm_mma<false, true, true><<<dim3(HP / 128, BB / 128), 256, GEMM_SMEM>>>(
        a_hi, a_lo, wt_hi + OF_PW2, wt_lo + OF_PW2, pb2, b_hi, b_lo, HP, HP);
    gemm_mma<false, true, true><<<dim3(HP / 128, BB / 128), 256, GEMM_SMEM>>>(
        b_hi, b_lo, wt_hi + OF_PW3, wt_lo + OF_PW3, pb3, a_hi, a_lo, HP, HP);
    gemm_mma<false, false, false><<<dim3(DD / 128, BB / 128), 256, GEMM_SMEM>>>(
        a_hi, a_lo, wt_hi + OF_PW4, wt_lo + OF_PW4, pb4, out_W, nullptr, HP, DD);

    // Selector path
    gemm_mma<true, true, false><<<dim3(HS / 128, BB / 128), 256, GEMM_SMEM>>>(
        x, nullptr, wt_hi + OF_SW1, wt_lo + OF_SW1, sb1, s1, nullptr, DD, HS);
    sgemm_sig_kernel<<<dim3(NN / 64, BB / 128), 256>>>(s1, sw2, sb2, out_P,
                                                       BB, NN, HS);

    // truth_x passthrough
    cudaMemcpyAsync(out_truth, truth, (size_t)BD_ELEMS * sizeof(float),
                    cudaMemcpyDeviceToDevice);
    // Fused tail
    finalize_kernel<<<BB, NN>>>(x, out_P, out_W, out_xcf);
}

// round 5
// speedup vs baseline: 2.2860x; 1.9347x over previous
#include <cuda_runtime.h>
#include <cuda_fp16.h>
#include <cstdint>
#include <math.h>

// ---------------------------------------------------------------------------
// Problem constants
// ---------------------------------------------------------------------------
#define BB 8192
#define NN 64
#define CC 8
#define DD (NN * CC)        // 512
#define HP 1024
#define HS 512
#define BD_ELEMS (BB * DD)  // 4,194,304
#define BN_ELEMS (BB * NN)  // 524,288

// ---------------------------------------------------------------------------
// Scratch (allocation-free: __device__ globals)
// ---------------------------------------------------------------------------
__device__ __half g_a_hi[BB * HP];
__device__ __half g_a_lo[BB * HP];
__device__ __half g_b_hi[BB * HP];
__device__ __half g_b_lo[BB * HP];
__device__ __half g_xh[BB * DD];
__device__ float  g_s1[BB * HS];

// Transposed + split weights, packed (Bt[n][k] layout), fp16 hi/lo:
#define OF_PW1 0
#define OF_SW1 524288
#define OF_PW2 786432
#define OF_PW3 1835008
#define OF_PW4 2883584
#define WT_TOTAL 3407872
__device__ __half g_wt_hi[WT_TOTAL];
__device__ __half g_wt_lo[WT_TOTAL];

// ---------------------------------------------------------------------------
// Threefry-2x32-20 (JAX)
// ---------------------------------------------------------------------------
struct TFK { unsigned a, b; };

__host__ __device__ constexpr unsigned tf_rotl(unsigned v, int r) {
    return (v << r) | (v >> (32 - r));
}

__host__ __device__ constexpr TFK tf2x32(unsigned k0, unsigned k1,
                                         unsigned x0, unsigned x1) {
    unsigned k2 = k0 ^ k1 ^ 0x1BD11BDAu;
    x0 += k0; x1 += k1;
    x0 += x1; x1 = tf_rotl(x1, 13); x1 ^= x0;
    x0 += x1; x1 = tf_rotl(x1, 15); x1 ^= x0;
    x0 += x1; x1 = tf_rotl(x1, 26); x1 ^= x0;
    x0 += x1; x1 = tf_rotl(x1,  6); x1 ^= x0;
    x0 += k1; x1 += k2 + 1u;
    x0 += x1; x1 = tf_rotl(x1, 17); x1 ^= x0;
    x0 += x1; x1 = tf_rotl(x1, 29); x1 ^= x0;
    x0 += x1; x1 = tf_rotl(x1, 16); x1 ^= x0;
    x0 += x1; x1 = tf_rotl(x1, 24); x1 ^= x0;
    x0 += k2; x1 += k0 + 2u;
    x0 += x1; x1 = tf_rotl(x1, 13); x1 ^= x0;
    x0 += x1; x1 = tf_rotl(x1, 15); x1 ^= x0;
    x0 += x1; x1 = tf_rotl(x1, 26); x1 ^= x0;
    x0 += x1; x1 = tf_rotl(x1,  6); x1 ^= x0;
    x0 += k0; x1 += k1 + 3u;
    x0 += x1; x1 = tf_rotl(x1, 17); x1 ^= x0;
    x0 += x1; x1 = tf_rotl(x1, 29); x1 ^= x0;
    x0 += x1; x1 = tf_rotl(x1, 16); x1 ^= x0;
    x0 += x1; x1 = tf_rotl(x1, 24); x1 ^= x0;
    x0 += k1; x1 += k2 + 4u;
    x0 += x1; x1 = tf_rotl(x1, 13); x1 ^= x0;
    x0 += x1; x1 = tf_rotl(x1, 15); x1 ^= x0;
    x0 += x1; x1 = tf_rotl(x1, 26); x1 ^= x0;
    x0 += x1; x1 = tf_rotl(x1,  6); x1 ^= x0;
    x0 += k2; x1 += k0 + 5u;
    return TFK{x0, x1};
}

constexpr unsigned KA0 = tf2x32(0u, 42u, 0u, 0u).a;
constexpr unsigned KA1 = tf2x32(0u, 42u, 0u, 0u).b;
constexpr unsigned KB0 = tf2x32(0u, 42u, 0u, 1u).a;
constexpr unsigned KB1 = tf2x32(0u, 42u, 0u, 1u).b;
constexpr unsigned KG0 = tf2x32(0u, 42u, 0u, 2u).a;
constexpr unsigned KG1 = tf2x32(0u, 42u, 0u, 2u).b;

__device__ __forceinline__ float jax_u01(unsigned k0, unsigned k1, unsigned idx) {
    TFK r = tf2x32(k0, k1, 0u, idx);
    unsigned bits = r.a ^ r.b;
    float f = __uint_as_float((bits >> 9) | 0x3f800000u) - 1.0f;
    f = f + 1e-8f;
    return fmaxf(1e-8f, f);
}

// ---------------------------------------------------------------------------
// Helpers
// ---------------------------------------------------------------------------
__device__ __forceinline__ uint32_t smem_u32(const void* p) {
    uint32_t a;
    asm("{ .reg .u64 t; cvta.to.shared.u64 t, %1; cvt.u32.u64 %0, t; }"
        : "=r"(a) : "l"(p));
    return a;
}

#define CP16(dst_u32, src_ptr) \
    asm volatile("cp.async.cg.shared.global [%0], [%1], 16;" \
                 :: "r"(dst_u32), "l"(src_ptr) : "memory")
#define CP_COMMIT() asm volatile("cp.async.commit_group;" ::: "memory")
#define CP_WAIT(n)  asm volatile("cp.async.wait_group %0;" :: "n"(n) : "memory")

// mma.sync m16n8k16 fp16 -> fp32 (baseline PTX, sm_80+)
__device__ __forceinline__ void mma16(float* d, const uint32_t* a,
                                      const uint32_t* b) {
    asm volatile(
        "mma.sync.aligned.m16n8k16.row.col.f32.f16.f16.f32 "
        "{%0,%1,%2,%3}, {%4,%5,%6,%7}, {%8,%9}, {%0,%1,%2,%3};"
        : "+f"(d[0]), "+f"(d[1]), "+f"(d[2]), "+f"(d[3])
        : "r"(a[0]), "r"(a[1]), "r"(a[2]), "r"(a[3]), "r"(b[0]), "r"(b[1]));
}

__device__ __forceinline__ void split_h(float y, __half& h, __half& l) {
    h = __float2half_rn(y);
    l = __float2half_rn(y - __half2float(h));
}

// ---------------------------------------------------------------------------
// fp16-split GEMM: O[M, Nout] = epi(A[M,K] @ Bt[Nout,K]^T + bias)
// BM=128, BN=128, BK=32, 256 threads, warp grid 2x4 (warp tile 64x32).
// A, B as exact fp16 (hi, lo) pairs: O = Ah*Bh + Ah*Bl (+ Al*Bh).
//   AEX:   A exact in fp16 (one-hot x) -> no A_lo term
//   RELU:  relu epilogue
//   SPLIT: outputs fp16 (hi, lo) pair; else fp32 into Of
// ---------------------------------------------------------------------------
#define PH 40                           // smem row pitch (halves) -> 80B rows
#define T_AH 0
#define T_AL (128 * PH)
#define T_BH (2 * 128 * PH)
#define T_BL (3 * 128 * PH)
#define STAGE_H (4 * 128 * PH)          // 20480 halves = 40960 B / stage
#define GEMM_SMEM (2 * STAGE_H * 2)     // 81920 bytes

template <bool AEX>
__device__ __forceinline__ void issue_chunk_h(
    uint32_t smb, int s, int c,
    const __half* __restrict__ A_hi, const __half* __restrict__ A_lo,
    const __half* __restrict__ B_hi, const __half* __restrict__ B_lo,
    int K, int bm0, int bn0, int tid) {
    const int k0 = c * 32;
    const uint32_t sb = smb + (uint32_t)(s * STAGE_H) * 2u;
#pragma unroll
    for (int i = 0; i < 2; i++) {
        const int f = tid + i * 256;       // 16B-unit index in [0,512)
        const int row = f >> 2;            // [0,128)
        const int q = f & 3;               // 16B unit within 64B row chunk
        const uint32_t doff = (uint32_t)(row * PH + q * 8) * 2u;
        CP16(sb + T_AH * 2 + doff, A_hi + (size_t)(bm0 + row) * K + k0 + q * 8);
        if (!AEX)
            CP16(sb + T_AL * 2 + doff,
                 A_lo + (size_t)(bm0 + row) * K + k0 + q * 8);
        CP16(sb + T_BH * 2 + doff, B_hi + (size_t)(bn0 + row) * K + k0 + q * 8);
        CP16(sb + T_BL * 2 + doff, B_lo + (size_t)(bn0 + row) * K + k0 + q * 8);
    }
    CP_COMMIT();
}

template <bool AEX, bool RELU, bool SPLIT>
__global__ void __launch_bounds__(256, 2)
gemm_h(const __half* __restrict__ A_hi, const __half* __restrict__ A_lo,
       const __half* __restrict__ Bt_hi, const __half* __restrict__ Bt_lo,
       const float* __restrict__ bias,
       __half* __restrict__ O_hi, __half* __restrict__ O_lo,
       float* __restrict__ Of,
       int K, int Nout) {
    extern __shared__ __half smh[];
    const uint32_t smb = smem_u32(smh);
    const int tid = threadIdx.x;
    const int l = tid & 31;
    const int warp = tid >> 5;
    const int wm = warp >> 2;          // 0..1
    const int wn = warp & 3;           // 0..3
    const int bm0 = blockIdx.y * 128;
    const int bn0 = blockIdx.x * 128;
    const int NC = K >> 5;             // BK=32 chunks

    float acc[4][4][4];
#pragma unroll
    for (int mf = 0; mf < 4; mf++)
#pragma unroll
        for (int nf = 0; nf < 4; nf++)
#pragma unroll
            for (int r = 0; r < 4; r++) acc[mf][nf][r] = 0.0f;

    issue_chunk_h<AEX>(smb, 0, 0, A_hi, A_lo, Bt_hi, Bt_lo, K, bm0, bn0, tid);

    const int rA = l >> 2;             // groupID 0..7
    const int cK = l & 3;              // threadID-in-group 0..3

    for (int c = 0; c < NC; c++) {
        const int s = c & 1;
        if (c + 1 < NC) {
            issue_chunk_h<AEX>(smb, (c + 1) & 1, c + 1, A_hi, A_lo, Bt_hi,
                               Bt_lo, K, bm0, bn0, tid);
            CP_WAIT(1);
        } else {
            CP_WAIT(0);
        }
        __syncthreads();

        const __half* st = smh + s * STAGE_H;
        const __half* pAh = st + T_AH + (wm * 64 + rA) * PH;
        const __half* pAl = st + T_AL + (wm * 64 + rA) * PH;
        const __half* pBh = st + T_BH + (wn * 32 + rA) * PH;
        const __half* pBl = st + T_BL + (wn * 32 + rA) * PH;

#pragma unroll
        for (int ks = 0; ks < 2; ks++) {
            const int kb = ks * 16 + 2 * cK;     // half index within row
            uint32_t bh[4][2], bl[4][2];
#pragma unroll
            for (int nf = 0; nf < 4; nf++) {
                const __half* p = pBh + nf * 8 * PH + kb;
                bh[nf][0] = *reinterpret_cast<const uint32_t*>(p);
                bh[nf][1] = *reinterpret_cast<const uint32_t*>(p + 8);
                const __half* q = pBl + nf * 8 * PH + kb;
                bl[nf][0] = *reinterpret_cast<const uint32_t*>(q);
                bl[nf][1] = *reinterpret_cast<const uint32_t*>(q + 8);
            }
#pragma unroll
            for (int mf = 0; mf < 4; mf++) {
                uint32_t ah[4], al[4];
                const __half* p = pAh + mf * 16 * PH + kb;
                ah[0] = *reinterpret_cast<const uint32_t*>(p);
                ah[1] = *reinterpret_cast<const uint32_t*>(p + 8 * PH);
                ah[2] = *reinterpret_cast<const uint32_t*>(p + 8);
                ah[3] = *reinterpret_cast<const uint32_t*>(p + 8 * PH + 8);
                if (!AEX) {
                    const __half* q = pAl + mf * 16 * PH + kb;
                    al[0] = *reinterpret_cast<const uint32_t*>(q);
                    al[1] = *reinterpret_cast<const uint32_t*>(q + 8 * PH);
                    al[2] = *reinterpret_cast<const uint32_t*>(q + 8);
                    al[3] = *reinterpret_cast<const uint32_t*>(q + 8 * PH + 8);
                }
#pragma unroll
                for (int nf = 0; nf < 4; nf++) {
                    mma16(acc[mf][nf], ah, bh[nf]);
                    mma16(acc[mf][nf], ah, bl[nf]);
                    if (!AEX) mma16(acc[mf][nf], al, bh[nf]);
                }
            }
        }
        __syncthreads();
    }

    // ---- Epilogue ----
#pragma unroll
    for (int nf = 0; nf < 4; nf++) {
        const int col = bn0 + wn * 32 + nf * 8 + 2 * cK;
        const float2 bv = *reinterpret_cast<const float2*>(bias + col);
#pragma unroll
        for (int mf = 0; mf < 4; mf++) {
            const int ra = bm0 + wm * 64 + mf * 16 + rA;
            float y[4];
            y[0] = acc[mf][nf][0] + bv.x;
            y[1] = acc[mf][nf][1] + bv.y;
            y[2] = acc[mf][nf][2] + bv.x;
            y[3] = acc[mf][nf][3] + bv.y;
            if (RELU) {
#pragma unroll
                for (int r = 0; r < 4; r++) y[r] = fmaxf(y[r], 0.0f);
            }
            if (SPLIT) {
                __half h[4], lo[4];
#pragma unroll
                for (int r = 0; r < 4; r++) split_h(y[r], h[r], lo[r]);
                *reinterpret_cast<__half2*>(O_hi + (size_t)ra * Nout + col) =
                    __halves2half2(h[0], h[1]);
                *reinterpret_cast<__half2*>(O_hi + (size_t)(ra + 8) * Nout + col) =
                    __halves2half2(h[2], h[3]);
                *reinterpret_cast<__half2*>(O_lo + (size_t)ra * Nout + col) =
                    __halves2half2(lo[0], lo[1]);
                *reinterpret_cast<__half2*>(O_lo + (size_t)(ra + 8) * Nout + col) =
                    __halves2half2(lo[2], lo[3]);
            } else {
                *reinterpret_cast<float2*>(Of + (size_t)ra * Nout + col) =
                    make_float2(y[0], y[1]);
                *reinterpret_cast<float2*>(Of + (size_t)(ra + 8) * Nout + col) =
                    make_float2(y[2], y[3]);
            }
        }
    }
}

// ---------------------------------------------------------------------------
// Weight transpose + fp16 split: Bt_hi/lo[n][k] = split(W[k][n])
// ---------------------------------------------------------------------------
__global__ void __launch_bounds__(256)
split_wh_kernel(const float* __restrict__ W, __half* __restrict__ bt_hi,
                __half* __restrict__ bt_lo, int K, int N) {
    __shared__ float t[32][33];
    const int kb = blockIdx.x * 32;
    const int nb = blockIdx.y * 32;
    const int tx = threadIdx.x & 31;
    const int ty = threadIdx.x >> 5;
#pragma unroll
    for (int r = ty; r < 32; r += 8)
        t[r][tx] = W[(size_t)(kb + r) * N + nb + tx];
    __syncthreads();
#pragma unroll
    for (int r = ty; r < 32; r += 8) {
        float wv = t[tx][r];
        __half h, lo;
        split_h(wv, h, lo);
        size_t o = (size_t)(nb + r) * K + kb + tx;
        bt_hi[o] = h;
        bt_lo[o] = lo;
    }
}

// x (exact one-hot fp32) -> fp16 (exact)
__global__ void __launch_bounds__(256)
convert_x_kernel(const float* __restrict__ x, __half* __restrict__ xh) {
    const int t = blockIdx.x * 256 + threadIdx.x;   // 8 elems each
    const float4 a = *reinterpret_cast<const float4*>(x + (size_t)t * 8);
    const float4 b = *reinterpret_cast<const float4*>(x + (size_t)t * 8 + 4);
    __half2 o[4];
    o[0] = __halves2half2(__float2half_rn(a.x), __float2half_rn(a.y));
    o[1] = __halves2half2(__float2half_rn(a.z), __float2half_rn(a.w));
    o[2] = __halves2half2(__float2half_rn(b.x), __float2half_rn(b.y));
    o[3] = __halves2half2(__float2half_rn(b.z), __float2half_rn(b.w));
    *reinterpret_cast<uint4*>(xh + (size_t)t * 8) =
        *reinterpret_cast<uint4*>(o);
}

// ---------------------------------------------------------------------------
// Scalar SGEMM for the small selector head (N=64), sigmoid epilogue
// ---------------------------------------------------------------------------
__global__ void __launch_bounds__(256)
sgemm_sig_kernel(const float* __restrict__ A, const float* __restrict__ B,
                 const float* __restrict__ bias, float* __restrict__ C,
                 int M, int N, int K) {
    __shared__ float As[16][128];
    __shared__ float Bs[16][64];

    const int tid = threadIdx.x;
    const int tx = tid & 15;
    const int ty = tid >> 4;
    const int bm0 = blockIdx.y * 128;
    const int bn0 = blockIdx.x * 64;

    float acc[8][4];
#pragma unroll
    for (int i = 0; i < 8; i++)
#pragma unroll
        for (int j = 0; j < 4; j++) acc[i][j] = 0.0f;

    const int nk = K >> 4;
    for (int kt = 0; kt < nk; kt++) {
#pragma unroll
        for (int lq = 0; lq < 2; lq++) {
            int f = tid + lq * 256;
            int row = f >> 2;
            int c4 = (f & 3) << 2;
            float4 v = *reinterpret_cast<const float4*>(
                A + (size_t)(bm0 + row) * K + (kt << 4) + c4);
            As[c4 + 0][row] = v.x;
            As[c4 + 1][row] = v.y;
            As[c4 + 2][row] = v.z;
            As[c4 + 3][row] = v.w;
        }
        {
            int row = tid >> 4;
            int col = (tid & 15) << 2;
            float4 v = *reinterpret_cast<const float4*>(
                B + (size_t)((kt << 4) + row) * N + bn0 + col);
            *reinterpret_cast<float4*>(&Bs[row][col]) = v;
        }
        __syncthreads();

#pragma unroll
        for (int k = 0; k < 16; k++) {
            float4 a0 = *reinterpret_cast<const float4*>(&As[k][ty * 8]);
            float4 a1 = *reinterpret_cast<const float4*>(&As[k][ty * 8 + 4]);
            float4 bv = *reinterpret_cast<const float4*>(&Bs[k][tx * 4]);
            float a[8] = {a0.x, a0.y, a0.z, a0.w, a1.x, a1.y, a1.z, a1.w};
            float bbv[4] = {bv.x, bv.y, bv.z, bv.w};
#pragma unroll
            for (int i = 0; i < 8; i++)
#pragma unroll
                for (int j = 0; j < 4; j++)
                    acc[i][j] = fmaf(a[i], bbv[j], acc[i][j]);
        }
        __syncthreads();
    }

    float4 bvec = *reinterpret_cast<const float4*>(bias + bn0 + tx * 4);
    float bias4[4] = {bvec.x, bvec.y, bvec.z, bvec.w};
#pragma unroll
    for (int i = 0; i < 8; i++) {
        float4 v;
        float* vp = &v.x;
#pragma unroll
        for (int j = 0; j < 4; j++) {
            float c = acc[i][j] + bias4[j];
            vp[j] = 1.0f / (1.0f + expf(-c));
        }
        *reinterpret_cast<float4*>(
            C + (size_t)(bm0 + ty * 8 + i) * N + bn0 + tx * 4) = v;
    }
}

// ---------------------------------------------------------------------------
// Fused elementwise tail (verified rounds 1-4)
// ---------------------------------------------------------------------------
__device__ __forceinline__ void gs8(const float* l, const float* g, float* xt) {
    float m = l[0];
#pragma unroll
    for (int c = 1; c < 8; c++) m = fmaxf(m, l[c]);
    float e[8], s = 0.0f;
#pragma unroll
    for (int c = 0; c < 8; c++) { e[c] = expf(l[c] - m); s += e[c]; }
    float t[8];
#pragma unroll
    for (int c = 0; c < 8; c++) {
        float pr = e[c] / s;
        pr = 0.9f * pr + 0.0125f;
        t[c] = (logf(pr) + g[c]) / 0.7f;
    }
    float m2 = t[0];
#pragma unroll
    for (int c = 1; c < 8; c++) m2 = fmaxf(m2, t[c]);
    float e2[8], s2 = 0.0f;
#pragma unroll
    for (int c = 0; c < 8; c++) { e2[c] = expf(t[c] - m2); s2 += e2[c]; }
#pragma unroll
    for (int c = 0; c < 8; c++) xt[c] = e2[c] / s2;
}

__global__ void finalize_kernel(const float* __restrict__ x,
                                const float* __restrict__ Pm,
                                const float* __restrict__ W,
                                float* __restrict__ xcf) {
    const int b = blockIdx.x;
    const int n = threadIdx.x;   // 64 threads
    __shared__ float sh_cst, sh_incr;

    const size_t base = (size_t)b * DD + n * CC;
    float4 xa = *reinterpret_cast<const float4*>(x + base);
    float4 xb = *reinterpret_cast<const float4*>(x + base + 4);
    float4 wa = *reinterpret_cast<const float4*>(W + base);
    float4 wb = *reinterpret_cast<const float4*>(W + base + 4);
    float xv[8] = {xa.x, xa.y, xa.z, xa.w, xb.x, xb.y, xb.z, xb.w};
    float Wv[8] = {wa.x, wa.y, wa.z, wa.w, wb.x, wb.y, wb.z, wb.w};

    const unsigned i = (unsigned)(b * NN + n);
    const float P = Pm[i];

    float ua = jax_u01(KA0, KA1, i);
    float ub = jax_u01(KB0, KB1, i);
    float ea = expf(-logf(-logf(ua)));
    float eb = expf(-logf(-logf(ub)));
    float no = P * ea / 0.7f;
    float de = no + (1.0f - P) * eb / 0.7f;
    float probs = no / de;

    float g[8];
#pragma unroll
    for (int c = 0; c < 8; c++) {
        float u = jax_u01(KG0, KG1, i * 8u + (unsigned)c);
        g[c] = -logf(-logf(u));
    }

    int curr = 0;
    {
        float m = xv[0];
#pragma unroll
        for (int c = 1; c < 8; c++)
            if (xv[c] > m) { m = xv[c]; curr = c; }
    }

    if (n == 2) {
        float xt_par[8];
        gs8(Wv, g, xt_par);
        int am = 0;
        float m = probs * xt_par[0] + (1.0f - probs) * xv[0];
#pragma unroll
        for (int c = 1; c < 8; c++) {
            float v = probs * xt_par[c] + (1.0f - probs) * xv[c];
            if (v > m) { m = v; am = c; }
        }
        int diff = am - curr;
        sh_cst  = (diff == 0) ? 1.0f : 0.0f;
        sh_incr = (diff >  0) ? 1.0f : 0.0f;
    }
    __syncthreads();
    const float cst = sh_cst;
    const float incr = sh_incr;

    float l[8];
    if (n == 0 || n == 5 || n == 10) {
#pragma unroll
        for (int c = 0; c < 8; c++) l[c] = Wv[c] + ((c < curr) ? -100.0f : 1.0f);
    } else if (n == 7) {
        const int thr = curr + 1;
        const bool inc = (incr > 0.5f);
#pragma unroll
        for (int c = 0; c < 8; c++)
            l[c] = Wv[c] + ((inc && c < thr) ? -100.0f : 1.0f);
    } else {
#pragma unroll
        for (int c = 0; c < 8; c++) l[c] = Wv[c];
    }

    float xt[8];
    gs8(l, g, xt);

    float p2 = probs;
    if (n == 7) {
        float pc = probs * (1.0f - cst);
        pc = pc + incr;
        p2 = fminf(fmaxf(pc, 0.0f), 1.0f);
    }

    float4 oa, ob;
    float* op = &oa.x;
#pragma unroll
    for (int c = 0; c < 4; c++) op[c] = p2 * xt[c] + (1.0f - p2) * xv[c];
    op = &ob.x;
#pragma unroll
    for (int c = 0; c < 4; c++) op[c] = p2 * xt[c + 4] + (1.0f - p2) * xv[c + 4];
    *reinterpret_cast<float4*>(xcf + base) = oa;
    *reinterpret_cast<float4*>(xcf + base + 4) = ob;
}

// ---------------------------------------------------------------------------
// Launch
// ---------------------------------------------------------------------------
extern "C" void kernel_launch(void* const* d_in, const int* in_sizes, int n_in,
                              void* d_out, int out_size) {
    const float* x     = (const float*)d_in[0];
    const float* truth = (const float*)d_in[1];
    const float* sw1   = (const float*)d_in[2];
    const float* sb1   = (const float*)d_in[3];
    const float* sw2   = (const float*)d_in[4];
    const float* sb2   = (const float*)d_in[5];
    const float* pw1   = (const float*)d_in[6];
    const float* pb1   = (const float*)d_in[7];
    const float* pw2   = (const float*)d_in[8];
    const float* pb2   = (const float*)d_in[9];
    const float* pw3   = (const float*)d_in[10];
    const float* pb3   = (const float*)d_in[11];
    const float* pw4   = (const float*)d_in[12];
    const float* pb4   = (const float*)d_in[13];

    float* out       = (float*)d_out;
    float* out_truth = out;
    float* out_xcf   = out + BD_ELEMS;
    float* out_P     = out + 2 * (size_t)BD_ELEMS;
    float* out_W     = out + 2 * (size_t)BD_ELEMS + BN_ELEMS;

    __half *a_hi, *a_lo, *b_hi, *b_lo, *xh, *wt_hi, *wt_lo;
    float *s1;
    cudaGetSymbolAddress((void**)&a_hi, g_a_hi);
    cudaGetSymbolAddress((void**)&a_lo, g_a_lo);
    cudaGetSymbolAddress((void**)&b_hi, g_b_hi);
    cudaGetSymbolAddress((void**)&b_lo, g_b_lo);
    cudaGetSymbolAddress((void**)&xh,   g_xh);
    cudaGetSymbolAddress((void**)&s1,   g_s1);
    cudaGetSymbolAddress((void**)&wt_hi, g_wt_hi);
    cudaGetSymbolAddress((void**)&wt_lo, g_wt_lo);

    cudaFuncSetAttribute(gemm_h<true, true, true>,
                         cudaFuncAttributeMaxDynamicSharedMemorySize, GEMM_SMEM);
    cudaFuncSetAttribute(gemm_h<true, true, false>,
                         cudaFuncAttributeMaxDynamicSharedMemorySize, GEMM_SMEM);
    cudaFuncSetAttribute(gemm_h<false, true, true>,
                         cudaFuncAttributeMaxDynamicSharedMemorySize, GEMM_SMEM);
    cudaFuncSetAttribute(gemm_h<false, false, false>,
                         cudaFuncAttributeMaxDynamicSharedMemorySize, GEMM_SMEM);

    // Input conversions: weight transpose+split, x -> fp16
    convert_x_kernel<<<(BB * DD / 8) / 256, 256>>>(x, xh);
    split_wh_kernel<<<dim3(512 / 32, 1024 / 32), 256>>>(pw1, wt_hi + OF_PW1, wt_lo + OF_PW1, 512, 1024);
    split_wh_kernel<<<dim3(512 / 32,  512 / 32), 256>>>(sw1, wt_hi + OF_SW1, wt_lo + OF_SW1, 512, 512);
    split_wh_kernel<<<dim3(1024 / 32, 1024 / 32), 256>>>(pw2, wt_hi + OF_PW2, wt_lo + OF_PW2, 1024, 1024);
    split_wh_kernel<<<dim3(1024 / 32, 1024 / 32), 256>>>(pw3, wt_hi + OF_PW3, wt_lo + OF_PW3, 1024, 1024);
    split_wh_kernel<<<dim3(1024 / 32,  512 / 32), 256>>>(pw4, wt_hi + OF_PW4, wt_lo + OF_PW4, 1024, 512);

    // MLP path (fp16-split mma.sync)
    gemm_h<true, true, true><<<dim3(HP / 128, BB / 128), 256, GEMM_SMEM>>>(
        xh, nullptr, wt_hi + OF_PW1, wt_lo + OF_PW1, pb1, a_hi, a_lo, nullptr,
        DD, HP);
    gemm_h<false, true, true><<<dim3(HP / 128, BB / 128), 256, GEMM_SMEM>>>(
        a_hi, a_lo, wt_hi + OF_PW2, wt_lo + OF_PW2, pb2, b_hi, b_lo, nullptr,
        HP, HP);
    gemm_h<false, true, true><<<dim3(HP / 128, BB / 128), 256, GEMM_SMEM>>>(
        b_hi, b_lo, wt_hi + OF_PW3, wt_lo + OF_PW3, pb3, a_hi, a_lo, nullptr,
        HP, HP);
    gemm_h<false, false, false><<<dim3(DD / 128, BB / 128), 256, GEMM_SMEM>>>(
        a_hi, a_lo, wt_hi + OF_PW4, wt_lo + OF_PW4, pb4, nullptr, nullptr,
        out_W, HP, DD);

    // Selector path
    gemm_h<true, true, false><<<dim3(HS / 128, BB / 128), 256, GEMM_SMEM>>>(
        xh, nullptr, wt_hi + OF_SW1, wt_lo + OF_SW1, sb1, nullptr, nullptr,
        s1, DD, HS);
    sgemm_sig_kernel<<<dim3(NN / 64, BB / 128), 256>>>(s1, sw2, sb2, out_P,
                                                       BB, NN, HS);

    // truth_x passthrough
    cudaMemcpyAsync(out_truth, truth, (size_t)BD_ELEMS * sizeof(float),
                    cudaMemcpyDeviceToDevice);
    // Fused tail
    finalize_kernel<<<BB, NN>>>(x, out_P, out_W, out_xcf);
}

// round 6
// speedup vs baseline: 2.3953x; 1.0478x over previous
#include <cuda_runtime.h>
#include <cuda_fp16.h>
#include <cstdint>
#include <math.h>

// ---------------------------------------------------------------------------
// Problem constants
// ---------------------------------------------------------------------------
#define BB 8192
#define NN 64
#define CC 8
#define DD (NN * CC)        // 512
#define HP 1024
#define HS 512
#define BD_ELEMS (BB * DD)  // 4,194,304
#define BN_ELEMS (BB * NN)  // 524,288

// ---------------------------------------------------------------------------
// Scratch (allocation-free: __device__ globals)
// ---------------------------------------------------------------------------
__device__ __half g_a_hi[BB * HP];
__device__ __half g_a_lo[BB * HP];
__device__ __half g_b_hi[BB * HP];
__device__ __half g_b_lo[BB * HP];
__device__ __half g_xh[BB * DD];
__device__ float  g_s1[BB * HS];

// Transposed + split weights, packed (Bt[n][k] layout), fp16 hi/lo:
#define OF_PW1 0
#define OF_SW1 524288
#define OF_PW2 786432
#define OF_PW3 1835008
#define OF_PW4 2883584
#define WT_TOTAL 3407872
__device__ __half g_wt_hi[WT_TOTAL];
__device__ __half g_wt_lo[WT_TOTAL];

// ---------------------------------------------------------------------------
// Threefry-2x32-20 (JAX)
// ---------------------------------------------------------------------------
struct TFK { unsigned a, b; };

__host__ __device__ constexpr unsigned tf_rotl(unsigned v, int r) {
    return (v << r) | (v >> (32 - r));
}

__host__ __device__ constexpr TFK tf2x32(unsigned k0, unsigned k1,
                                         unsigned x0, unsigned x1) {
    unsigned k2 = k0 ^ k1 ^ 0x1BD11BDAu;
    x0 += k0; x1 += k1;
    x0 += x1; x1 = tf_rotl(x1, 13); x1 ^= x0;
    x0 += x1; x1 = tf_rotl(x1, 15); x1 ^= x0;
    x0 += x1; x1 = tf_rotl(x1, 26); x1 ^= x0;
    x0 += x1; x1 = tf_rotl(x1,  6); x1 ^= x0;
    x0 += k1; x1 += k2 + 1u;
    x0 += x1; x1 = tf_rotl(x1, 17); x1 ^= x0;
    x0 += x1; x1 = tf_rotl(x1, 29); x1 ^= x0;
    x0 += x1; x1 = tf_rotl(x1, 16); x1 ^= x0;
    x0 += x1; x1 = tf_rotl(x1, 24); x1 ^= x0;
    x0 += k2; x1 += k0 + 2u;
    x0 += x1; x1 = tf_rotl(x1, 13); x1 ^= x0;
    x0 += x1; x1 = tf_rotl(x1, 15); x1 ^= x0;
    x0 += x1; x1 = tf_rotl(x1, 26); x1 ^= x0;
    x0 += x1; x1 = tf_rotl(x1,  6); x1 ^= x0;
    x0 += k0; x1 += k1 + 3u;
    x0 += x1; x1 = tf_rotl(x1, 17); x1 ^= x0;
    x0 += x1; x1 = tf_rotl(x1, 29); x1 ^= x0;
    x0 += x1; x1 = tf_rotl(x1, 16); x1 ^= x0;
    x0 += x1; x1 = tf_rotl(x1, 24); x1 ^= x0;
    x0 += k1; x1 += k2 + 4u;
    x0 += x1; x1 = tf_rotl(x1, 13); x1 ^= x0;
    x0 += x1; x1 = tf_rotl(x1, 15); x1 ^= x0;
    x0 += x1; x1 = tf_rotl(x1, 26); x1 ^= x0;
    x0 += x1; x1 = tf_rotl(x1,  6); x1 ^= x0;
    x0 += k2; x1 += k0 + 5u;
    return TFK{x0, x1};
}

constexpr unsigned KA0 = tf2x32(0u, 42u, 0u, 0u).a;
constexpr unsigned KA1 = tf2x32(0u, 42u, 0u, 0u).b;
constexpr unsigned KB0 = tf2x32(0u, 42u, 0u, 1u).a;
constexpr unsigned KB1 = tf2x32(0u, 42u, 0u, 1u).b;
constexpr unsigned KG0 = tf2x32(0u, 42u, 0u, 2u).a;
constexpr unsigned KG1 = tf2x32(0u, 42u, 0u, 2u).b;

__device__ __forceinline__ float jax_u01(unsigned k0, unsigned k1, unsigned idx) {
    TFK r = tf2x32(k0, k1, 0u, idx);
    unsigned bits = r.a ^ r.b;
    float f = __uint_as_float((bits >> 9) | 0x3f800000u) - 1.0f;
    f = f + 1e-8f;
    return fmaxf(1e-8f, f);
}

// ---------------------------------------------------------------------------
// Helpers
// ---------------------------------------------------------------------------
__device__ __forceinline__ uint32_t smem_u32(const void* p) {
    uint32_t a;
    asm("{ .reg .u64 t; cvta.to.shared.u64 t, %1; cvt.u32.u64 %0, t; }"
        : "=r"(a) : "l"(p));
    return a;
}

#define CP16(dst_u32, src_ptr) \
    asm volatile("cp.async.cg.shared.global [%0], [%1], 16;" \
                 :: "r"(dst_u32), "l"(src_ptr) : "memory")
#define CP_COMMIT() asm volatile("cp.async.commit_group;" ::: "memory")
#define CP_WAIT(n)  asm volatile("cp.async.wait_group %0;" :: "n"(n) : "memory")

// mma.sync m16n8k16 fp16 -> fp32 (baseline PTX, sm_80+)
__device__ __forceinline__ void mma16(float* d, const uint32_t* a,
                                      const uint32_t* b) {
    asm volatile(
        "mma.sync.aligned.m16n8k16.row.col.f32.f16.f16.f32 "
        "{%0,%1,%2,%3}, {%4,%5,%6,%7}, {%8,%9}, {%0,%1,%2,%3};"
        : "+f"(d[0]), "+f"(d[1]), "+f"(d[2]), "+f"(d[3])
        : "r"(a[0]), "r"(a[1]), "r"(a[2]), "r"(a[3]), "r"(b[0]), "r"(b[1]));
}

// ldmatrix x4 b16 (baseline PTX, sm_75+)
__device__ __forceinline__ void ldsm_x4(uint32_t* r, uint32_t addr) {
    asm volatile(
        "ldmatrix.sync.aligned.m8n8.x4.shared.b16 {%0,%1,%2,%3}, [%4];"
        : "=r"(r[0]), "=r"(r[1]), "=r"(r[2]), "=r"(r[3]) : "r"(addr));
}

__device__ __forceinline__ void split_h(float y, __half& h, __half& l) {
    h = __float2half_rn(y);
    l = __float2half_rn(y - __half2float(h));
}

// ---------------------------------------------------------------------------
// fp16-split GEMM: O[M, Nout] = epi(A[M,K] @ Bt[Nout,K]^T + bias)
// BM=128, BN=128, BK=32, 256 threads, warp grid 2x4 (warp tile 64x32).
// Fragments via ldmatrix.x4. O = Ah*Bh + Ah*Bl (+ Al*Bh).
// ---------------------------------------------------------------------------
#define PH 40                           // smem row pitch (halves) -> 80B rows
#define T_AH 0
#define T_AL (128 * PH)
#define T_BH (2 * 128 * PH)
#define T_BL (3 * 128 * PH)
#define STAGE_H (4 * 128 * PH)          // 20480 halves = 40960 B / stage
#define GEMM_SMEM (2 * STAGE_H * 2)     // 81920 bytes

template <bool AEX>
__device__ __forceinline__ void issue_chunk_h(
    uint32_t smb, int s, int c,
    const __half* __restrict__ A_hi, const __half* __restrict__ A_lo,
    const __half* __restrict__ B_hi, const __half* __restrict__ B_lo,
    int K, int bm0, int bn0, int tid) {
    const int k0 = c * 32;
    const uint32_t sb = smb + (uint32_t)(s * STAGE_H) * 2u;
#pragma unroll
    for (int i = 0; i < 2; i++) {
        const int f = tid + i * 256;       // 16B-unit index in [0,512)
        const int row = f >> 2;            // [0,128)
        const int q = f & 3;               // 16B unit within 64B row chunk
        const uint32_t doff = (uint32_t)(row * PH + q * 8) * 2u;
        CP16(sb + T_AH * 2 + doff, A_hi + (size_t)(bm0 + row) * K + k0 + q * 8);
        if (!AEX)
            CP16(sb + T_AL * 2 + doff,
                 A_lo + (size_t)(bm0 + row) * K + k0 + q * 8);
        CP16(sb + T_BH * 2 + doff, B_hi + (size_t)(bn0 + row) * K + k0 + q * 8);
        CP16(sb + T_BL * 2 + doff, B_lo + (size_t)(bn0 + row) * K + k0 + q * 8);
    }
    CP_COMMIT();
}

template <bool AEX, bool RELU, bool SPLIT>
__global__ void __launch_bounds__(256, 2)
gemm_h(const __half* __restrict__ A_hi, const __half* __restrict__ A_lo,
       const __half* __restrict__ Bt_hi, const __half* __restrict__ Bt_lo,
       const float* __restrict__ bias,
       __half* __restrict__ O_hi, __half* __restrict__ O_lo,
       float* __restrict__ Of,
       int K, int Nout) {
    extern __shared__ __half smh[];
    const uint32_t smb = smem_u32(smh);
    const int tid = threadIdx.x;
    const int l = tid & 31;
    const int warp = tid >> 5;
    const int wm = warp >> 2;          // 0..1
    const int wn = warp & 3;           // 0..3
    const int bm0 = blockIdx.y * 128;
    const int bn0 = blockIdx.x * 128;
    const int NC = K >> 5;             // BK=32 chunks

    float acc[4][4][4];
#pragma unroll
    for (int mf = 0; mf < 4; mf++)
#pragma unroll
        for (int nf = 0; nf < 4; nf++)
#pragma unroll
            for (int r = 0; r < 4; r++) acc[mf][nf][r] = 0.0f;

    issue_chunk_h<AEX>(smb, 0, 0, A_hi, A_lo, Bt_hi, Bt_lo, K, bm0, bn0, tid);

    // ldmatrix lane offsets (bytes)
    // A x4: matrices (r0-7,k0-7)(r8-15,k0-7)(r0-7,k8-15)(r8-15,k8-15)
    const uint32_t aoff = (uint32_t)(((l & 15) * PH + (l >> 4) * 8) * 2);
    // B x4: (n0-7,k0-7)(n0-7,k8-15)(n8-15,k0-7)(n8-15,k8-15) over an nf-pair
    const uint32_t boff = (uint32_t)(((((l >> 4) & 1) * 8 + (l & 7)) * PH +
                                      ((l >> 3) & 1) * 8) * 2);

    for (int c = 0; c < NC; c++) {
        const int s = c & 1;
        if (c + 1 < NC) {
            issue_chunk_h<AEX>(smb, (c + 1) & 1, c + 1, A_hi, A_lo, Bt_hi,
                               Bt_lo, K, bm0, bn0, tid);
            CP_WAIT(1);
        } else {
            CP_WAIT(0);
        }
        __syncthreads();

        const uint32_t stage = smb + (uint32_t)(s * STAGE_H) * 2u;
        const uint32_t baseAh = stage + (uint32_t)((T_AH + wm * 64 * PH) * 2) + aoff;
        const uint32_t baseAl = stage + (uint32_t)((T_AL + wm * 64 * PH) * 2) + aoff;
        const uint32_t baseBh = stage + (uint32_t)((T_BH + wn * 32 * PH) * 2) + boff;
        const uint32_t baseBl = stage + (uint32_t)((T_BL + wn * 32 * PH) * 2) + boff;

#pragma unroll
        for (int ks = 0; ks < 2; ks++) {
            const uint32_t koff = (uint32_t)(ks * 16 * 2);
            // B fragments: 2 x4 per (hi|lo), each covers an nf-pair
            uint32_t bh[4][2], bl[4][2];
#pragma unroll
            for (int j = 0; j < 2; j++) {
                uint32_t t[4];
                ldsm_x4(t, baseBh + (uint32_t)(j * 16 * PH * 2) + koff);
                bh[2 * j][0] = t[0]; bh[2 * j][1] = t[1];
                bh[2 * j + 1][0] = t[2]; bh[2 * j + 1][1] = t[3];
                ldsm_x4(t, baseBl + (uint32_t)(j * 16 * PH * 2) + koff);
                bl[2 * j][0] = t[0]; bl[2 * j][1] = t[1];
                bl[2 * j + 1][0] = t[2]; bl[2 * j + 1][1] = t[3];
            }
#pragma unroll
            for (int mf = 0; mf < 4; mf++) {
                uint32_t ah[4], al[4];
                ldsm_x4(ah, baseAh + (uint32_t)(mf * 16 * PH * 2) + koff);
                if (!AEX)
                    ldsm_x4(al, baseAl + (uint32_t)(mf * 16 * PH * 2) + koff);
#pragma unroll
                for (int nf = 0; nf < 4; nf++) {
                    mma16(acc[mf][nf], ah, bh[nf]);
                    mma16(acc[mf][nf], ah, bl[nf]);
                    if (!AEX) mma16(acc[mf][nf], al, bh[nf]);
                }
            }
        }
        __syncthreads();
    }

    // ---- Epilogue ----
    const int rA = l >> 2;
    const int cK = l & 3;
#pragma unroll
    for (int nf = 0; nf < 4; nf++) {
        const int col = bn0 + wn * 32 + nf * 8 + 2 * cK;
        const float2 bv = *reinterpret_cast<const float2*>(bias + col);
#pragma unroll
        for (int mf = 0; mf < 4; mf++) {
            const int ra = bm0 + wm * 64 + mf * 16 + rA;
            float y[4];
            y[0] = acc[mf][nf][0] + bv.x;
            y[1] = acc[mf][nf][1] + bv.y;
            y[2] = acc[mf][nf][2] + bv.x;
            y[3] = acc[mf][nf][3] + bv.y;
            if (RELU) {
#pragma unroll
                for (int r = 0; r < 4; r++) y[r] = fmaxf(y[r], 0.0f);
            }
            if (SPLIT) {
                __half h[4], lo[4];
#pragma unroll
                for (int r = 0; r < 4; r++) split_h(y[r], h[r], lo[r]);
                *reinterpret_cast<__half2*>(O_hi + (size_t)ra * Nout + col) =
                    __halves2half2(h[0], h[1]);
                *reinterpret_cast<__half2*>(O_hi + (size_t)(ra + 8) * Nout + col) =
                    __halves2half2(h[2], h[3]);
                *reinterpret_cast<__half2*>(O_lo + (size_t)ra * Nout + col) =
                    __halves2half2(lo[0], lo[1]);
                *reinterpret_cast<__half2*>(O_lo + (size_t)(ra + 8) * Nout + col) =
                    __halves2half2(lo[2], lo[3]);
            } else {
                *reinterpret_cast<float2*>(Of + (size_t)ra * Nout + col) =
                    make_float2(y[0], y[1]);
                *reinterpret_cast<float2*>(Of + (size_t)(ra + 8) * Nout + col) =
                    make_float2(y[2], y[3]);
            }
        }
    }
}

// ---------------------------------------------------------------------------
// Weight transpose + fp16 split: Bt_hi/lo[n][k] = split(W[k][n])
// ---------------------------------------------------------------------------
__global__ void __launch_bounds__(256)
split_wh_kernel(const float* __restrict__ W, __half* __restrict__ bt_hi,
                __half* __restrict__ bt_lo, int K, int N) {
    __shared__ float t[32][33];
    const int kb = blockIdx.x * 32;
    const int nb = blockIdx.y * 32;
    const int tx = threadIdx.x & 31;
    const int ty = threadIdx.x >> 5;
#pragma unroll
    for (int r = ty; r < 32; r += 8)
        t[r][tx] = W[(size_t)(kb + r) * N + nb + tx];
    __syncthreads();
#pragma unroll
    for (int r = ty; r < 32; r += 8) {
        float wv = t[tx][r];
        __half h, lo;
        split_h(wv, h, lo);
        size_t o = (size_t)(nb + r) * K + kb + tx;
        bt_hi[o] = h;
        bt_lo[o] = lo;
    }
}

// x (exact one-hot fp32) -> fp16 (exact)
__global__ void __launch_bounds__(256)
convert_x_kernel(const float* __restrict__ x, __half* __restrict__ xh) {
    const int t = blockIdx.x * 256 + threadIdx.x;   // 8 elems each
    const float4 a = *reinterpret_cast<const float4*>(x + (size_t)t * 8);
    const float4 b = *reinterpret_cast<const float4*>(x + (size_t)t * 8 + 4);
    __half2 o[4];
    o[0] = __halves2half2(__float2half_rn(a.x), __float2half_rn(a.y));
    o[1] = __halves2half2(__float2half_rn(a.z), __float2half_rn(a.w));
    o[2] = __halves2half2(__float2half_rn(b.x), __float2half_rn(b.y));
    o[3] = __halves2half2(__float2half_rn(b.z), __float2half_rn(b.w));
    *reinterpret_cast<uint4*>(xh + (size_t)t * 8) =
        *reinterpret_cast<uint4*>(o);
}

// ---------------------------------------------------------------------------
// Scalar SGEMM for the small selector head (N=64), sigmoid epilogue
// ---------------------------------------------------------------------------
__global__ void __launch_bounds__(256)
sgemm_sig_kernel(const float* __restrict__ A, const float* __restrict__ B,
                 const float* __restrict__ bias, float* __restrict__ C,
                 int M, int N, int K) {
    __shared__ float As[16][128];
    __shared__ float Bs[16][64];

    const int tid = threadIdx.x;
    const int tx = tid & 15;
    const int ty = tid >> 4;
    const int bm0 = blockIdx.y * 128;
    const int bn0 = blockIdx.x * 64;

    float acc[8][4];
#pragma unroll
    for (int i = 0; i < 8; i++)
#pragma unroll
        for (int j = 0; j < 4; j++) acc[i][j] = 0.0f;

    const int nk = K >> 4;
    for (int kt = 0; kt < nk; kt++) {
#pragma unroll
        for (int lq = 0; lq < 2; lq++) {
            int f = tid + lq * 256;
            int row = f >> 2;
            int c4 = (f & 3) << 2;
            float4 v = *reinterpret_cast<const float4*>(
                A + (size_t)(bm0 + row) * K + (kt << 4) + c4);
            As[c4 + 0][row] = v.x;
            As[c4 + 1][row] = v.y;
            As[c4 + 2][row] = v.z;
            As[c4 + 3][row] = v.w;
        }
        {
            int row = tid >> 4;
            int col = (tid & 15) << 2;
            float4 v = *reinterpret_cast<const float4*>(
                B + (size_t)((kt << 4) + row) * N + bn0 + col);
            *reinterpret_cast<float4*>(&Bs[row][col]) = v;
        }
        __syncthreads();

#pragma unroll
        for (int k = 0; k < 16; k++) {
            float4 a0 = *reinterpret_cast<const float4*>(&As[k][ty * 8]);
            float4 a1 = *reinterpret_cast<const float4*>(&As[k][ty * 8 + 4]);
            float4 bv = *reinterpret_cast<const float4*>(&Bs[k][tx * 4]);
            float a[8] = {a0.x, a0.y, a0.z, a0.w, a1.x, a1.y, a1.z, a1.w};
            float bbv[4] = {bv.x, bv.y, bv.z, bv.w};
#pragma unroll
            for (int i = 0; i < 8; i++)
#pragma unroll
                for (int j = 0; j < 4; j++)
                    acc[i][j] = fmaf(a[i], bbv[j], acc[i][j]);
        }
        __syncthreads();
    }

    float4 bvec = *reinterpret_cast<const float4*>(bias + bn0 + tx * 4);
    float bias4[4] = {bvec.x, bvec.y, bvec.z, bvec.w};
#pragma unroll
    for (int i = 0; i < 8; i++) {
        float4 v;
        float* vp = &v.x;
#pragma unroll
        for (int j = 0; j < 4; j++) {
            float c = acc[i][j] + bias4[j];
            vp[j] = 1.0f / (1.0f + expf(-c));
        }
        *reinterpret_cast<float4*>(
            C + (size_t)(bm0 + ty * 8 + i) * N + bn0 + tx * 4) = v;
    }
}

// ---------------------------------------------------------------------------
// Fused elementwise tail (verified rounds 1-5)
// ---------------------------------------------------------------------------
__device__ __forceinline__ void gs8(const float* l, const float* g, float* xt) {
    float m = l[0];
#pragma unroll
    for (int c = 1; c < 8; c++) m = fmaxf(m, l[c]);
    float e[8], s = 0.0f;
#pragma unroll
    for (int c = 0; c < 8; c++) { e[c] = expf(l[c] - m); s += e[c]; }
    float t[8];
#pragma unroll
    for (int c = 0; c < 8; c++) {
        float pr = e[c] / s;
        pr = 0.9f * pr + 0.0125f;
        t[c] = (logf(pr) + g[c]) / 0.7f;
    }
    float m2 = t[0];
#pragma unroll
    for (int c = 1; c < 8; c++) m2 = fmaxf(m2, t[c]);
    float e2[8], s2 = 0.0f;
#pragma unroll
    for (int c = 0; c < 8; c++) { e2[c] = expf(t[c] - m2); s2 += e2[c]; }
#pragma unroll
    for (int c = 0; c < 8; c++) xt[c] = e2[c] / s2;
}

__global__ void finalize_kernel(const float* __restrict__ x,
                                const float* __restrict__ Pm,
                                const float* __restrict__ W,
                                float* __restrict__ xcf) {
    const int b = blockIdx.x;
    const int n = threadIdx.x;   // 64 threads
    __shared__ float sh_cst, sh_incr;

    const size_t base = (size_t)b * DD + n * CC;
    float4 xa = *reinterpret_cast<const float4*>(x + base);
    float4 xb = *reinterpret_cast<const float4*>(x + base + 4);
    float4 wa = *reinterpret_cast<const float4*>(W + base);
    float4 wb = *reinterpret_cast<const float4*>(W + base + 4);
    float xv[8] = {xa.x, xa.y, xa.z, xa.w, xb.x, xb.y, xb.z, xb.w};
    float Wv[8] = {wa.x, wa.y, wa.z, wa.w, wb.x, wb.y, wb.z, wb.w};

    const unsigned i = (unsigned)(b * NN + n);
    const float P = Pm[i];

    float ua = jax_u01(KA0, KA1, i);
    float ub = jax_u01(KB0, KB1, i);
    float ea = expf(-logf(-logf(ua)));
    float eb = expf(-logf(-logf(ub)));
    float no = P * ea / 0.7f;
    float de = no + (1.0f - P) * eb / 0.7f;
    float probs = no / de;

    float g[8];
#pragma unroll
    for (int c = 0; c < 8; c++) {
        float u = jax_u01(KG0, KG1, i * 8u + (unsigned)c);
        g[c] = -logf(-logf(u));
    }

    int curr = 0;
    {
        float m = xv[0];
#pragma unroll
        for (int c = 1; c < 8; c++)
            if (xv[c] > m) { m = xv[c]; curr = c; }
    }

    if (n == 2) {
        float xt_par[8];
        gs8(Wv, g, xt_par);
        int am = 0;
        float m = probs * xt_par[0] + (1.0f - probs) * xv[0];
#pragma unroll
        for (int c = 1; c < 8; c++) {
            float v = probs * xt_par[c] + (1.0f - probs) * xv[c];
            if (v > m) { m = v; am = c; }
        }
        int diff = am - curr;
        sh_cst  = (diff == 0) ? 1.0f : 0.0f;
        sh_incr = (diff >  0) ? 1.0f : 0.0f;
    }
    __syncthreads();
    const float cst = sh_cst;
    const float incr = sh_incr;

    float l[8];
    if (n == 0 || n == 5 || n == 10) {
#pragma unroll
        for (int c = 0; c < 8; c++) l[c] = Wv[c] + ((c < curr) ? -100.0f : 1.0f);
    } else if (n == 7) {
        const int thr = curr + 1;
        const bool inc = (incr > 0.5f);
#pragma unroll
        for (int c = 0; c < 8; c++)
            l[c] = Wv[c] + ((inc && c < thr) ? -100.0f : 1.0f);
    } else {
#pragma unroll
        for (int c = 0; c < 8; c++) l[c] = Wv[c];
    }

    float xt[8];
    gs8(l, g, xt);

    float p2 = probs;
    if (n == 7) {
        float pc = probs * (1.0f - cst);
        pc = pc + incr;
        p2 = fminf(fmaxf(pc, 0.0f), 1.0f);
    }

    float4 oa, ob;
    float* op = &oa.x;
#pragma unroll
    for (int c = 0; c < 4; c++) op[c] = p2 * xt[c] + (1.0f - p2) * xv[c];
    op = &ob.x;
#pragma unroll
    for (int c = 0; c < 4; c++) op[c] = p2 * xt[c + 4] + (1.0f - p2) * xv[c + 4];
    *reinterpret_cast<float4*>(xcf + base) = oa;
    *reinterpret_cast<float4*>(xcf + base + 4) = ob;
}

// ---------------------------------------------------------------------------
// Launch
// ---------------------------------------------------------------------------
extern "C" void kernel_launch(void* const* d_in, const int* in_sizes, int n_in,
                              void* d_out, int out_size) {
    const float* x     = (const float*)d_in[0];
    const float* truth = (const float*)d_in[1];
    const float* sw1   = (const float*)d_in[2];
    const float* sb1   = (const float*)d_in[3];
    const float* sw2   = (const float*)d_in[4];
    const float* sb2   = (const float*)d_in[5];
    const float* pw1   = (const float*)d_in[6];
    const float* pb1   = (const float*)d_in[7];
    const float* pw2   = (const float*)d_in[8];
    const float* pb2   = (const float*)d_in[9];
    const float* pw3   = (const float*)d_in[10];
    const float* pb3   = (const float*)d_in[11];
    const float* pw4   = (const float*)d_in[12];
    const float* pb4   = (const float*)d_in[13];

    float* out       = (float*)d_out;
    float* out_truth = out;
    float* out_xcf   = out + BD_ELEMS;
    float* out_P     = out + 2 * (size_t)BD_ELEMS;
    float* out_W     = out + 2 * (size_t)BD_ELEMS + BN_ELEMS;

    __half *a_hi, *a_lo, *b_hi, *b_lo, *xh, *wt_hi, *wt_lo;
    float *s1;
    cudaGetSymbolAddress((void**)&a_hi, g_a_hi);
    cudaGetSymbolAddress((void**)&a_lo, g_a_lo);
    cudaGetSymbolAddress((void**)&b_hi, g_b_hi);
    cudaGetSymbolAddress((void**)&b_lo, g_b_lo);
    cudaGetSymbolAddress((void**)&xh,   g_xh);
    cudaGetSymbolAddress((void**)&s1,   g_s1);
    cudaGetSymbolAddress((void**)&wt_hi, g_wt_hi);
    cudaGetSymbolAddress((void**)&wt_lo, g_wt_lo);

    cudaFuncSetAttribute(gemm_h<true, true, true>,
                         cudaFuncAttributeMaxDynamicSharedMemorySize, GEMM_SMEM);
    cudaFuncSetAttribute(gemm_h<true, true, false>,
                         cudaFuncAttributeMaxDynamicSharedMemorySize, GEMM_SMEM);
    cudaFuncSetAttribute(gemm_h<false, true, true>,
                         cudaFuncAttributeMaxDynamicSharedMemorySize, GEMM_SMEM);
    cudaFuncSetAttribute(gemm_h<false, false, false>,
                         cudaFuncAttributeMaxDynamicSharedMemorySize, GEMM_SMEM);

    // Input conversions: weight transpose+split, x -> fp16
    convert_x_kernel<<<(BB * DD / 8) / 256, 256>>>(x, xh);
    split_wh_kernel<<<dim3(512 / 32, 1024 / 32), 256>>>(pw1, wt_hi + OF_PW1, wt_lo + OF_PW1, 512, 1024);
    split_wh_kernel<<<dim3(512 / 32,  512 / 32), 256>>>(sw1, wt_hi + OF_SW1, wt_lo + OF_SW1, 512, 512);
    split_wh_kernel<<<dim3(1024 / 32, 1024 / 32), 256>>>(pw2, wt_hi + OF_PW2, wt_lo + OF_PW2, 1024, 1024);
    split_wh_kernel<<<dim3(1024 / 32, 1024 / 32), 256>>>(pw3, wt_hi + OF_PW3, wt_lo + OF_PW3, 1024, 1024);
    split_wh_kernel<<<dim3(1024 / 32,  512 / 32), 256>>>(pw4, wt_hi + OF_PW4, wt_lo + OF_PW4, 1024, 512);

    // MLP path (fp16-split mma.sync + ldmatrix)
    gemm_h<true, true, true><<<dim3(HP / 128, BB / 128), 256, GEMM_SMEM>>>(
        xh, nullptr, wt_hi + OF_PW1, wt_lo + OF_PW1, pb1, a_hi, a_lo, nullptr,
        DD, HP);
    gemm_h<false, true, true><<<dim3(HP / 128, BB / 128), 256, GEMM_SMEM>>>(
        a_hi, a_lo, wt_hi + OF_PW2, wt_lo + OF_PW2, pb2, b_hi, b_lo, nullptr,
        HP, HP);
    gemm_h<false, true, true><<<dim3(HP / 128, BB / 128), 256, GEMM_SMEM>>>(
        b_hi, b_lo, wt_hi + OF_PW3, wt_lo + OF_PW3, pb3, a_hi, a_lo, nullptr,
        HP, HP);
    gemm_h<false, false, false><<<dim3(DD / 128, BB / 128), 256, GEMM_SMEM>>>(
        a_hi, a_lo, wt_hi + OF_PW4, wt_lo + OF_PW4, pb4, nullptr, nullptr,
        out_W, HP, DD);

    // Selector path
    gemm_h<true, true, false><<<dim3(HS / 128, BB / 128), 256, GEMM_SMEM>>>(
        xh, nullptr, wt_hi + OF_SW1, wt_lo + OF_SW1, sb1, nullptr, nullptr,
        s1, DD, HS);
    sgemm_sig_kernel<<<dim3(NN / 64, BB / 128), 256>>>(s1, sw2, sb2, out_P,
                                                       BB, NN, HS);

    // truth_x passthrough
    cudaMemcpyAsync(out_truth, truth, (size_t)BD_ELEMS * sizeof(float),
                    cudaMemcpyDeviceToDevice);
    // Fused tail
    finalize_kernel<<<BB, NN>>>(x, out_P, out_W, out_xcf);
}

// round 7
// speedup vs baseline: 2.4375x; 1.0176x over previous
#include <cuda_runtime.h>
#include <cuda_fp16.h>
#include <cstdint>
#include <math.h>

// ---------------------------------------------------------------------------
// Problem constants
// ---------------------------------------------------------------------------
#define BB 8192
#define NN 64
#define CC 8
#define DD (NN * CC)        // 512
#define HP 1024
#define HS 512
#define BD_ELEMS (BB * DD)  // 4,194,304
#define BN_ELEMS (BB * NN)  // 524,288

// ---------------------------------------------------------------------------
// Scratch (allocation-free: __device__ globals)
// ---------------------------------------------------------------------------
__device__ __half g_a_hi[BB * HP];
__device__ __half g_a_lo[BB * HP];
__device__ __half g_b_hi[BB * HP];
__device__ __half g_b_lo[BB * HP];
__device__ __half g_xh[BB * DD];
__device__ float  g_s1[BB * HS];
__device__ float  g_bias_l1[HP + HS];   // pb1 ++ sb1

// Transposed + split weights, packed (Bt[n][k] layout), fp16 hi/lo.
// pw1t (1024x512) and sw1t (512x512) are contiguous -> combined L1 weight
// of 1536 N-rows @ K=512 starting at offset 0.
#define OF_PW1 0
#define OF_SW1 524288
#define OF_PW2 786432
#define OF_PW3 1835008
#define OF_PW4 2883584
#define WT_TOTAL 3407872
__device__ __half g_wt_hi[WT_TOTAL];
__device__ __half g_wt_lo[WT_TOTAL];

// ---------------------------------------------------------------------------
// Threefry-2x32-20 (JAX)
// ---------------------------------------------------------------------------
struct TFK { unsigned a, b; };

__host__ __device__ constexpr unsigned tf_rotl(unsigned v, int r) {
    return (v << r) | (v >> (32 - r));
}

__host__ __device__ constexpr TFK tf2x32(unsigned k0, unsigned k1,
                                         unsigned x0, unsigned x1) {
    unsigned k2 = k0 ^ k1 ^ 0x1BD11BDAu;
    x0 += k0; x1 += k1;
    x0 += x1; x1 = tf_rotl(x1, 13); x1 ^= x0;
    x0 += x1; x1 = tf_rotl(x1, 15); x1 ^= x0;
    x0 += x1; x1 = tf_rotl(x1, 26); x1 ^= x0;
    x0 += x1; x1 = tf_rotl(x1,  6); x1 ^= x0;
    x0 += k1; x1 += k2 + 1u;
    x0 += x1; x1 = tf_rotl(x1, 17); x1 ^= x0;
    x0 += x1; x1 = tf_rotl(x1, 29); x1 ^= x0;
    x0 += x1; x1 = tf_rotl(x1, 16); x1 ^= x0;
    x0 += x1; x1 = tf_rotl(x1, 24); x1 ^= x0;
    x0 += k2; x1 += k0 + 2u;
    x0 += x1; x1 = tf_rotl(x1, 13); x1 ^= x0;
    x0 += x1; x1 = tf_rotl(x1, 15); x1 ^= x0;
    x0 += x1; x1 = tf_rotl(x1, 26); x1 ^= x0;
    x0 += x1; x1 = tf_rotl(x1,  6); x1 ^= x0;
    x0 += k0; x1 += k1 + 3u;
    x0 += x1; x1 = tf_rotl(x1, 17); x1 ^= x0;
    x0 += x1; x1 = tf_rotl(x1, 29); x1 ^= x0;
    x0 += x1; x1 = tf_rotl(x1, 16); x1 ^= x0;
    x0 += x1; x1 = tf_rotl(x1, 24); x1 ^= x0;
    x0 += k1; x1 += k2 + 4u;
    x0 += x1; x1 = tf_rotl(x1, 13); x1 ^= x0;
    x0 += x1; x1 = tf_rotl(x1, 15); x1 ^= x0;
    x0 += x1; x1 = tf_rotl(x1, 26); x1 ^= x0;
    x0 += x1; x1 = tf_rotl(x1,  6); x1 ^= x0;
    x0 += k2; x1 += k0 + 5u;
    return TFK{x0, x1};
}

constexpr unsigned KA0 = tf2x32(0u, 42u, 0u, 0u).a;
constexpr unsigned KA1 = tf2x32(0u, 42u, 0u, 0u).b;
constexpr unsigned KB0 = tf2x32(0u, 42u, 0u, 1u).a;
constexpr unsigned KB1 = tf2x32(0u, 42u, 0u, 1u).b;
constexpr unsigned KG0 = tf2x32(0u, 42u, 0u, 2u).a;
constexpr unsigned KG1 = tf2x32(0u, 42u, 0u, 2u).b;

__device__ __forceinline__ float jax_u01(unsigned k0, unsigned k1, unsigned idx) {
    TFK r = tf2x32(k0, k1, 0u, idx);
    unsigned bits = r.a ^ r.b;
    float f = __uint_as_float((bits >> 9) | 0x3f800000u) - 1.0f;
    f = f + 1e-8f;
    return fmaxf(1e-8f, f);
}

// ---------------------------------------------------------------------------
// Helpers
// ---------------------------------------------------------------------------
__device__ __forceinline__ uint32_t smem_u32(const void* p) {
    uint32_t a;
    asm("{ .reg .u64 t; cvta.to.shared.u64 t, %1; cvt.u32.u64 %0, t; }"
        : "=r"(a) : "l"(p));
    return a;
}

#define CP16(dst_u32, src_ptr) \
    asm volatile("cp.async.cg.shared.global [%0], [%1], 16;" \
                 :: "r"(dst_u32), "l"(src_ptr) : "memory")
#define CP_COMMIT() asm volatile("cp.async.commit_group;" ::: "memory")
#define CP_WAIT(n)  asm volatile("cp.async.wait_group %0;" :: "n"(n) : "memory")

__device__ __forceinline__ void mma16(float* d, const uint32_t* a,
                                      const uint32_t* b) {
    asm volatile(
        "mma.sync.aligned.m16n8k16.row.col.f32.f16.f16.f32 "
        "{%0,%1,%2,%3}, {%4,%5,%6,%7}, {%8,%9}, {%0,%1,%2,%3};"
        : "+f"(d[0]), "+f"(d[1]), "+f"(d[2]), "+f"(d[3])
        : "r"(a[0]), "r"(a[1]), "r"(a[2]), "r"(a[3]), "r"(b[0]), "r"(b[1]));
}

__device__ __forceinline__ void ldsm_x4(uint32_t* r, uint32_t addr) {
    asm volatile(
        "ldmatrix.sync.aligned.m8n8.x4.shared.b16 {%0,%1,%2,%3}, [%4];"
        : "=r"(r[0]), "=r"(r[1]), "=r"(r[2]), "=r"(r[3]) : "r"(addr));
}

__device__ __forceinline__ void split_h(float y, __half& h, __half& l) {
    h = __float2half_rn(y);
    l = __float2half_rn(y - __half2float(h));
}

// ---------------------------------------------------------------------------
// fp16-split GEMM. BM=128, BN=128, BK=32, 256 threads, warps 2x4 (tile 64x32).
// OMODE: 0 = relu + split (O_hi/O_lo, width Nout)
//        1 = plain fp32 (Of, width Nout)
//        2 = MIXED L1: cols <1024 relu+split into O_hi/O_lo (width HP);
//                      cols >=1024 relu+fp32 into Of=s1 (width HS)
// ---------------------------------------------------------------------------
#define PH 40
#define T_AH 0
#define T_AL (128 * PH)
#define T_BH (2 * 128 * PH)
#define T_BL (3 * 128 * PH)
#define STAGE_H (4 * 128 * PH)
#define GEMM_SMEM (2 * STAGE_H * 2)     // 81920 bytes

template <bool AEX>
__device__ __forceinline__ void issue_chunk_h(
    uint32_t smb, int s, int c,
    const __half* __restrict__ A_hi, const __half* __restrict__ A_lo,
    const __half* __restrict__ B_hi, const __half* __restrict__ B_lo,
    int K, int bm0, int bn0, int tid) {
    const int k0 = c * 32;
    const uint32_t sb = smb + (uint32_t)(s * STAGE_H) * 2u;
#pragma unroll
    for (int i = 0; i < 2; i++) {
        const int f = tid + i * 256;
        const int row = f >> 2;
        const int q = f & 3;
        const uint32_t doff = (uint32_t)(row * PH + q * 8) * 2u;
        CP16(sb + T_AH * 2 + doff, A_hi + (size_t)(bm0 + row) * K + k0 + q * 8);
        if (!AEX)
            CP16(sb + T_AL * 2 + doff,
                 A_lo + (size_t)(bm0 + row) * K + k0 + q * 8);
        CP16(sb + T_BH * 2 + doff, B_hi + (size_t)(bn0 + row) * K + k0 + q * 8);
        CP16(sb + T_BL * 2 + doff, B_lo + (size_t)(bn0 + row) * K + k0 + q * 8);
    }
    CP_COMMIT();
}

template <bool AEX, int OMODE>
__global__ void __launch_bounds__(256, 2)
gemm_h(const __half* __restrict__ A_hi, const __half* __restrict__ A_lo,
       const __half* __restrict__ Bt_hi, const __half* __restrict__ Bt_lo,
       const float* __restrict__ bias,
       __half* __restrict__ O_hi, __half* __restrict__ O_lo,
       float* __restrict__ Of,
       int K, int Nout) {
    extern __shared__ __half smh[];
    const uint32_t smb = smem_u32(smh);
    const int tid = threadIdx.x;
    const int l = tid & 31;
    const int warp = tid >> 5;
    const int wm = warp >> 2;
    const int wn = warp & 3;
    const int bm0 = blockIdx.y * 128;
    const int bn0 = blockIdx.x * 128;
    const int NC = K >> 5;

    float acc[4][4][4];
#pragma unroll
    for (int mf = 0; mf < 4; mf++)
#pragma unroll
        for (int nf = 0; nf < 4; nf++)
#pragma unroll
            for (int r = 0; r < 4; r++) acc[mf][nf][r] = 0.0f;

    issue_chunk_h<AEX>(smb, 0, 0, A_hi, A_lo, Bt_hi, Bt_lo, K, bm0, bn0, tid);

    const uint32_t aoff = (uint32_t)(((l & 15) * PH + (l >> 4) * 8) * 2);
    const uint32_t boff = (uint32_t)(((((l >> 4) & 1) * 8 + (l & 7)) * PH +
                                      ((l >> 3) & 1) * 8) * 2);

    for (int c = 0; c < NC; c++) {
        const int s = c & 1;
        if (c + 1 < NC) {
            issue_chunk_h<AEX>(smb, (c + 1) & 1, c + 1, A_hi, A_lo, Bt_hi,
                               Bt_lo, K, bm0, bn0, tid);
            CP_WAIT(1);
        } else {
            CP_WAIT(0);
        }
        __syncthreads();

        const uint32_t stage = smb + (uint32_t)(s * STAGE_H) * 2u;
        const uint32_t baseAh = stage + (uint32_t)((T_AH + wm * 64 * PH) * 2) + aoff;
        const uint32_t baseAl = stage + (uint32_t)((T_AL + wm * 64 * PH) * 2) + aoff;
        const uint32_t baseBh = stage + (uint32_t)((T_BH + wn * 32 * PH) * 2) + boff;
        const uint32_t baseBl = stage + (uint32_t)((T_BL + wn * 32 * PH) * 2) + boff;

#pragma unroll
        for (int ks = 0; ks < 2; ks++) {
            const uint32_t koff = (uint32_t)(ks * 16 * 2);
            uint32_t bh[4][2], bl[4][2];
#pragma unroll
            for (int j = 0; j < 2; j++) {
                uint32_t t[4];
                ldsm_x4(t, baseBh + (uint32_t)(j * 16 * PH * 2) + koff);
                bh[2 * j][0] = t[0]; bh[2 * j][1] = t[1];
                bh[2 * j + 1][0] = t[2]; bh[2 * j + 1][1] = t[3];
                ldsm_x4(t, baseBl + (uint32_t)(j * 16 * PH * 2) + koff);
                bl[2 * j][0] = t[0]; bl[2 * j][1] = t[1];
                bl[2 * j + 1][0] = t[2]; bl[2 * j + 1][1] = t[3];
            }
#pragma unroll
            for (int mf = 0; mf < 4; mf++) {
                uint32_t ah[4], al[4];
                ldsm_x4(ah, baseAh + (uint32_t)(mf * 16 * PH * 2) + koff);
                if (!AEX)
                    ldsm_x4(al, baseAl + (uint32_t)(mf * 16 * PH * 2) + koff);
#pragma unroll
                for (int nf = 0; nf < 4; nf++) {
                    mma16(acc[mf][nf], ah, bh[nf]);
                    mma16(acc[mf][nf], ah, bl[nf]);
                    if (!AEX) mma16(acc[mf][nf], al, bh[nf]);
                }
            }
        }
        __syncthreads();
    }

    // ---- Epilogue ----
    const int rA = l >> 2;
    const int cK = l & 3;
    const bool f32_region = (OMODE == 1) || (OMODE == 2 && bn0 >= HP);
    const int ow = (OMODE == 2) ? (f32_region ? HS : HP) : Nout;
    const int cbase = (OMODE == 2 && f32_region) ? (bn0 - HP) : bn0;

#pragma unroll
    for (int nf = 0; nf < 4; nf++) {
        const int gcol = bn0 + wn * 32 + nf * 8 + 2 * cK;     // bias index
        const int col = cbase + wn * 32 + nf * 8 + 2 * cK;    // output index
        const float2 bv = *reinterpret_cast<const float2*>(bias + gcol);
#pragma unroll
        for (int mf = 0; mf < 4; mf++) {
            const int ra = bm0 + wm * 64 + mf * 16 + rA;
            float y[4];
            y[0] = acc[mf][nf][0] + bv.x;
            y[1] = acc[mf][nf][1] + bv.y;
            y[2] = acc[mf][nf][2] + bv.x;
            y[3] = acc[mf][nf][3] + bv.y;
            if (OMODE != 1) {
#pragma unroll
                for (int r = 0; r < 4; r++) y[r] = fmaxf(y[r], 0.0f);
            }
            if (!f32_region && OMODE != 1) {
                __half h[4], lo[4];
#pragma unroll
                for (int r = 0; r < 4; r++) split_h(y[r], h[r], lo[r]);
                *reinterpret_cast<__half2*>(O_hi + (size_t)ra * ow + col) =
                    __halves2half2(h[0], h[1]);
                *reinterpret_cast<__half2*>(O_hi + (size_t)(ra + 8) * ow + col) =
                    __halves2half2(h[2], h[3]);
                *reinterpret_cast<__half2*>(O_lo + (size_t)ra * ow + col) =
                    __halves2half2(lo[0], lo[1]);
                *reinterpret_cast<__half2*>(O_lo + (size_t)(ra + 8) * ow + col) =
                    __halves2half2(lo[2], lo[3]);
            } else {
                *reinterpret_cast<float2*>(Of + (size_t)ra * ow + col) =
                    make_float2(y[0], y[1]);
                *reinterpret_cast<float2*>(Of + (size_t)(ra + 8) * ow + col) =
                    make_float2(y[2], y[3]);
            }
        }
    }
}

// ---------------------------------------------------------------------------
// ONE merged weight transpose+split kernel for all 5 weights.
// Each block = one 32x32 tile. Table dispatch on blockIdx.x.
// ---------------------------------------------------------------------------
__global__ void __launch_bounds__(256)
split_all_kernel(const float* __restrict__ pw1, const float* __restrict__ sw1,
                 const float* __restrict__ pw2, const float* __restrict__ pw3,
                 const float* __restrict__ pw4,
                 __half* __restrict__ bt_hi, __half* __restrict__ bt_lo) {
    const int b = blockIdx.x;
    const float* W;
    int off, K, N, lb;
    if (b < 512)        { W = pw1; off = OF_PW1; K = 512;  N = 1024; lb = b; }
    else if (b < 768)   { W = sw1; off = OF_SW1; K = 512;  N = 512;  lb = b - 512; }
    else if (b < 1792)  { W = pw2; off = OF_PW2; K = 1024; N = 1024; lb = b - 768; }
    else if (b < 2816)  { W = pw3; off = OF_PW3; K = 1024; N = 1024; lb = b - 1792; }
    else                { W = pw4; off = OF_PW4; K = 1024; N = 512;  lb = b - 2816; }
    const int kt = K >> 5;
    const int kb = (lb % kt) * 32;
    const int nb = (lb / kt) * 32;

    __shared__ float t[32][33];
    const int tx = threadIdx.x & 31;
    const int ty = threadIdx.x >> 5;
#pragma unroll
    for (int r = ty; r < 32; r += 8)
        t[r][tx] = W[(size_t)(kb + r) * N + nb + tx];
    __syncthreads();
#pragma unroll
    for (int r = ty; r < 32; r += 8) {
        float wv = t[tx][r];
        __half h, lo;
        split_h(wv, h, lo);
        size_t o = (size_t)off + (size_t)(nb + r) * K + kb + tx;
        bt_hi[o] = h;
        bt_lo[o] = lo;
    }
}

// x (exact one-hot fp32) -> fp16 (exact), plus bias concat (pb1 ++ sb1)
__global__ void __launch_bounds__(256)
convert_x_kernel(const float* __restrict__ x, __half* __restrict__ xh,
                 const float* __restrict__ pb1, const float* __restrict__ sb1,
                 float* __restrict__ bias_l1) {
    const int t = blockIdx.x * 256 + threadIdx.x;
    const float4 a = *reinterpret_cast<const float4*>(x + (size_t)t * 8);
    const float4 b = *reinterpret_cast<const float4*>(x + (size_t)t * 8 + 4);
    __half2 o[4];
    o[0] = __halves2half2(__float2half_rn(a.x), __float2half_rn(a.y));
    o[1] = __halves2half2(__float2half_rn(a.z), __float2half_rn(a.w));
    o[2] = __halves2half2(__float2half_rn(b.x), __float2half_rn(b.y));
    o[3] = __halves2half2(__float2half_rn(b.z), __float2half_rn(b.w));
    *reinterpret_cast<uint4*>(xh + (size_t)t * 8) =
        *reinterpret_cast<uint4*>(o);
    if (t < HP + HS)
        bias_l1[t] = (t < HP) ? pb1[t] : sb1[t - HP];
}

// ---------------------------------------------------------------------------
// Scalar SGEMM for the small selector head (N=64), sigmoid epilogue
// ---------------------------------------------------------------------------
__global__ void __launch_bounds__(256)
sgemm_sig_kernel(const float* __restrict__ A, const float* __restrict__ B,
                 const float* __restrict__ bias, float* __restrict__ C,
                 int M, int N, int K) {
    __shared__ float As[16][128];
    __shared__ float Bs[16][64];

    const int tid = threadIdx.x;
    const int tx = tid & 15;
    const int ty = tid >> 4;
    const int bm0 = blockIdx.y * 128;
    const int bn0 = blockIdx.x * 64;

    float acc[8][4];
#pragma unroll
    for (int i = 0; i < 8; i++)
#pragma unroll
        for (int j = 0; j < 4; j++) acc[i][j] = 0.0f;

    const int nk = K >> 4;
    for (int kt = 0; kt < nk; kt++) {
#pragma unroll
        for (int lq = 0; lq < 2; lq++) {
            int f = tid + lq * 256;
            int row = f >> 2;
            int c4 = (f & 3) << 2;
            float4 v = *reinterpret_cast<const float4*>(
                A + (size_t)(bm0 + row) * K + (kt << 4) + c4);
            As[c4 + 0][row] = v.x;
            As[c4 + 1][row] = v.y;
            As[c4 + 2][row] = v.z;
            As[c4 + 3][row] = v.w;
        }
        {
            int row = tid >> 4;
            int col = (tid & 15) << 2;
            float4 v = *reinterpret_cast<const float4*>(
                B + (size_t)((kt << 4) + row) * N + bn0 + col);
            *reinterpret_cast<float4*>(&Bs[row][col]) = v;
        }
        __syncthreads();

#pragma unroll
        for (int k = 0; k < 16; k++) {
            float4 a0 = *reinterpret_cast<const float4*>(&As[k][ty * 8]);
            float4 a1 = *reinterpret_cast<const float4*>(&As[k][ty * 8 + 4]);
            float4 bv = *reinterpret_cast<const float4*>(&Bs[k][tx * 4]);
            float a[8] = {a0.x, a0.y, a0.z, a0.w, a1.x, a1.y, a1.z, a1.w};
            float bbv[4] = {bv.x, bv.y, bv.z, bv.w};
#pragma unroll
            for (int i = 0; i < 8; i++)
#pragma unroll
                for (int j = 0; j < 4; j++)
                    acc[i][j] = fmaf(a[i], bbv[j], acc[i][j]);
        }
        __syncthreads();
    }

    float4 bvec = *reinterpret_cast<const float4*>(bias + bn0 + tx * 4);
    float bias4[4] = {bvec.x, bvec.y, bvec.z, bvec.w};
#pragma unroll
    for (int i = 0; i < 8; i++) {
        float4 v;
        float* vp = &v.x;
#pragma unroll
        for (int j = 0; j < 4; j++) {
            float c = acc[i][j] + bias4[j];
            vp[j] = 1.0f / (1.0f + expf(-c));
        }
        *reinterpret_cast<float4*>(
            C + (size_t)(bm0 + ty * 8 + i) * N + bn0 + tx * 4) = v;
    }
}

// ---------------------------------------------------------------------------
// Fused elementwise tail (verified rounds 1-6)
// ---------------------------------------------------------------------------
__device__ __forceinline__ void gs8(const float* l, const float* g, float* xt) {
    float m = l[0];
#pragma unroll
    for (int c = 1; c < 8; c++) m = fmaxf(m, l[c]);
    float e[8], s = 0.0f;
#pragma unroll
    for (int c = 0; c < 8; c++) { e[c] = expf(l[c] - m); s += e[c]; }
    float t[8];
#pragma unroll
    for (int c = 0; c < 8; c++) {
        float pr = e[c] / s;
        pr = 0.9f * pr + 0.0125f;
        t[c] = (logf(pr) + g[c]) / 0.7f;
    }
    float m2 = t[0];
#pragma unroll
    for (int c = 1; c < 8; c++) m2 = fmaxf(m2, t[c]);
    float e2[8], s2 = 0.0f;
#pragma unroll
    for (int c = 0; c < 8; c++) { e2[c] = expf(t[c] - m2); s2 += e2[c]; }
#pragma unroll
    for (int c = 0; c < 8; c++) xt[c] = e2[c] / s2;
}

__global__ void finalize_kernel(const float* __restrict__ x,
                                const float* __restrict__ Pm,
                                const float* __restrict__ W,
                                float* __restrict__ xcf) {
    const int b = blockIdx.x;
    const int n = threadIdx.x;
    __shared__ float sh_cst, sh_incr;

    const size_t base = (size_t)b * DD + n * CC;
    float4 xa = *reinterpret_cast<const float4*>(x + base);
    float4 xb = *reinterpret_cast<const float4*>(x + base + 4);
    float4 wa = *reinterpret_cast<const float4*>(W + base);
    float4 wb = *reinterpret_cast<const float4*>(W + base + 4);
    float xv[8] = {xa.x, xa.y, xa.z, xa.w, xb.x, xb.y, xb.z, xb.w};
    float Wv[8] = {wa.x, wa.y, wa.z, wa.w, wb.x, wb.y, wb.z, wb.w};

    const unsigned i = (unsigned)(b * NN + n);
    const float P = Pm[i];

    float ua = jax_u01(KA0, KA1, i);
    float ub = jax_u01(KB0, KB1, i);
    float ea = expf(-logf(-logf(ua)));
    float eb = expf(-logf(-logf(ub)));
    float no = P * ea / 0.7f;
    float de = no + (1.0f - P) * eb / 0.7f;
    float probs = no / de;

    float g[8];
#pragma unroll
    for (int c = 0; c < 8; c++) {
        float u = jax_u01(KG0, KG1, i * 8u + (unsigned)c);
        g[c] = -logf(-logf(u));
    }

    int curr = 0;
    {
        float m = xv[0];
#pragma unroll
        for (int c = 1; c < 8; c++)
            if (xv[c] > m) { m = xv[c]; curr = c; }
    }

    if (n == 2) {
        float xt_par[8];
        gs8(Wv, g, xt_par);
        int am = 0;
        float m = probs * xt_par[0] + (1.0f - probs) * xv[0];
#pragma unroll
        for (int c = 1; c < 8; c++) {
            float v = probs * xt_par[c] + (1.0f - probs) * xv[c];
            if (v > m) { m = v; am = c; }
        }
        int diff = am - curr;
        sh_cst  = (diff == 0) ? 1.0f : 0.0f;
        sh_incr = (diff >  0) ? 1.0f : 0.0f;
    }
    __syncthreads();
    const float cst = sh_cst;
    const float incr = sh_incr;

    float l[8];
    if (n == 0 || n == 5 || n == 10) {
#pragma unroll
        for (int c = 0; c < 8; c++) l[c] = Wv[c] + ((c < curr) ? -100.0f : 1.0f);
    } else if (n == 7) {
        const int thr = curr + 1;
        const bool inc = (incr > 0.5f);
#pragma unroll
        for (int c = 0; c < 8; c++)
            l[c] = Wv[c] + ((inc && c < thr) ? -100.0f : 1.0f);
    } else {
#pragma unroll
        for (int c = 0; c < 8; c++) l[c] = Wv[c];
    }

    float xt[8];
    gs8(l, g, xt);

    float p2 = probs;
    if (n == 7) {
        float pc = probs * (1.0f - cst);
        pc = pc + incr;
        p2 = fminf(fmaxf(pc, 0.0f), 1.0f);
    }

    float4 oa, ob;
    float* op = &oa.x;
#pragma unroll
    for (int c = 0; c < 4; c++) op[c] = p2 * xt[c] + (1.0f - p2) * xv[c];
    op = &ob.x;
#pragma unroll
    for (int c = 0; c < 4; c++) op[c] = p2 * xt[c + 4] + (1.0f - p2) * xv[c + 4];
    *reinterpret_cast<float4*>(xcf + base) = oa;
    *reinterpret_cast<float4*>(xcf + base + 4) = ob;
}

// ---------------------------------------------------------------------------
// Launch
// ---------------------------------------------------------------------------
extern "C" void kernel_launch(void* const* d_in, const int* in_sizes, int n_in,
                              void* d_out, int out_size) {
    const float* x     = (const float*)d_in[0];
    const float* truth = (const float*)d_in[1];
    const float* sw1   = (const float*)d_in[2];
    const float* sb1   = (const float*)d_in[3];
    const float* sw2   = (const float*)d_in[4];
    const float* sb2   = (const float*)d_in[5];
    const float* pw1   = (const float*)d_in[6];
    const float* pb1   = (const float*)d_in[7];
    const float* pw2   = (const float*)d_in[8];
    const float* pb2   = (const float*)d_in[9];
    const float* pw3   = (const float*)d_in[10];
    const float* pb3   = (const float*)d_in[11];
    const float* pw4   = (const float*)d_in[12];
    const float* pb4   = (const float*)d_in[13];

    float* out       = (float*)d_out;
    float* out_truth = out;
    float* out_xcf   = out + BD_ELEMS;
    float* out_P     = out + 2 * (size_t)BD_ELEMS;
    float* out_W     = out + 2 * (size_t)BD_ELEMS + BN_ELEMS;

    __half *a_hi, *a_lo, *b_hi, *b_lo, *xh, *wt_hi, *wt_lo;
    float *s1, *bias_l1;
    cudaGetSymbolAddress((void**)&a_hi, g_a_hi);
    cudaGetSymbolAddress((void**)&a_lo, g_a_lo);
    cudaGetSymbolAddress((void**)&b_hi, g_b_hi);
    cudaGetSymbolAddress((void**)&b_lo, g_b_lo);
    cudaGetSymbolAddress((void**)&xh,   g_xh);
    cudaGetSymbolAddress((void**)&s1,   g_s1);
    cudaGetSymbolAddress((void**)&wt_hi, g_wt_hi);
    cudaGetSymbolAddress((void**)&wt_lo, g_wt_lo);
    cudaGetSymbolAddress((void**)&bias_l1, g_bias_l1);

    cudaFuncSetAttribute(gemm_h<true, 2>,
                         cudaFuncAttributeMaxDynamicSharedMemorySize, GEMM_SMEM);
    cudaFuncSetAttribute(gemm_h<false, 0>,
                         cudaFuncAttributeMaxDynamicSharedMemorySize, GEMM_SMEM);
    cudaFuncSetAttribute(gemm_h<false, 1>,
                         cudaFuncAttributeMaxDynamicSharedMemorySize, GEMM_SMEM);

    // Conversions: x -> fp16 (+ L1 bias concat), all weight splits in one go
    convert_x_kernel<<<(BB * DD / 8) / 256, 256>>>(x, xh, pb1, sb1, bias_l1);
    split_all_kernel<<<3328, 256>>>(pw1, sw1, pw2, pw3, pw4, wt_hi, wt_lo);

    // L1 (pw1 + sw1 merged, AEX, mixed epilogue)
    gemm_h<true, 2><<<dim3((HP + HS) / 128, BB / 128), 256, GEMM_SMEM>>>(
        xh, nullptr, wt_hi, wt_lo, bias_l1, a_hi, a_lo, s1, DD, HP);
    // Selector head can start as soon as s1 is ready
    sgemm_sig_kernel<<<dim3(NN / 64, BB / 128), 256>>>(s1, sw2, sb2, out_P,
                                                       BB, NN, HS);
    // MLP layers 2-4
    gemm_h<false, 0><<<dim3(HP / 128, BB / 128), 256, GEMM_SMEM>>>(
        a_hi, a_lo, wt_hi + OF_PW2, wt_lo + OF_PW2, pb2, b_hi, b_lo, nullptr,
        HP, HP);
    gemm_h<false, 0><<<dim3(HP / 128, BB / 128), 256, GEMM_SMEM>>>(
        b_hi, b_lo, wt_hi + OF_PW3, wt_lo + OF_PW3, pb3, a_hi, a_lo, nullptr,
        HP, HP);
    gemm_h<false, 1><<<dim3(DD / 128, BB / 128), 256, GEMM_SMEM>>>(
        a_hi, a_lo, wt_hi + OF_PW4, wt_lo + OF_PW4, pb4, nullptr, nullptr,
        out_W, HP, DD);

    // truth_x passthrough
    cudaMemcpyAsync(out_truth, truth, (size_t)BD_ELEMS * sizeof(float),
                    cudaMemcpyDeviceToDevice);
    // Fused tail
    finalize_kernel<<<BB, NN>>>(x, out_P, out_W, out_xcf);
}

// round 8
// speedup vs baseline: 2.4947x; 1.0235x over previous
#include <cuda_runtime.h>
#include <cuda_fp16.h>
#include <cstdint>
#include <math.h>

// ---------------------------------------------------------------------------
// Problem constants
// ---------------------------------------------------------------------------
#define BB 8192
#define NN 64
#define CC 8
#define DD (NN * CC)        // 512
#define HP 1024
#define HS 512
#define BD_ELEMS (BB * DD)  // 4,194,304
#define BN_ELEMS (BB * NN)  // 524,288

// ---------------------------------------------------------------------------
// Scratch (allocation-free: __device__ globals)
// ---------------------------------------------------------------------------
__device__ __half g_a_hi[BB * HP];
__device__ __half g_a_lo[BB * HP];
__device__ __half g_b_hi[BB * HP];
__device__ __half g_b_lo[BB * HP];
__device__ __half g_xh[BB * DD];
__device__ float  g_s1[BB * HS];
__device__ float  g_bias_l1[HP + HS];   // pb1 ++ sb1

// Transposed + split weights, packed (Bt[n][k] layout), fp16 hi/lo.
// pw1t (1024x512) and sw1t (512x512) are contiguous -> combined L1 weight
// of 1536 N-rows @ K=512 starting at offset 0.
#define OF_PW1 0
#define OF_SW1 524288
#define OF_PW2 786432
#define OF_PW3 1835008
#define OF_PW4 2883584
#define WT_TOTAL 3407872
__device__ __half g_wt_hi[WT_TOTAL];
__device__ __half g_wt_lo[WT_TOTAL];

// ---------------------------------------------------------------------------
// Threefry-2x32-20 (JAX)
// ---------------------------------------------------------------------------
struct TFK { unsigned a, b; };

__host__ __device__ constexpr unsigned tf_rotl(unsigned v, int r) {
    return (v << r) | (v >> (32 - r));
}

__host__ __device__ constexpr TFK tf2x32(unsigned k0, unsigned k1,
                                         unsigned x0, unsigned x1) {
    unsigned k2 = k0 ^ k1 ^ 0x1BD11BDAu;
    x0 += k0; x1 += k1;
    x0 += x1; x1 = tf_rotl(x1, 13); x1 ^= x0;
    x0 += x1; x1 = tf_rotl(x1, 15); x1 ^= x0;
    x0 += x1; x1 = tf_rotl(x1, 26); x1 ^= x0;
    x0 += x1; x1 = tf_rotl(x1,  6); x1 ^= x0;
    x0 += k1; x1 += k2 + 1u;
    x0 += x1; x1 = tf_rotl(x1, 17); x1 ^= x0;
    x0 += x1; x1 = tf_rotl(x1, 29); x1 ^= x0;
    x0 += x1; x1 = tf_rotl(x1, 16); x1 ^= x0;
    x0 += x1; x1 = tf_rotl(x1, 24); x1 ^= x0;
    x0 += k2; x1 += k0 + 2u;
    x0 += x1; x1 = tf_rotl(x1, 13); x1 ^= x0;
    x0 += x1; x1 = tf_rotl(x1, 15); x1 ^= x0;
    x0 += x1; x1 = tf_rotl(x1, 26); x1 ^= x0;
    x0 += x1; x1 = tf_rotl(x1,  6); x1 ^= x0;
    x0 += k0; x1 += k1 + 3u;
    x0 += x1; x1 = tf_rotl(x1, 17); x1 ^= x0;
    x0 += x1; x1 = tf_rotl(x1, 29); x1 ^= x0;
    x0 += x1; x1 = tf_rotl(x1, 16); x1 ^= x0;
    x0 += x1; x1 = tf_rotl(x1, 24); x1 ^= x0;
    x0 += k1; x1 += k2 + 4u;
    x0 += x1; x1 = tf_rotl(x1, 13); x1 ^= x0;
    x0 += x1; x1 = tf_rotl(x1, 15); x1 ^= x0;
    x0 += x1; x1 = tf_rotl(x1, 26); x1 ^= x0;
    x0 += x1; x1 = tf_rotl(x1,  6); x1 ^= x0;
    x0 += k2; x1 += k0 + 5u;
    return TFK{x0, x1};
}

constexpr unsigned KA0 = tf2x32(0u, 42u, 0u, 0u).a;
constexpr unsigned KA1 = tf2x32(0u, 42u, 0u, 0u).b;
constexpr unsigned KB0 = tf2x32(0u, 42u, 0u, 1u).a;
constexpr unsigned KB1 = tf2x32(0u, 42u, 0u, 1u).b;
constexpr unsigned KG0 = tf2x32(0u, 42u, 0u, 2u).a;
constexpr unsigned KG1 = tf2x32(0u, 42u, 0u, 2u).b;

__device__ __forceinline__ float jax_u01(unsigned k0, unsigned k1, unsigned idx) {
    TFK r = tf2x32(k0, k1, 0u, idx);
    unsigned bits = r.a ^ r.b;
    float f = __uint_as_float((bits >> 9) | 0x3f800000u) - 1.0f;
    f = f + 1e-8f;
    return fmaxf(1e-8f, f);
}

// ---------------------------------------------------------------------------
// Helpers
// ---------------------------------------------------------------------------
__device__ __forceinline__ uint32_t smem_u32(const void* p) {
    uint32_t a;
    asm("{ .reg .u64 t; cvta.to.shared.u64 t, %1; cvt.u32.u64 %0, t; }"
        : "=r"(a) : "l"(p));
    return a;
}

#define CP16(dst_u32, src_ptr) \
    asm volatile("cp.async.cg.shared.global [%0], [%1], 16;" \
                 :: "r"(dst_u32), "l"(src_ptr) : "memory")
#define CP_COMMIT() asm volatile("cp.async.commit_group;" ::: "memory")
#define CP_WAIT(n)  asm volatile("cp.async.wait_group %0;" :: "n"(n) : "memory")

__device__ __forceinline__ void mma16(float* d, const uint32_t* a,
                                      const uint32_t* b) {
    asm volatile(
        "mma.sync.aligned.m16n8k16.row.col.f32.f16.f16.f32 "
        "{%0,%1,%2,%3}, {%4,%5,%6,%7}, {%8,%9}, {%0,%1,%2,%3};"
        : "+f"(d[0]), "+f"(d[1]), "+f"(d[2]), "+f"(d[3])
        : "r"(a[0]), "r"(a[1]), "r"(a[2]), "r"(a[3]), "r"(b[0]), "r"(b[1]));
}

__device__ __forceinline__ void ldsm_x4(uint32_t* r, uint32_t addr) {
    asm volatile(
        "ldmatrix.sync.aligned.m8n8.x4.shared.b16 {%0,%1,%2,%3}, [%4];"
        : "=r"(r[0]), "=r"(r[1]), "=r"(r[2]), "=r"(r[3]) : "r"(addr));
}

__device__ __forceinline__ void split_h(float y, __half& h, __half& l) {
    h = __float2half_rn(y);
    l = __float2half_rn(y - __half2float(h));
}

// ---------------------------------------------------------------------------
// fp16-split GEMM. BM=128, BN=128, BK=32, 256 threads, warps 2x4 (tile 64x32).
// OMODE: 0 = relu + split (O_hi/O_lo, width Nout)
//        1 = plain fp32 (Of, width Nout)
//        2 = MIXED L1: cols <1024 relu+split into O_hi/O_lo (width HP);
//                      cols >=1024 relu+fp32 into Of=s1 (width HS)
// ---------------------------------------------------------------------------
#define PH 40
#define T_AH 0
#define T_AL (128 * PH)
#define T_BH (2 * 128 * PH)
#define T_BL (3 * 128 * PH)
#define STAGE_H (4 * 128 * PH)
#define GEMM_SMEM (2 * STAGE_H * 2)     // 81920 bytes

template <bool AEX>
__device__ __forceinline__ void issue_chunk_h(
    uint32_t smb, int s, int c,
    const __half* __restrict__ A_hi, const __half* __restrict__ A_lo,
    const __half* __restrict__ B_hi, const __half* __restrict__ B_lo,
    int K, int bm0, int bn0, int tid) {
    const int k0 = c * 32;
    const uint32_t sb = smb + (uint32_t)(s * STAGE_H) * 2u;
#pragma unroll
    for (int i = 0; i < 2; i++) {
        const int f = tid + i * 256;
        const int row = f >> 2;
        const int q = f & 3;
        const uint32_t doff = (uint32_t)(row * PH + q * 8) * 2u;
        CP16(sb + T_AH * 2 + doff, A_hi + (size_t)(bm0 + row) * K + k0 + q * 8);
        if (!AEX)
            CP16(sb + T_AL * 2 + doff,
                 A_lo + (size_t)(bm0 + row) * K + k0 + q * 8);
        CP16(sb + T_BH * 2 + doff, B_hi + (size_t)(bn0 + row) * K + k0 + q * 8);
        CP16(sb + T_BL * 2 + doff, B_lo + (size_t)(bn0 + row) * K + k0 + q * 8);
    }
    CP_COMMIT();
}

template <bool AEX, int OMODE>
__global__ void __launch_bounds__(256, 2)
gemm_h(const __half* __restrict__ A_hi, const __half* __restrict__ A_lo,
       const __half* __restrict__ Bt_hi, const __half* __restrict__ Bt_lo,
       const float* __restrict__ bias,
       __half* __restrict__ O_hi, __half* __restrict__ O_lo,
       float* __restrict__ Of,
       int K, int Nout) {
    extern __shared__ __half smh[];
    const uint32_t smb = smem_u32(smh);
    const int tid = threadIdx.x;
    const int l = tid & 31;
    const int warp = tid >> 5;
    const int wm = warp >> 2;
    const int wn = warp & 3;
    const int bm0 = blockIdx.y * 128;
    const int bn0 = blockIdx.x * 128;
    const int NC = K >> 5;

    float acc[4][4][4];
#pragma unroll
    for (int mf = 0; mf < 4; mf++)
#pragma unroll
        for (int nf = 0; nf < 4; nf++)
#pragma unroll
            for (int r = 0; r < 4; r++) acc[mf][nf][r] = 0.0f;

    issue_chunk_h<AEX>(smb, 0, 0, A_hi, A_lo, Bt_hi, Bt_lo, K, bm0, bn0, tid);

    const uint32_t aoff = (uint32_t)(((l & 15) * PH + (l >> 4) * 8) * 2);
    const uint32_t boff = (uint32_t)(((((l >> 4) & 1) * 8 + (l & 7)) * PH +
                                      ((l >> 3) & 1) * 8) * 2);

    for (int c = 0; c < NC; c++) {
        const int s = c & 1;
        if (c + 1 < NC) {
            issue_chunk_h<AEX>(smb, (c + 1) & 1, c + 1, A_hi, A_lo, Bt_hi,
                               Bt_lo, K, bm0, bn0, tid);
            CP_WAIT(1);
        } else {
            CP_WAIT(0);
        }
        __syncthreads();

        const uint32_t stage = smb + (uint32_t)(s * STAGE_H) * 2u;
        const uint32_t baseAh = stage + (uint32_t)((T_AH + wm * 64 * PH) * 2) + aoff;
        const uint32_t baseAl = stage + (uint32_t)((T_AL + wm * 64 * PH) * 2) + aoff;
        const uint32_t baseBh = stage + (uint32_t)((T_BH + wn * 32 * PH) * 2) + boff;
        const uint32_t baseBl = stage + (uint32_t)((T_BL + wn * 32 * PH) * 2) + boff;

#pragma unroll
        for (int ks = 0; ks < 2; ks++) {
            const uint32_t koff = (uint32_t)(ks * 16 * 2);
            uint32_t bh[4][2], bl[4][2];
#pragma unroll
            for (int j = 0; j < 2; j++) {
                uint32_t t[4];
                ldsm_x4(t, baseBh + (uint32_t)(j * 16 * PH * 2) + koff);
                bh[2 * j][0] = t[0]; bh[2 * j][1] = t[1];
                bh[2 * j + 1][0] = t[2]; bh[2 * j + 1][1] = t[3];
                ldsm_x4(t, baseBl + (uint32_t)(j * 16 * PH * 2) + koff);
                bl[2 * j][0] = t[0]; bl[2 * j][1] = t[1];
                bl[2 * j + 1][0] = t[2]; bl[2 * j + 1][1] = t[3];
            }
#pragma unroll
            for (int mf = 0; mf < 4; mf++) {
                uint32_t ah[4], al[4];
                ldsm_x4(ah, baseAh + (uint32_t)(mf * 16 * PH * 2) + koff);
                if (!AEX)
                    ldsm_x4(al, baseAl + (uint32_t)(mf * 16 * PH * 2) + koff);
#pragma unroll
                for (int nf = 0; nf < 4; nf++) {
                    mma16(acc[mf][nf], ah, bh[nf]);
                    mma16(acc[mf][nf], ah, bl[nf]);
                    if (!AEX) mma16(acc[mf][nf], al, bh[nf]);
                }
            }
        }
        __syncthreads();
    }

    // ---- Epilogue ----
    const int rA = l >> 2;
    const int cK = l & 3;
    const bool f32_region = (OMODE == 1) || (OMODE == 2 && bn0 >= HP);
    const int ow = (OMODE == 2) ? (f32_region ? HS : HP) : Nout;
    const int cbase = (OMODE == 2 && f32_region) ? (bn0 - HP) : bn0;

#pragma unroll
    for (int nf = 0; nf < 4; nf++) {
        const int gcol = bn0 + wn * 32 + nf * 8 + 2 * cK;     // bias index
        const int col = cbase + wn * 32 + nf * 8 + 2 * cK;    // output index
        const float2 bv = *reinterpret_cast<const float2*>(bias + gcol);
#pragma unroll
        for (int mf = 0; mf < 4; mf++) {
            const int ra = bm0 + wm * 64 + mf * 16 + rA;
            float y[4];
            y[0] = acc[mf][nf][0] + bv.x;
            y[1] = acc[mf][nf][1] + bv.y;
            y[2] = acc[mf][nf][2] + bv.x;
            y[3] = acc[mf][nf][3] + bv.y;
            if (OMODE != 1) {
#pragma unroll
                for (int r = 0; r < 4; r++) y[r] = fmaxf(y[r], 0.0f);
            }
            if (!f32_region && OMODE != 1) {
                __half h[4], lo[4];
#pragma unroll
                for (int r = 0; r < 4; r++) split_h(y[r], h[r], lo[r]);
                *reinterpret_cast<__half2*>(O_hi + (size_t)ra * ow + col) =
                    __halves2half2(h[0], h[1]);
                *reinterpret_cast<__half2*>(O_hi + (size_t)(ra + 8) * ow + col) =
                    __halves2half2(h[2], h[3]);
                *reinterpret_cast<__half2*>(O_lo + (size_t)ra * ow + col) =
                    __halves2half2(lo[0], lo[1]);
                *reinterpret_cast<__half2*>(O_lo + (size_t)(ra + 8) * ow + col) =
                    __halves2half2(lo[2], lo[3]);
            } else {
                *reinterpret_cast<float2*>(Of + (size_t)ra * ow + col) =
                    make_float2(y[0], y[1]);
                *reinterpret_cast<float2*>(Of + (size_t)(ra + 8) * ow + col) =
                    make_float2(y[2], y[3]);
            }
        }
    }
}

// ---------------------------------------------------------------------------
// ONE merged weight transpose+split kernel for all 5 weights.
// ---------------------------------------------------------------------------
__global__ void __launch_bounds__(256)
split_all_kernel(const float* __restrict__ pw1, const float* __restrict__ sw1,
                 const float* __restrict__ pw2, const float* __restrict__ pw3,
                 const float* __restrict__ pw4,
                 __half* __restrict__ bt_hi, __half* __restrict__ bt_lo) {
    const int b = blockIdx.x;
    const float* W;
    int off, K, N, lb;
    if (b < 512)        { W = pw1; off = OF_PW1; K = 512;  N = 1024; lb = b; }
    else if (b < 768)   { W = sw1; off = OF_SW1; K = 512;  N = 512;  lb = b - 512; }
    else if (b < 1792)  { W = pw2; off = OF_PW2; K = 1024; N = 1024; lb = b - 768; }
    else if (b < 2816)  { W = pw3; off = OF_PW3; K = 1024; N = 1024; lb = b - 1792; }
    else                { W = pw4; off = OF_PW4; K = 1024; N = 512;  lb = b - 2816; }
    const int kt = K >> 5;
    const int kb = (lb % kt) * 32;
    const int nb = (lb / kt) * 32;

    __shared__ float t[32][33];
    const int tx = threadIdx.x & 31;
    const int ty = threadIdx.x >> 5;
#pragma unroll
    for (int r = ty; r < 32; r += 8)
        t[r][tx] = W[(size_t)(kb + r) * N + nb + tx];
    __syncthreads();
#pragma unroll
    for (int r = ty; r < 32; r += 8) {
        float wv = t[tx][r];
        __half h, lo;
        split_h(wv, h, lo);
        size_t o = (size_t)off + (size_t)(nb + r) * K + kb + tx;
        bt_hi[o] = h;
        bt_lo[o] = lo;
    }
}

// x (exact one-hot fp32) -> fp16 (exact), plus bias concat (pb1 ++ sb1)
__global__ void __launch_bounds__(256)
convert_x_kernel(const float* __restrict__ x, __half* __restrict__ xh,
                 const float* __restrict__ pb1, const float* __restrict__ sb1,
                 float* __restrict__ bias_l1) {
    const int t = blockIdx.x * 256 + threadIdx.x;
    const float4 a = *reinterpret_cast<const float4*>(x + (size_t)t * 8);
    const float4 b = *reinterpret_cast<const float4*>(x + (size_t)t * 8 + 4);
    __half2 o[4];
    o[0] = __halves2half2(__float2half_rn(a.x), __float2half_rn(a.y));
    o[1] = __halves2half2(__float2half_rn(a.z), __float2half_rn(a.w));
    o[2] = __halves2half2(__float2half_rn(b.x), __float2half_rn(b.y));
    o[3] = __halves2half2(__float2half_rn(b.z), __float2half_rn(b.w));
    *reinterpret_cast<uint4*>(xh + (size_t)t * 8) =
        *reinterpret_cast<uint4*>(o);
    if (t < HP + HS)
        bias_l1[t] = (t < HP) ? pb1[t] : sb1[t - HP];
}

// ---------------------------------------------------------------------------
// Selector head: P = sigmoid(s1 @ sw2 + sb2). BM=32, BN=64 -> 256 blocks.
// 256 threads: thread tile 2x4 over a 32x64 output block, K=512.
// ---------------------------------------------------------------------------
__global__ void __launch_bounds__(256)
sel_head_kernel(const float* __restrict__ A, const float* __restrict__ B,
                const float* __restrict__ bias, float* __restrict__ C) {
    __shared__ float As[16][33];
    __shared__ float Bs[16][64];

    const int tid = threadIdx.x;
    const int tx = tid & 15;        // col group (4 cols)
    const int ty = tid >> 4;        // row pair (2 rows)
    const int bm0 = blockIdx.x * 32;
    const int K = HS, N = NN;

    float acc[2][4] = {{0.f, 0.f, 0.f, 0.f}, {0.f, 0.f, 0.f, 0.f}};

    for (int kt = 0; kt < K / 16; kt++) {
        if (tid < 128) {
            int row = tid >> 2;           // 0..31
            int c4 = (tid & 3) << 2;
            float4 v = *reinterpret_cast<const float4*>(
                A + (size_t)(bm0 + row) * K + (kt << 4) + c4);
            As[c4 + 0][row] = v.x;
            As[c4 + 1][row] = v.y;
            As[c4 + 2][row] = v.z;
            As[c4 + 3][row] = v.w;
        }
        {
            int row = tid >> 4;           // 0..15
            int col = (tid & 15) << 2;    // 0..60
            float4 v = *reinterpret_cast<const float4*>(
                B + (size_t)((kt << 4) + row) * N + col);
            *reinterpret_cast<float4*>(&Bs[row][col]) = v;
        }
        __syncthreads();

#pragma unroll
        for (int k = 0; k < 16; k++) {
            float a0 = As[k][ty * 2];
            float a1 = As[k][ty * 2 + 1];
            float4 bv = *reinterpret_cast<const float4*>(&Bs[k][tx * 4]);
            acc[0][0] = fmaf(a0, bv.x, acc[0][0]);
            acc[0][1] = fmaf(a0, bv.y, acc[0][1]);
            acc[0][2] = fmaf(a0, bv.z, acc[0][2]);
            acc[0][3] = fmaf(a0, bv.w, acc[0][3]);
            acc[1][0] = fmaf(a1, bv.x, acc[1][0]);
            acc[1][1] = fmaf(a1, bv.y, acc[1][1]);
            acc[1][2] = fmaf(a1, bv.z, acc[1][2]);
            acc[1][3] = fmaf(a1, bv.w, acc[1][3]);
        }
        __syncthreads();
    }

    float4 bvec = *reinterpret_cast<const float4*>(bias + tx * 4);
    float bias4[4] = {bvec.x, bvec.y, bvec.z, bvec.w};
#pragma unroll
    for (int i = 0; i < 2; i++) {
        float4 v;
        float* vp = &v.x;
#pragma unroll
        for (int j = 0; j < 4; j++) {
            float cv = acc[i][j] + bias4[j];
            vp[j] = 1.0f / (1.0f + expf(-cv));
        }
        *reinterpret_cast<float4*>(
            C + (size_t)(bm0 + ty * 2 + i) * N + tx * 4) = v;
    }
}

// ---------------------------------------------------------------------------
// Fused elementwise tail (verified rounds 1-7)
// ---------------------------------------------------------------------------
__device__ __forceinline__ void gs8(const float* l, const float* g, float* xt) {
    float m = l[0];
#pragma unroll
    for (int c = 1; c < 8; c++) m = fmaxf(m, l[c]);
    float e[8], s = 0.0f;
#pragma unroll
    for (int c = 0; c < 8; c++) { e[c] = expf(l[c] - m); s += e[c]; }
    float t[8];
#pragma unroll
    for (int c = 0; c < 8; c++) {
        float pr = e[c] / s;
        pr = 0.9f * pr + 0.0125f;
        t[c] = (logf(pr) + g[c]) / 0.7f;
    }
    float m2 = t[0];
#pragma unroll
    for (int c = 1; c < 8; c++) m2 = fmaxf(m2, t[c]);
    float e2[8], s2 = 0.0f;
#pragma unroll
    for (int c = 0; c < 8; c++) { e2[c] = expf(t[c] - m2); s2 += e2[c]; }
#pragma unroll
    for (int c = 0; c < 8; c++) xt[c] = e2[c] / s2;
}

__global__ void finalize_kernel(const float* __restrict__ x,
                                const float* __restrict__ Pm,
                                const float* __restrict__ W,
                                float* __restrict__ xcf) {
    const int b = blockIdx.x;
    const int n = threadIdx.x;
    __shared__ float sh_cst, sh_incr;

    const size_t base = (size_t)b * DD + n * CC;
    float4 xa = *reinterpret_cast<const float4*>(x + base);
    float4 xb = *reinterpret_cast<const float4*>(x + base + 4);
    float4 wa = *reinterpret_cast<const float4*>(W + base);
    float4 wb = *reinterpret_cast<const float4*>(W + base + 4);
    float xv[8] = {xa.x, xa.y, xa.z, xa.w, xb.x, xb.y, xb.z, xb.w};
    float Wv[8] = {wa.x, wa.y, wa.z, wa.w, wb.x, wb.y, wb.z, wb.w};

    const unsigned i = (unsigned)(b * NN + n);
    const float P = Pm[i];

    float ua = jax_u01(KA0, KA1, i);
    float ub = jax_u01(KB0, KB1, i);
    float ea = expf(-logf(-logf(ua)));
    float eb = expf(-logf(-logf(ub)));
    float no = P * ea / 0.7f;
    float de = no + (1.0f - P) * eb / 0.7f;
    float probs = no / de;

    float g[8];
#pragma unroll
    for (int c = 0; c < 8; c++) {
        float u = jax_u01(KG0, KG1, i * 8u + (unsigned)c);
        g[c] = -logf(-logf(u));
    }

    int curr = 0;
    {
        float m = xv[0];
#pragma unroll
        for (int c = 1; c < 8; c++)
            if (xv[c] > m) { m = xv[c]; curr = c; }
    }

    if (n == 2) {
        float xt_par[8];
        gs8(Wv, g, xt_par);
        int am = 0;
        float m = probs * xt_par[0] + (1.0f - probs) * xv[0];
#pragma unroll
        for (int c = 1; c < 8; c++) {
            float v = probs * xt_par[c] + (1.0f - probs) * xv[c];
            if (v > m) { m = v; am = c; }
        }
        int diff = am - curr;
        sh_cst  = (diff == 0) ? 1.0f : 0.0f;
        sh_incr = (diff >  0) ? 1.0f : 0.0f;
    }
    __syncthreads();
    const float cst = sh_cst;
    const float incr = sh_incr;

    float l[8];
    if (n == 0 || n == 5 || n == 10) {
#pragma unroll
        for (int c = 0; c < 8; c++) l[c] = Wv[c] + ((c < curr) ? -100.0f : 1.0f);
    } else if (n == 7) {
        const int thr = curr + 1;
        const bool inc = (incr > 0.5f);
#pragma unroll
        for (int c = 0; c < 8; c++)
            l[c] = Wv[c] + ((inc && c < thr) ? -100.0f : 1.0f);
    } else {
#pragma unroll
        for (int c = 0; c < 8; c++) l[c] = Wv[c];
    }

    float xt[8];
    gs8(l, g, xt);

    float p2 = probs;
    if (n == 7) {
        float pc = probs * (1.0f - cst);
        pc = pc + incr;
        p2 = fminf(fmaxf(pc, 0.0f), 1.0f);
    }

    float4 oa, ob;
    float* op = &oa.x;
#pragma unroll
    for (int c = 0; c < 4; c++) op[c] = p2 * xt[c] + (1.0f - p2) * xv[c];
    op = &ob.x;
#pragma unroll
    for (int c = 0; c < 4; c++) op[c] = p2 * xt[c + 4] + (1.0f - p2) * xv[c + 4];
    *reinterpret_cast<float4*>(xcf + base) = oa;
    *reinterpret_cast<float4*>(xcf + base + 4) = ob;
}

// ---------------------------------------------------------------------------
// Launch
// ---------------------------------------------------------------------------
extern "C" void kernel_launch(void* const* d_in, const int* in_sizes, int n_in,
                              void* d_out, int out_size) {
    const float* x     = (const float*)d_in[0];
    const float* truth = (const float*)d_in[1];
    const float* sw1   = (const float*)d_in[2];
    const float* sb1   = (const float*)d_in[3];
    const float* sw2   = (const float*)d_in[4];
    const float* sb2   = (const float*)d_in[5];
    const float* pw1   = (const float*)d_in[6];
    const float* pb1   = (const float*)d_in[7];
    const float* pw2   = (const float*)d_in[8];
    const float* pb2   = (const float*)d_in[9];
    const float* pw3   = (const float*)d_in[10];
    const float* pb3   = (const float*)d_in[11];
    const float* pw4   = (const float*)d_in[12];
    const float* pb4   = (const float*)d_in[13];

    float* out       = (float*)d_out;
    float* out_truth = out;
    float* out_xcf   = out + BD_ELEMS;
    float* out_P     = out + 2 * (size_t)BD_ELEMS;
    float* out_W     = out + 2 * (size_t)BD_ELEMS + BN_ELEMS;

    __half *a_hi, *a_lo, *b_hi, *b_lo, *xh, *wt_hi, *wt_lo;
    float *s1, *bias_l1;
    cudaGetSymbolAddress((void**)&a_hi, g_a_hi);
    cudaGetSymbolAddress((void**)&a_lo, g_a_lo);
    cudaGetSymbolAddress((void**)&b_hi, g_b_hi);
    cudaGetSymbolAddress((void**)&b_lo, g_b_lo);
    cudaGetSymbolAddress((void**)&xh,   g_xh);
    cudaGetSymbolAddress((void**)&s1,   g_s1);
    cudaGetSymbolAddress((void**)&wt_hi, g_wt_hi);
    cudaGetSymbolAddress((void**)&wt_lo, g_wt_lo);
    cudaGetSymbolAddress((void**)&bias_l1, g_bias_l1);

    cudaFuncSetAttribute(gemm_h<true, 2>,
                         cudaFuncAttributeMaxDynamicSharedMemorySize, GEMM_SMEM);
    cudaFuncSetAttribute(gemm_h<false, 0>,
                         cudaFuncAttributeMaxDynamicSharedMemorySize, GEMM_SMEM);
    cudaFuncSetAttribute(gemm_h<false, 1>,
                         cudaFuncAttributeMaxDynamicSharedMemorySize, GEMM_SMEM);

    // Conversions: x -> fp16 (+ L1 bias concat), all weight splits in one go
    convert_x_kernel<<<(BB * DD / 8) / 256, 256>>>(x, xh, pb1, sb1, bias_l1);
    split_all_kernel<<<3328, 256>>>(pw1, sw1, pw2, pw3, pw4, wt_hi, wt_lo);

    // L1 (pw1 + sw1 merged, AEX, mixed epilogue)
    gemm_h<true, 2><<<dim3((HP + HS) / 128, BB / 128), 256, GEMM_SMEM>>>(
        xh, nullptr, wt_hi, wt_lo, bias_l1, a_hi, a_lo, s1, DD, HP);
    // Selector head (BM=32 -> 256 blocks, parallelism-fixed)
    sel_head_kernel<<<BB / 32, 256>>>(s1, sw2, sb2, out_P);
    // MLP layers 2-4
    gemm_h<false, 0><<<dim3(HP / 128, BB / 128), 256, GEMM_SMEM>>>(
        a_hi, a_lo, wt_hi + OF_PW2, wt_lo + OF_PW2, pb2, b_hi, b_lo, nullptr,
        HP, HP);
    gemm_h<false, 0><<<dim3(HP / 128, BB / 128), 256, GEMM_SMEM>>>(
        b_hi, b_lo, wt_hi + OF_PW3, wt_lo + OF_PW3, pb3, a_hi, a_lo, nullptr,
        HP, HP);
    gemm_h<false, 1><<<dim3(DD / 128, BB / 128), 256, GEMM_SMEM>>>(
        a_hi, a_lo, wt_hi + OF_PW4, wt_lo + OF_PW4, pb4, nullptr, nullptr,
        out_W, HP, DD);

    // truth_x passthrough
    cudaMemcpyAsync(out_truth, truth, (size_t)BD_ELEMS * sizeof(float),
                    cudaMemcpyDeviceToDevice);
    // Fused tail
    finalize_kernel<<<BB, NN>>>(x, out_P, out_W, out_xcf);
}

// round 9
// speedup vs baseline: 2.5450x; 1.0202x over previous
#include <cuda_runtime.h>
#include <cuda_fp16.h>
#include <cstdint>
#include <math.h>

// ---------------------------------------------------------------------------
// Problem constants
// ---------------------------------------------------------------------------
#define BB 8192
#define NN 64
#define CC 8
#define DD (NN * CC)        // 512
#define HP 1024
#define HS 512
#define BD_ELEMS (BB * DD)  // 4,194,304
#define BN_ELEMS (BB * NN)  // 524,288

// ---------------------------------------------------------------------------
// Scratch (allocation-free: __device__ globals)
// ---------------------------------------------------------------------------
__device__ __half g_a_hi[BB * HP];
__device__ __half g_a_lo[BB * HP];
__device__ __half g_b_hi[BB * HP];
__device__ __half g_b_lo[BB * HP];
__device__ __half g_xh[BB * DD];
__device__ float  g_s1[BB * HS];
__device__ float  g_bias_l1[HP + HS];   // pb1 ++ sb1

// Transposed + split weights, packed (Bt[n][k] layout), fp16 hi/lo.
#define OF_PW1 0
#define OF_SW1 524288
#define OF_PW2 786432
#define OF_PW3 1835008
#define OF_PW4 2883584
#define WT_TOTAL 3407872
__device__ __half g_wt_hi[WT_TOTAL];
__device__ __half g_wt_lo[WT_TOTAL];

// ---------------------------------------------------------------------------
// Threefry-2x32-20 (JAX)
// ---------------------------------------------------------------------------
struct TFK { unsigned a, b; };

__host__ __device__ constexpr unsigned tf_rotl(unsigned v, int r) {
    return (v << r) | (v >> (32 - r));
}

__host__ __device__ constexpr TFK tf2x32(unsigned k0, unsigned k1,
                                         unsigned x0, unsigned x1) {
    unsigned k2 = k0 ^ k1 ^ 0x1BD11BDAu;
    x0 += k0; x1 += k1;
    x0 += x1; x1 = tf_rotl(x1, 13); x1 ^= x0;
    x0 += x1; x1 = tf_rotl(x1, 15); x1 ^= x0;
    x0 += x1; x1 = tf_rotl(x1, 26); x1 ^= x0;
    x0 += x1; x1 = tf_rotl(x1,  6); x1 ^= x0;
    x0 += k1; x1 += k2 + 1u;
    x0 += x1; x1 = tf_rotl(x1, 17); x1 ^= x0;
    x0 += x1; x1 = tf_rotl(x1, 29); x1 ^= x0;
    x0 += x1; x1 = tf_rotl(x1, 16); x1 ^= x0;
    x0 += x1; x1 = tf_rotl(x1, 24); x1 ^= x0;
    x0 += k2; x1 += k0 + 2u;
    x0 += x1; x1 = tf_rotl(x1, 13); x1 ^= x0;
    x0 += x1; x1 = tf_rotl(x1, 15); x1 ^= x0;
    x0 += x1; x1 = tf_rotl(x1, 26); x1 ^= x0;
    x0 += x1; x1 = tf_rotl(x1,  6); x1 ^= x0;
    x0 += k0; x1 += k1 + 3u;
    x0 += x1; x1 = tf_rotl(x1, 17); x1 ^= x0;
    x0 += x1; x1 = tf_rotl(x1, 29); x1 ^= x0;
    x0 += x1; x1 = tf_rotl(x1, 16); x1 ^= x0;
    x0 += x1; x1 = tf_rotl(x1, 24); x1 ^= x0;
    x0 += k1; x1 += k2 + 4u;
    x0 += x1; x1 = tf_rotl(x1, 13); x1 ^= x0;
    x0 += x1; x1 = tf_rotl(x1, 15); x1 ^= x0;
    x0 += x1; x1 = tf_rotl(x1, 26); x1 ^= x0;
    x0 += x1; x1 = tf_rotl(x1,  6); x1 ^= x0;
    x0 += k2; x1 += k0 + 5u;
    return TFK{x0, x1};
}

constexpr unsigned KA0 = tf2x32(0u, 42u, 0u, 0u).a;
constexpr unsigned KA1 = tf2x32(0u, 42u, 0u, 0u).b;
constexpr unsigned KB0 = tf2x32(0u, 42u, 0u, 1u).a;
constexpr unsigned KB1 = tf2x32(0u, 42u, 0u, 1u).b;
constexpr unsigned KG0 = tf2x32(0u, 42u, 0u, 2u).a;
constexpr unsigned KG1 = tf2x32(0u, 42u, 0u, 2u).b;

__device__ __forceinline__ float jax_u01(unsigned k0, unsigned k1, unsigned idx) {
    TFK r = tf2x32(k0, k1, 0u, idx);
    unsigned bits = r.a ^ r.b;
    float f = __uint_as_float((bits >> 9) | 0x3f800000u) - 1.0f;
    f = f + 1e-8f;
    return fmaxf(1e-8f, f);
}

// ---------------------------------------------------------------------------
// Helpers
// ---------------------------------------------------------------------------
__device__ __forceinline__ uint32_t smem_u32(const void* p) {
    uint32_t a;
    asm("{ .reg .u64 t; cvta.to.shared.u64 t, %1; cvt.u32.u64 %0, t; }"
        : "=r"(a) : "l"(p));
    return a;
}

#define CP16(dst_u32, src_ptr) \
    asm volatile("cp.async.cg.shared.global [%0], [%1], 16;" \
                 :: "r"(dst_u32), "l"(src_ptr) : "memory")
#define CP_COMMIT() asm volatile("cp.async.commit_group;" ::: "memory")
#define CP_WAIT(n)  asm volatile("cp.async.wait_group %0;" :: "n"(n) : "memory")

__device__ __forceinline__ void mma16(float* d, const uint32_t* a,
                                      const uint32_t* b) {
    asm volatile(
        "mma.sync.aligned.m16n8k16.row.col.f32.f16.f16.f32 "
        "{%0,%1,%2,%3}, {%4,%5,%6,%7}, {%8,%9}, {%0,%1,%2,%3};"
        : "+f"(d[0]), "+f"(d[1]), "+f"(d[2]), "+f"(d[3])
        : "r"(a[0]), "r"(a[1]), "r"(a[2]), "r"(a[3]), "r"(b[0]), "r"(b[1]));
}

__device__ __forceinline__ void ldsm_x4(uint32_t* r, uint32_t addr) {
    asm volatile(
        "ldmatrix.sync.aligned.m8n8.x4.shared.b16 {%0,%1,%2,%3}, [%4];"
        : "=r"(r[0]), "=r"(r[1]), "=r"(r[2]), "=r"(r[3]) : "r"(addr));
}

__device__ __forceinline__ void split_h(float y, __half& h, __half& l) {
    h = __float2half_rn(y);
    l = __float2half_rn(y - __half2float(h));
}

// ---------------------------------------------------------------------------
// fp16-split GEMM. BM=128, BN=128, BK=32, 256 threads, warps 2x4 (tile 64x32).
// OMODE: 0 = relu + split; 1 = plain fp32; 2 = MIXED L1 (see round 7)
// ---------------------------------------------------------------------------
#define PH 40
#define T_AH 0
#define T_AL (128 * PH)
#define T_BH (2 * 128 * PH)
#define T_BL (3 * 128 * PH)
#define STAGE_H (4 * 128 * PH)
#define GEMM_SMEM (2 * STAGE_H * 2)     // 81920 bytes

template <bool AEX>
__device__ __forceinline__ void issue_chunk_h(
    uint32_t smb, int s, int c,
    const __half* __restrict__ A_hi, const __half* __restrict__ A_lo,
    const __half* __restrict__ B_hi, const __half* __restrict__ B_lo,
    int K, int bm0, int bn0, int tid) {
    const int k0 = c * 32;
    const uint32_t sb = smb + (uint32_t)(s * STAGE_H) * 2u;
#pragma unroll
    for (int i = 0; i < 2; i++) {
        const int f = tid + i * 256;
        const int row = f >> 2;
        const int q = f & 3;
        const uint32_t doff = (uint32_t)(row * PH + q * 8) * 2u;
        CP16(sb + T_AH * 2 + doff, A_hi + (size_t)(bm0 + row) * K + k0 + q * 8);
        if (!AEX)
            CP16(sb + T_AL * 2 + doff,
                 A_lo + (size_t)(bm0 + row) * K + k0 + q * 8);
        CP16(sb + T_BH * 2 + doff, B_hi + (size_t)(bn0 + row) * K + k0 + q * 8);
        CP16(sb + T_BL * 2 + doff, B_lo + (size_t)(bn0 + row) * K + k0 + q * 8);
    }
    CP_COMMIT();
}

template <bool AEX, int OMODE>
__global__ void __launch_bounds__(256, 2)
gemm_h(const __half* __restrict__ A_hi, const __half* __restrict__ A_lo,
       const __half* __restrict__ Bt_hi, const __half* __restrict__ Bt_lo,
       const float* __restrict__ bias,
       __half* __restrict__ O_hi, __half* __restrict__ O_lo,
       float* __restrict__ Of,
       int K, int Nout) {
    extern __shared__ __half smh[];
    const uint32_t smb = smem_u32(smh);
    const int tid = threadIdx.x;
    const int l = tid & 31;
    const int warp = tid >> 5;
    const int wm = warp >> 2;
    const int wn = warp & 3;
    const int bm0 = blockIdx.y * 128;
    const int bn0 = blockIdx.x * 128;
    const int NC = K >> 5;

    float acc[4][4][4];
#pragma unroll
    for (int mf = 0; mf < 4; mf++)
#pragma unroll
        for (int nf = 0; nf < 4; nf++)
#pragma unroll
            for (int r = 0; r < 4; r++) acc[mf][nf][r] = 0.0f;

    issue_chunk_h<AEX>(smb, 0, 0, A_hi, A_lo, Bt_hi, Bt_lo, K, bm0, bn0, tid);

    const uint32_t aoff = (uint32_t)(((l & 15) * PH + (l >> 4) * 8) * 2);
    const uint32_t boff = (uint32_t)(((((l >> 4) & 1) * 8 + (l & 7)) * PH +
                                      ((l >> 3) & 1) * 8) * 2);

    for (int c = 0; c < NC; c++) {
        const int s = c & 1;
        if (c + 1 < NC) {
            issue_chunk_h<AEX>(smb, (c + 1) & 1, c + 1, A_hi, A_lo, Bt_hi,
                               Bt_lo, K, bm0, bn0, tid);
            CP_WAIT(1);
        } else {
            CP_WAIT(0);
        }
        __syncthreads();

        const uint32_t stage = smb + (uint32_t)(s * STAGE_H) * 2u;
        const uint32_t baseAh = stage + (uint32_t)((T_AH + wm * 64 * PH) * 2) + aoff;
        const uint32_t baseAl = stage + (uint32_t)((T_AL + wm * 64 * PH) * 2) + aoff;
        const uint32_t baseBh = stage + (uint32_t)((T_BH + wn * 32 * PH) * 2) + boff;
        const uint32_t baseBl = stage + (uint32_t)((T_BL + wn * 32 * PH) * 2) + boff;

#pragma unroll
        for (int ks = 0; ks < 2; ks++) {
            const uint32_t koff = (uint32_t)(ks * 16 * 2);
            uint32_t bh[4][2], bl[4][2];
#pragma unroll
            for (int j = 0; j < 2; j++) {
                uint32_t t[4];
                ldsm_x4(t, baseBh + (uint32_t)(j * 16 * PH * 2) + koff);
                bh[2 * j][0] = t[0]; bh[2 * j][1] = t[1];
                bh[2 * j + 1][0] = t[2]; bh[2 * j + 1][1] = t[3];
                ldsm_x4(t, baseBl + (uint32_t)(j * 16 * PH * 2) + koff);
                bl[2 * j][0] = t[0]; bl[2 * j][1] = t[1];
                bl[2 * j + 1][0] = t[2]; bl[2 * j + 1][1] = t[3];
            }
#pragma unroll
            for (int mf = 0; mf < 4; mf++) {
                uint32_t ah[4], al[4];
                ldsm_x4(ah, baseAh + (uint32_t)(mf * 16 * PH * 2) + koff);
                if (!AEX)
                    ldsm_x4(al, baseAl + (uint32_t)(mf * 16 * PH * 2) + koff);
#pragma unroll
                for (int nf = 0; nf < 4; nf++) {
                    mma16(acc[mf][nf], ah, bh[nf]);
                    mma16(acc[mf][nf], ah, bl[nf]);
                    if (!AEX) mma16(acc[mf][nf], al, bh[nf]);
                }
            }
        }
        __syncthreads();
    }

    // ---- Epilogue ----
    const int rA = l >> 2;
    const int cK = l & 3;
    const bool f32_region = (OMODE == 1) || (OMODE == 2 && bn0 >= HP);
    const int ow = (OMODE == 2) ? (f32_region ? HS : HP) : Nout;
    const int cbase = (OMODE == 2 && f32_region) ? (bn0 - HP) : bn0;

#pragma unroll
    for (int nf = 0; nf < 4; nf++) {
        const int gcol = bn0 + wn * 32 + nf * 8 + 2 * cK;
        const int col = cbase + wn * 32 + nf * 8 + 2 * cK;
        const float2 bv = *reinterpret_cast<const float2*>(bias + gcol);
#pragma unroll
        for (int mf = 0; mf < 4; mf++) {
            const int ra = bm0 + wm * 64 + mf * 16 + rA;
            float y[4];
            y[0] = acc[mf][nf][0] + bv.x;
            y[1] = acc[mf][nf][1] + bv.y;
            y[2] = acc[mf][nf][2] + bv.x;
            y[3] = acc[mf][nf][3] + bv.y;
            if (OMODE != 1) {
#pragma unroll
                for (int r = 0; r < 4; r++) y[r] = fmaxf(y[r], 0.0f);
            }
            if (!f32_region && OMODE != 1) {
                __half h[4], lo[4];
#pragma unroll
                for (int r = 0; r < 4; r++) split_h(y[r], h[r], lo[r]);
                *reinterpret_cast<__half2*>(O_hi + (size_t)ra * ow + col) =
                    __halves2half2(h[0], h[1]);
                *reinterpret_cast<__half2*>(O_hi + (size_t)(ra + 8) * ow + col) =
                    __halves2half2(h[2], h[3]);
                *reinterpret_cast<__half2*>(O_lo + (size_t)ra * ow + col) =
                    __halves2half2(lo[0], lo[1]);
                *reinterpret_cast<__half2*>(O_lo + (size_t)(ra + 8) * ow + col) =
                    __halves2half2(lo[2], lo[3]);
            } else {
                *reinterpret_cast<float2*>(Of + (size_t)ra * ow + col) =
                    make_float2(y[0], y[1]);
                *reinterpret_cast<float2*>(Of + (size_t)(ra + 8) * ow + col) =
                    make_float2(y[2], y[3]);
            }
        }
    }
}

// ---------------------------------------------------------------------------
// ONE merged weight transpose+split kernel for all 5 weights.
// ---------------------------------------------------------------------------
__global__ void __launch_bounds__(256)
split_all_kernel(const float* __restrict__ pw1, const float* __restrict__ sw1,
                 const float* __restrict__ pw2, const float* __restrict__ pw3,
                 const float* __restrict__ pw4,
                 __half* __restrict__ bt_hi, __half* __restrict__ bt_lo) {
    const int b = blockIdx.x;
    const float* W;
    int off, K, N, lb;
    if (b < 512)        { W = pw1; off = OF_PW1; K = 512;  N = 1024; lb = b; }
    else if (b < 768)   { W = sw1; off = OF_SW1; K = 512;  N = 512;  lb = b - 512; }
    else if (b < 1792)  { W = pw2; off = OF_PW2; K = 1024; N = 1024; lb = b - 768; }
    else if (b < 2816)  { W = pw3; off = OF_PW3; K = 1024; N = 1024; lb = b - 1792; }
    else                { W = pw4; off = OF_PW4; K = 1024; N = 512;  lb = b - 2816; }
    const int kt = K >> 5;
    const int kb = (lb % kt) * 32;
    const int nb = (lb / kt) * 32;

    __shared__ float t[32][33];
    const int tx = threadIdx.x & 31;
    const int ty = threadIdx.x >> 5;
#pragma unroll
    for (int r = ty; r < 32; r += 8)
        t[r][tx] = W[(size_t)(kb + r) * N + nb + tx];
    __syncthreads();
#pragma unroll
    for (int r = ty; r < 32; r += 8) {
        float wv = t[tx][r];
        __half h, lo;
        split_h(wv, h, lo);
        size_t o = (size_t)off + (size_t)(nb + r) * K + kb + tx;
        bt_hi[o] = h;
        bt_lo[o] = lo;
    }
}

// x (exact one-hot fp32) -> fp16 (exact), plus bias concat (pb1 ++ sb1)
__global__ void __launch_bounds__(256)
convert_x_kernel(const float* __restrict__ x, __half* __restrict__ xh,
                 const float* __restrict__ pb1, const float* __restrict__ sb1,
                 float* __restrict__ bias_l1) {
    const int t = blockIdx.x * 256 + threadIdx.x;
    const float4 a = *reinterpret_cast<const float4*>(x + (size_t)t * 8);
    const float4 b = *reinterpret_cast<const float4*>(x + (size_t)t * 8 + 4);
    __half2 o[4];
    o[0] = __halves2half2(__float2half_rn(a.x), __float2half_rn(a.y));
    o[1] = __halves2half2(__float2half_rn(a.z), __float2half_rn(a.w));
    o[2] = __halves2half2(__float2half_rn(b.x), __float2half_rn(b.y));
    o[3] = __halves2half2(__float2half_rn(b.z), __float2half_rn(b.w));
    *reinterpret_cast<uint4*>(xh + (size_t)t * 8) =
        *reinterpret_cast<uint4*>(o);
    if (t < HP + HS)
        bias_l1[t] = (t < HP) ? pb1[t] : sb1[t - HP];
}

// ---------------------------------------------------------------------------
// Selector head: P = sigmoid(s1 @ sw2 + sb2). BM=32, BN=64 -> 256 blocks.
// 3-stage cp.async pipeline (prefetch distance 2) to hide global latency.
// Same FMA order as round 8 -> bitwise-identical result.
// ---------------------------------------------------------------------------
__global__ void __launch_bounds__(256)
sel_head_kernel(const float* __restrict__ A, const float* __restrict__ B,
                const float* __restrict__ bias, float* __restrict__ C) {
    __shared__ float As[3][32][20];   // [stage][row][k] (pad 20)
    __shared__ float Bs[3][16][64];   // [stage][k][n]

    const int tid = threadIdx.x;
    const int tx = tid & 15;        // col group (4 cols)
    const int ty = tid >> 4;        // row pair (2 rows)
    const int bm0 = blockIdx.x * 32;
    const int K = HS, N = NN;
    const int NC = K / 16;          // 32 chunks

    const uint32_t asb = smem_u32(As);
    const uint32_t bsb = smem_u32(Bs);

    // issue chunk c into stage c%3
    auto issue = [&](int c) {
        const int s = c % 3;
        const int k0 = c * 16;
        if (tid < 128) {
            const int row = tid >> 2;       // 0..31
            const int q = tid & 3;          // 0..3 (4 k's each)
            CP16(asb + (uint32_t)(((s * 32 + row) * 20 + q * 4) * 4),
                 A + (size_t)(bm0 + row) * K + k0 + q * 4);
        }
        {
            const int kr = tid >> 4;        // 0..15
            const int q = tid & 15;         // 0..15 (4 n's each)
            CP16(bsb + (uint32_t)(((s * 16 + kr) * 64 + q * 4) * 4),
                 B + (size_t)(k0 + kr) * N + q * 4);
        }
        CP_COMMIT();
    };

    float acc[2][4] = {{0.f, 0.f, 0.f, 0.f}, {0.f, 0.f, 0.f, 0.f}};

    issue(0);
    issue(1);
    issue(2);

    for (int c = 0; c < NC; c++) {
        const int s = c % 3;
        CP_WAIT(2);                 // chunk c complete (<=2 groups pending)
        __syncthreads();

#pragma unroll
        for (int k = 0; k < 16; k++) {
            float a0 = As[s][ty * 2][k];
            float a1 = As[s][ty * 2 + 1][k];
            float4 bv = *reinterpret_cast<const float4*>(&Bs[s][k][tx * 4]);
            acc[0][0] = fmaf(a0, bv.x, acc[0][0]);
            acc[0][1] = fmaf(a0, bv.y, acc[0][1]);
            acc[0][2] = fmaf(a0, bv.z, acc[0][2]);
            acc[0][3] = fmaf(a0, bv.w, acc[0][3]);
            acc[1][0] = fmaf(a1, bv.x, acc[1][0]);
            acc[1][1] = fmaf(a1, bv.y, acc[1][1]);
            acc[1][2] = fmaf(a1, bv.z, acc[1][2]);
            acc[1][3] = fmaf(a1, bv.w, acc[1][3]);
        }
        __syncthreads();
        if (c + 3 < NC) issue(c + 3);
    }

    float4 bvec = *reinterpret_cast<const float4*>(bias + tx * 4);
    float bias4[4] = {bvec.x, bvec.y, bvec.z, bvec.w};
#pragma unroll
    for (int i = 0; i < 2; i++) {
        float4 v;
        float* vp = &v.x;
#pragma unroll
        for (int j = 0; j < 4; j++) {
            float cv = acc[i][j] + bias4[j];
            vp[j] = 1.0f / (1.0f + expf(-cv));
        }
        *reinterpret_cast<float4*>(
            C + (size_t)(bm0 + ty * 2 + i) * N + tx * 4) = v;
    }
}

// ---------------------------------------------------------------------------
// Fused elementwise tail (verified rounds 1-8)
// ---------------------------------------------------------------------------
__device__ __forceinline__ void gs8(const float* l, const float* g, float* xt) {
    float m = l[0];
#pragma unroll
    for (int c = 1; c < 8; c++) m = fmaxf(m, l[c]);
    float e[8], s = 0.0f;
#pragma unroll
    for (int c = 0; c < 8; c++) { e[c] = expf(l[c] - m); s += e[c]; }
    float t[8];
#pragma unroll
    for (int c = 0; c < 8; c++) {
        float pr = e[c] / s;
        pr = 0.9f * pr + 0.0125f;
        t[c] = (logf(pr) + g[c]) / 0.7f;
    }
    float m2 = t[0];
#pragma unroll
    for (int c = 1; c < 8; c++) m2 = fmaxf(m2, t[c]);
    float e2[8], s2 = 0.0f;
#pragma unroll
    for (int c = 0; c < 8; c++) { e2[c] = expf(t[c] - m2); s2 += e2[c]; }
#pragma unroll
    for (int c = 0; c < 8; c++) xt[c] = e2[c] / s2;
}

__global__ void finalize_kernel(const float* __restrict__ x,
                                const float* __restrict__ Pm,
                                const float* __restrict__ W,
                                float* __restrict__ xcf) {
    const int b = blockIdx.x;
    const int n = threadIdx.x;
    __shared__ float sh_cst, sh_incr;

    const size_t base = (size_t)b * DD + n * CC;
    float4 xa = *reinterpret_cast<const float4*>(x + base);
    float4 xb = *reinterpret_cast<const float4*>(x + base + 4);
    float4 wa = *reinterpret_cast<const float4*>(W + base);
    float4 wb = *reinterpret_cast<const float4*>(W + base + 4);
    float xv[8] = {xa.x, xa.y, xa.z, xa.w, xb.x, xb.y, xb.z, xb.w};
    float Wv[8] = {wa.x, wa.y, wa.z, wa.w, wb.x, wb.y, wb.z, wb.w};

    const unsigned i = (unsigned)(b * NN + n);
    const float P = Pm[i];

    float ua = jax_u01(KA0, KA1, i);
    float ub = jax_u01(KB0, KB1, i);
    float ea = expf(-logf(-logf(ua)));
    float eb = expf(-logf(-logf(ub)));
    float no = P * ea / 0.7f;
    float de = no + (1.0f - P) * eb / 0.7f;
    float probs = no / de;

    float g[8];
#pragma unroll
    for (int c = 0; c < 8; c++) {
        float u = jax_u01(KG0, KG1, i * 8u + (unsigned)c);
        g[c] = -logf(-logf(u));
    }

    int curr = 0;
    {
        float m = xv[0];
#pragma unroll
        for (int c = 1; c < 8; c++)
            if (xv[c] > m) { m = xv[c]; curr = c; }
    }

    if (n == 2) {
        float xt_par[8];
        gs8(Wv, g, xt_par);
        int am = 0;
        float m = probs * xt_par[0] + (1.0f - probs) * xv[0];
#pragma unroll
        for (int c = 1; c < 8; c++) {
            float v = probs * xt_par[c] + (1.0f - probs) * xv[c];
            if (v > m) { m = v; am = c; }
        }
        int diff = am - curr;
        sh_cst  = (diff == 0) ? 1.0f : 0.0f;
        sh_incr = (diff >  0) ? 1.0f : 0.0f;
    }
    __syncthreads();
    const float cst = sh_cst;
    const float incr = sh_incr;

    float l[8];
    if (n == 0 || n == 5 || n == 10) {
#pragma unroll
        for (int c = 0; c < 8; c++) l[c] = Wv[c] + ((c < curr) ? -100.0f : 1.0f);
    } else if (n == 7) {
        const int thr = curr + 1;
        const bool inc = (incr > 0.5f);
#pragma unroll
        for (int c = 0; c < 8; c++)
            l[c] = Wv[c] + ((inc && c < thr) ? -100.0f : 1.0f);
    } else {
#pragma unroll
        for (int c = 0; c < 8; c++) l[c] = Wv[c];
    }

    float xt[8];
    gs8(l, g, xt);

    float p2 = probs;
    if (n == 7) {
        float pc = probs * (1.0f - cst);
        pc = pc + incr;
        p2 = fminf(fmaxf(pc, 0.0f), 1.0f);
    }

    float4 oa, ob;
    float* op = &oa.x;
#pragma unroll
    for (int c = 0; c < 4; c++) op[c] = p2 * xt[c] + (1.0f - p2) * xv[c];
    op = &ob.x;
#pragma unroll
    for (int c = 0; c < 4; c++) op[c] = p2 * xt[c + 4] + (1.0f - p2) * xv[c + 4];
    *reinterpret_cast<float4*>(xcf + base) = oa;
    *reinterpret_cast<float4*>(xcf + base + 4) = ob;
}

// ---------------------------------------------------------------------------
// Launch
// ---------------------------------------------------------------------------
extern "C" void kernel_launch(void* const* d_in, const int* in_sizes, int n_in,
                              void* d_out, int out_size) {
    const float* x     = (const float*)d_in[0];
    const float* truth = (const float*)d_in[1];
    const float* sw1   = (const float*)d_in[2];
    const float* sb1   = (const float*)d_in[3];
    const float* sw2   = (const float*)d_in[4];
    const float* sb2   = (const float*)d_in[5];
    const float* pw1   = (const float*)d_in[6];
    const float* pb1   = (const float*)d_in[7];
    const float* pw2   = (const float*)d_in[8];
    const float* pb2   = (const float*)d_in[9];
    const float* pw3   = (const float*)d_in[10];
    const float* pb3   = (const float*)d_in[11];
    const float* pw4   = (const float*)d_in[12];
    const float* pb4   = (const float*)d_in[13];

    float* out       = (float*)d_out;
    float* out_truth = out;
    float* out_xcf   = out + BD_ELEMS;
    float* out_P     = out + 2 * (size_t)BD_ELEMS;
    float* out_W     = out + 2 * (size_t)BD_ELEMS + BN_ELEMS;

    __half *a_hi, *a_lo, *b_hi, *b_lo, *xh, *wt_hi, *wt_lo;
    float *s1, *bias_l1;
    cudaGetSymbolAddress((void**)&a_hi, g_a_hi);
    cudaGetSymbolAddress((void**)&a_lo, g_a_lo);
    cudaGetSymbolAddress((void**)&b_hi, g_b_hi);
    cudaGetSymbolAddress((void**)&b_lo, g_b_lo);
    cudaGetSymbolAddress((void**)&xh,   g_xh);
    cudaGetSymbolAddress((void**)&s1,   g_s1);
    cudaGetSymbolAddress((void**)&wt_hi, g_wt_hi);
    cudaGetSymbolAddress((void**)&wt_lo, g_wt_lo);
    cudaGetSymbolAddress((void**)&bias_l1, g_bias_l1);

    cudaFuncSetAttribute(gemm_h<true, 2>,
                         cudaFuncAttributeMaxDynamicSharedMemorySize, GEMM_SMEM);
    cudaFuncSetAttribute(gemm_h<false, 0>,
                         cudaFuncAttributeMaxDynamicSharedMemorySize, GEMM_SMEM);
    cudaFuncSetAttribute(gemm_h<false, 1>,
                         cudaFuncAttributeMaxDynamicSharedMemorySize, GEMM_SMEM);

    // Conversions: x -> fp16 (+ L1 bias concat), all weight splits in one go
    convert_x_kernel<<<(BB * DD / 8) / 256, 256>>>(x, xh, pb1, sb1, bias_l1);
    split_all_kernel<<<3328, 256>>>(pw1, sw1, pw2, pw3, pw4, wt_hi, wt_lo);

    // L1 (pw1 + sw1 merged, AEX, mixed epilogue)
    gemm_h<true, 2><<<dim3((HP + HS) / 128, BB / 128), 256, GEMM_SMEM>>>(
        xh, nullptr, wt_hi, wt_lo, bias_l1, a_hi, a_lo, s1, DD, HP);
    // Selector head (3-stage cp.async pipeline)
    sel_head_kernel<<<BB / 32, 256>>>(s1, sw2, sb2, out_P);
    // MLP layers 2-4
    gemm_h<false, 0><<<dim3(HP / 128, BB / 128), 256, GEMM_SMEM>>>(
        a_hi, a_lo, wt_hi + OF_PW2, wt_lo + OF_PW2, pb2, b_hi, b_lo, nullptr,
        HP, HP);
    gemm_h<false, 0><<<dim3(HP / 128, BB / 128), 256, GEMM_SMEM>>>(
        b_hi, b_lo, wt_hi + OF_PW3, wt_lo + OF_PW3, pb3, a_hi, a_lo, nullptr,
        HP, HP);
    gemm_h<false, 1><<<dim3(DD / 128, BB / 128), 256, GEMM_SMEM>>>(
        a_hi, a_lo, wt_hi + OF_PW4, wt_lo + OF_PW4, pb4, nullptr, nullptr,
        out_W, HP, DD);

    // truth_x passthrough
    cudaMemcpyAsync(out_truth, truth, (size_t)BD_ELEMS * sizeof(float),
                    cudaMemcpyDeviceToDevice);
    // Fused tail
    finalize_kernel<<<BB, NN>>>(x, out_P, out_W, out_xcf);
}

// round 10
// speedup vs baseline: 2.6706x; 1.0494x over previous
#include <cuda_runtime.h>
#include <cuda_fp16.h>
#include <cstdint>
#include <math.h>

// ---------------------------------------------------------------------------
// Problem constants
// ---------------------------------------------------------------------------
#define BB 8192
#define NN 64
#define CC 8
#define DD (NN * CC)        // 512
#define HP 1024
#define HS 512
#define BD_ELEMS (BB * DD)  // 4,194,304
#define BN_ELEMS (BB * NN)  // 524,288

// ---------------------------------------------------------------------------
// Scratch (allocation-free: __device__ globals)
// ---------------------------------------------------------------------------
__device__ __half g_a_hi[BB * HP];
__device__ __half g_a_lo[BB * HP];
__device__ __half g_b_hi[BB * HP];
__device__ __half g_b_lo[BB * HP];
__device__ __half g_xh[BB * DD];
__device__ float  g_s1[BB * HS];
__device__ float  g_bias_l1[HP + HS];   // pb1 ++ sb1

// Transposed + split weights, packed (Bt[n][k] layout), fp16 hi/lo.
#define OF_PW1 0
#define OF_SW1 524288
#define OF_PW2 786432
#define OF_PW3 1835008
#define OF_PW4 2883584
#define WT_TOTAL 3407872
__device__ __half g_wt_hi[WT_TOTAL];
__device__ __half g_wt_lo[WT_TOTAL];

// ---------------------------------------------------------------------------
// Threefry-2x32-20 (JAX)
// ---------------------------------------------------------------------------
struct TFK { unsigned a, b; };

__host__ __device__ constexpr unsigned tf_rotl(unsigned v, int r) {
    return (v << r) | (v >> (32 - r));
}

__host__ __device__ constexpr TFK tf2x32(unsigned k0, unsigned k1,
                                         unsigned x0, unsigned x1) {
    unsigned k2 = k0 ^ k1 ^ 0x1BD11BDAu;
    x0 += k0; x1 += k1;
    x0 += x1; x1 = tf_rotl(x1, 13); x1 ^= x0;
    x0 += x1; x1 = tf_rotl(x1, 15); x1 ^= x0;
    x0 += x1; x1 = tf_rotl(x1, 26); x1 ^= x0;
    x0 += x1; x1 = tf_rotl(x1,  6); x1 ^= x0;
    x0 += k1; x1 += k2 + 1u;
    x0 += x1; x1 = tf_rotl(x1, 17); x1 ^= x0;
    x0 += x1; x1 = tf_rotl(x1, 29); x1 ^= x0;
    x0 += x1; x1 = tf_rotl(x1, 16); x1 ^= x0;
    x0 += x1; x1 = tf_rotl(x1, 24); x1 ^= x0;
    x0 += k2; x1 += k0 + 2u;
    x0 += x1; x1 = tf_rotl(x1, 13); x1 ^= x0;
    x0 += x1; x1 = tf_rotl(x1, 15); x1 ^= x0;
    x0 += x1; x1 = tf_rotl(x1, 26); x1 ^= x0;
    x0 += x1; x1 = tf_rotl(x1,  6); x1 ^= x0;
    x0 += k0; x1 += k1 + 3u;
    x0 += x1; x1 = tf_rotl(x1, 17); x1 ^= x0;
    x0 += x1; x1 = tf_rotl(x1, 29); x1 ^= x0;
    x0 += x1; x1 = tf_rotl(x1, 16); x1 ^= x0;
    x0 += x1; x1 = tf_rotl(x1, 24); x1 ^= x0;
    x0 += k1; x1 += k2 + 4u;
    x0 += x1; x1 = tf_rotl(x1, 13); x1 ^= x0;
    x0 += x1; x1 = tf_rotl(x1, 15); x1 ^= x0;
    x0 += x1; x1 = tf_rotl(x1, 26); x1 ^= x0;
    x0 += x1; x1 = tf_rotl(x1,  6); x1 ^= x0;
    x0 += k2; x1 += k0 + 5u;
    return TFK{x0, x1};
}

constexpr unsigned KA0 = tf2x32(0u, 42u, 0u, 0u).a;
constexpr unsigned KA1 = tf2x32(0u, 42u, 0u, 0u).b;
constexpr unsigned KB0 = tf2x32(0u, 42u, 0u, 1u).a;
constexpr unsigned KB1 = tf2x32(0u, 42u, 0u, 1u).b;
constexpr unsigned KG0 = tf2x32(0u, 42u, 0u, 2u).a;
constexpr unsigned KG1 = tf2x32(0u, 42u, 0u, 2u).b;

__device__ __forceinline__ float jax_u01(unsigned k0, unsigned k1, unsigned idx) {
    TFK r = tf2x32(k0, k1, 0u, idx);
    unsigned bits = r.a ^ r.b;
    float f = __uint_as_float((bits >> 9) | 0x3f800000u) - 1.0f;
    f = f + 1e-8f;
    return fmaxf(1e-8f, f);
}

// ---------------------------------------------------------------------------
// Helpers
// ---------------------------------------------------------------------------
__device__ __forceinline__ uint32_t smem_u32(const void* p) {
    uint32_t a;
    asm("{ .reg .u64 t; cvta.to.shared.u64 t, %1; cvt.u32.u64 %0, t; }"
        : "=r"(a) : "l"(p));
    return a;
}

#define CP16(dst_u32, src_ptr) \
    asm volatile("cp.async.cg.shared.global [%0], [%1], 16;" \
                 :: "r"(dst_u32), "l"(src_ptr) : "memory")
#define CP_COMMIT() asm volatile("cp.async.commit_group;" ::: "memory")
#define CP_WAIT(n)  asm volatile("cp.async.wait_group %0;" :: "n"(n) : "memory")

__device__ __forceinline__ void mma16(float* d, const uint32_t* a,
                                      const uint32_t* b) {
    asm volatile(
        "mma.sync.aligned.m16n8k16.row.col.f32.f16.f16.f32 "
        "{%0,%1,%2,%3}, {%4,%5,%6,%7}, {%8,%9}, {%0,%1,%2,%3};"
        : "+f"(d[0]), "+f"(d[1]), "+f"(d[2]), "+f"(d[3])
        : "r"(a[0]), "r"(a[1]), "r"(a[2]), "r"(a[3]), "r"(b[0]), "r"(b[1]));
}

__device__ __forceinline__ void ldsm_x4(uint32_t* r, uint32_t addr) {
    asm volatile(
        "ldmatrix.sync.aligned.m8n8.x4.shared.b16 {%0,%1,%2,%3}, [%4];"
        : "=r"(r[0]), "=r"(r[1]), "=r"(r[2]), "=r"(r[3]) : "r"(addr));
}

__device__ __forceinline__ void split_h(float y, __half& h, __half& l) {
    h = __float2half_rn(y);
    l = __float2half_rn(y - __half2float(h));
}

// ---------------------------------------------------------------------------
// Shared GEMM mainloop pieces (fp16-split, BM=128, BN=128, BK=32, 256 thr)
// ---------------------------------------------------------------------------
#define PH 40
#define T_AH 0
#define T_AL (128 * PH)
#define T_BH (2 * 128 * PH)
#define T_BL (3 * 128 * PH)
#define STAGE_H (4 * 128 * PH)
#define GEMM_SMEM (2 * STAGE_H * 2)     // 81920 bytes

template <bool AEX>
__device__ __forceinline__ void issue_chunk_h(
    uint32_t smb, int s, int c,
    const __half* __restrict__ A_hi, const __half* __restrict__ A_lo,
    const __half* __restrict__ B_hi, const __half* __restrict__ B_lo,
    int K, int bm0, int bn0, int tid) {
    const int k0 = c * 32;
    const uint32_t sb = smb + (uint32_t)(s * STAGE_H) * 2u;
#pragma unroll
    for (int i = 0; i < 2; i++) {
        const int f = tid + i * 256;
        const int row = f >> 2;
        const int q = f & 3;
        const uint32_t doff = (uint32_t)(row * PH + q * 8) * 2u;
        CP16(sb + T_AH * 2 + doff, A_hi + (size_t)(bm0 + row) * K + k0 + q * 8);
        if (!AEX)
            CP16(sb + T_AL * 2 + doff,
                 A_lo + (size_t)(bm0 + row) * K + k0 + q * 8);
        CP16(sb + T_BH * 2 + doff, B_hi + (size_t)(bn0 + row) * K + k0 + q * 8);
        CP16(sb + T_BL * 2 + doff, B_lo + (size_t)(bn0 + row) * K + k0 + q * 8);
    }
    CP_COMMIT();
}

// Mainloop: accumulates into acc[4][4][4]; caller handles epilogue.
template <bool AEX>
__device__ __forceinline__ void gemm_mainloop(
    uint32_t smb, const __half* __restrict__ A_hi,
    const __half* __restrict__ A_lo, const __half* __restrict__ Bt_hi,
    const __half* __restrict__ Bt_lo, int K, int bm0, int bn0, int tid,
    float acc[4][4][4]) {
    const int l = tid & 31;
    const int warp = tid >> 5;
    const int wm = warp >> 2;
    const int wn = warp & 3;
    const int NC = K >> 5;

    issue_chunk_h<AEX>(smb, 0, 0, A_hi, A_lo, Bt_hi, Bt_lo, K, bm0, bn0, tid);

    const uint32_t aoff = (uint32_t)(((l & 15) * PH + (l >> 4) * 8) * 2);
    const uint32_t boff = (uint32_t)(((((l >> 4) & 1) * 8 + (l & 7)) * PH +
                                      ((l >> 3) & 1) * 8) * 2);

    for (int c = 0; c < NC; c++) {
        const int s = c & 1;
        if (c + 1 < NC) {
            issue_chunk_h<AEX>(smb, (c + 1) & 1, c + 1, A_hi, A_lo, Bt_hi,
                               Bt_lo, K, bm0, bn0, tid);
            CP_WAIT(1);
        } else {
            CP_WAIT(0);
        }
        __syncthreads();

        const uint32_t stage = smb + (uint32_t)(s * STAGE_H) * 2u;
        const uint32_t baseAh = stage + (uint32_t)((T_AH + wm * 64 * PH) * 2) + aoff;
        const uint32_t baseAl = stage + (uint32_t)((T_AL + wm * 64 * PH) * 2) + aoff;
        const uint32_t baseBh = stage + (uint32_t)((T_BH + wn * 32 * PH) * 2) + boff;
        const uint32_t baseBl = stage + (uint32_t)((T_BL + wn * 32 * PH) * 2) + boff;

#pragma unroll
        for (int ks = 0; ks < 2; ks++) {
            const uint32_t koff = (uint32_t)(ks * 16 * 2);
            uint32_t bh[4][2], bl[4][2];
#pragma unroll
            for (int j = 0; j < 2; j++) {
                uint32_t t[4];
                ldsm_x4(t, baseBh + (uint32_t)(j * 16 * PH * 2) + koff);
                bh[2 * j][0] = t[0]; bh[2 * j][1] = t[1];
                bh[2 * j + 1][0] = t[2]; bh[2 * j + 1][1] = t[3];
                ldsm_x4(t, baseBl + (uint32_t)(j * 16 * PH * 2) + koff);
                bl[2 * j][0] = t[0]; bl[2 * j][1] = t[1];
                bl[2 * j + 1][0] = t[2]; bl[2 * j + 1][1] = t[3];
            }
#pragma unroll
            for (int mf = 0; mf < 4; mf++) {
                uint32_t ah[4], al[4];
                ldsm_x4(ah, baseAh + (uint32_t)(mf * 16 * PH * 2) + koff);
                if (!AEX)
                    ldsm_x4(al, baseAl + (uint32_t)(mf * 16 * PH * 2) + koff);
#pragma unroll
                for (int nf = 0; nf < 4; nf++) {
                    mma16(acc[mf][nf], ah, bh[nf]);
                    mma16(acc[mf][nf], ah, bl[nf]);
                    if (!AEX) mma16(acc[mf][nf], al, bh[nf]);
                }
            }
        }
        __syncthreads();
    }
}

// Epilogue for relu+split / fp32 outputs
template <int OMODE>   // 0 = relu+split, 1 = fp32, 2 = mixed L1
__device__ __forceinline__ void gemm_epilogue(
    float acc[4][4][4], const float* __restrict__ bias,
    __half* __restrict__ O_hi, __half* __restrict__ O_lo,
    float* __restrict__ Of, int Nout, int bm0, int bn0, int tid) {
    const int l = tid & 31;
    const int warp = tid >> 5;
    const int wm = warp >> 2;
    const int wn = warp & 3;
    const int rA = l >> 2;
    const int cK = l & 3;
    const bool f32_region = (OMODE == 1) || (OMODE == 2 && bn0 >= HP);
    const int ow = (OMODE == 2) ? (f32_region ? HS : HP) : Nout;
    const int cbase = (OMODE == 2 && f32_region) ? (bn0 - HP) : bn0;

#pragma unroll
    for (int nf = 0; nf < 4; nf++) {
        const int gcol = bn0 + wn * 32 + nf * 8 + 2 * cK;
        const int col = cbase + wn * 32 + nf * 8 + 2 * cK;
        const float2 bv = *reinterpret_cast<const float2*>(bias + gcol);
#pragma unroll
        for (int mf = 0; mf < 4; mf++) {
            const int ra = bm0 + wm * 64 + mf * 16 + rA;
            float y[4];
            y[0] = acc[mf][nf][0] + bv.x;
            y[1] = acc[mf][nf][1] + bv.y;
            y[2] = acc[mf][nf][2] + bv.x;
            y[3] = acc[mf][nf][3] + bv.y;
            if (OMODE != 1) {
#pragma unroll
                for (int r = 0; r < 4; r++) y[r] = fmaxf(y[r], 0.0f);
            }
            if (!f32_region && OMODE != 1) {
                __half h[4], lo[4];
#pragma unroll
                for (int r = 0; r < 4; r++) split_h(y[r], h[r], lo[r]);
                *reinterpret_cast<__half2*>(O_hi + (size_t)ra * ow + col) =
                    __halves2half2(h[0], h[1]);
                *reinterpret_cast<__half2*>(O_hi + (size_t)(ra + 8) * ow + col) =
                    __halves2half2(h[2], h[3]);
                *reinterpret_cast<__half2*>(O_lo + (size_t)ra * ow + col) =
                    __halves2half2(lo[0], lo[1]);
                *reinterpret_cast<__half2*>(O_lo + (size_t)(ra + 8) * ow + col) =
                    __halves2half2(lo[2], lo[3]);
            } else {
                *reinterpret_cast<float2*>(Of + (size_t)ra * ow + col) =
                    make_float2(y[0], y[1]);
                *reinterpret_cast<float2*>(Of + (size_t)(ra + 8) * ow + col) =
                    make_float2(y[2], y[3]);
            }
        }
    }
}

// Plain GEMM kernels (L1 mixed, L3 split, L4 fp32)
template <bool AEX, int OMODE>
__global__ void __launch_bounds__(256, 2)
gemm_h(const __half* __restrict__ A_hi, const __half* __restrict__ A_lo,
       const __half* __restrict__ Bt_hi, const __half* __restrict__ Bt_lo,
       const float* __restrict__ bias,
       __half* __restrict__ O_hi, __half* __restrict__ O_lo,
       float* __restrict__ Of,
       int K, int Nout) {
    extern __shared__ __half smh[];
    const uint32_t smb = smem_u32(smh);
    const int tid = threadIdx.x;
    const int bm0 = blockIdx.y * 128;
    const int bn0 = blockIdx.x * 128;

    float acc[4][4][4];
#pragma unroll
    for (int mf = 0; mf < 4; mf++)
#pragma unroll
        for (int nf = 0; nf < 4; nf++)
#pragma unroll
            for (int r = 0; r < 4; r++) acc[mf][nf][r] = 0.0f;

    gemm_mainloop<AEX>(smb, A_hi, A_lo, Bt_hi, Bt_lo, K, bm0, bn0, tid, acc);
    gemm_epilogue<OMODE>(acc, bias, O_hi, O_lo, Of, Nout, bm0, bn0, tid);
}

// ---------------------------------------------------------------------------
// Selector head body (3-stage cp.async pipeline) — runs inside fused kernel.
// smc points at >= 20 KB of shared memory.
// ---------------------------------------------------------------------------
__device__ __forceinline__ void sel_head_body(
    char* smc, int bm0, int tid,
    const float* __restrict__ A, const float* __restrict__ B,
    const float* __restrict__ bias, float* __restrict__ C) {
    float (*As)[32][20] = reinterpret_cast<float (*)[32][20]>(smc);
    float (*Bs)[16][64] = reinterpret_cast<float (*)[16][64]>(smc + 3 * 32 * 20 * 4);

    const int tx = tid & 15;
    const int ty = tid >> 4;
    const int K = HS, N = NN;
    const int NC = K / 16;

    const uint32_t asb = smem_u32(As);
    const uint32_t bsb = smem_u32(Bs);

    auto issue = [&](int c) {
        const int s = c % 3;
        const int k0 = c * 16;
        if (tid < 128) {
            const int row = tid >> 2;
            const int q = tid & 3;
            CP16(asb + (uint32_t)(((s * 32 + row) * 20 + q * 4) * 4),
                 A + (size_t)(bm0 + row) * K + k0 + q * 4);
        }
        {
            const int kr = tid >> 4;
            const int q = tid & 15;
            CP16(bsb + (uint32_t)(((s * 16 + kr) * 64 + q * 4) * 4),
                 B + (size_t)(k0 + kr) * N + q * 4);
        }
        CP_COMMIT();
    };

    float acc[2][4] = {{0.f, 0.f, 0.f, 0.f}, {0.f, 0.f, 0.f, 0.f}};

    issue(0);
    issue(1);
    issue(2);

    for (int c = 0; c < NC; c++) {
        const int s = c % 3;
        CP_WAIT(2);
        __syncthreads();

#pragma unroll
        for (int k = 0; k < 16; k++) {
            float a0 = As[s][ty * 2][k];
            float a1 = As[s][ty * 2 + 1][k];
            float4 bv = *reinterpret_cast<const float4*>(&Bs[s][k][tx * 4]);
            acc[0][0] = fmaf(a0, bv.x, acc[0][0]);
            acc[0][1] = fmaf(a0, bv.y, acc[0][1]);
            acc[0][2] = fmaf(a0, bv.z, acc[0][2]);
            acc[0][3] = fmaf(a0, bv.w, acc[0][3]);
            acc[1][0] = fmaf(a1, bv.x, acc[1][0]);
            acc[1][1] = fmaf(a1, bv.y, acc[1][1]);
            acc[1][2] = fmaf(a1, bv.z, acc[1][2]);
            acc[1][3] = fmaf(a1, bv.w, acc[1][3]);
        }
        __syncthreads();
        if (c + 3 < NC) issue(c + 3);
    }

    float4 bvec = *reinterpret_cast<const float4*>(bias + tx * 4);
    float bias4[4] = {bvec.x, bvec.y, bvec.z, bvec.w};
#pragma unroll
    for (int i = 0; i < 2; i++) {
        float4 v;
        float* vp = &v.x;
#pragma unroll
        for (int j = 0; j < 4; j++) {
            float cv = acc[i][j] + bias4[j];
            vp[j] = 1.0f / (1.0f + expf(-cv));
        }
        *reinterpret_cast<float4*>(
            C + (size_t)(bm0 + ty * 2 + i) * N + tx * 4) = v;
    }
}

// ---------------------------------------------------------------------------
// FUSED gemm2 + selector head. grid = (8, 64 + 32):
//   y <  64: gemm2 tile (a_hi/a_lo @ pw2 -> b_hi/b_lo, relu+split)
//   y >= 64: head block hb = (y-64)*8 + x in [0,256): 32 rows of P each
// ---------------------------------------------------------------------------
__global__ void __launch_bounds__(256, 2)
gemm2_head_kernel(const __half* __restrict__ A_hi,
                  const __half* __restrict__ A_lo,
                  const __half* __restrict__ Bt_hi,
                  const __half* __restrict__ Bt_lo,
                  const float* __restrict__ bias,
                  __half* __restrict__ O_hi, __half* __restrict__ O_lo,
                  const float* __restrict__ s1, const float* __restrict__ sw2,
                  const float* __restrict__ sb2, float* __restrict__ P) {
    extern __shared__ char smc[];
    const int tid = threadIdx.x;

    if (blockIdx.y >= 64) {
        const int hb = (blockIdx.y - 64) * 8 + blockIdx.x;   // 0..255
        sel_head_body(smc, hb * 32, tid, s1, sw2, sb2, P);
        return;
    }

    const uint32_t smb = smem_u32(smc);
    const int bm0 = blockIdx.y * 128;
    const int bn0 = blockIdx.x * 128;

    float acc[4][4][4];
#pragma unroll
    for (int mf = 0; mf < 4; mf++)
#pragma unroll
        for (int nf = 0; nf < 4; nf++)
#pragma unroll
            for (int r = 0; r < 4; r++) acc[mf][nf][r] = 0.0f;

    gemm_mainloop<false>(smb, A_hi, A_lo, Bt_hi, Bt_lo, HP, bm0, bn0, tid, acc);
    gemm_epilogue<0>(acc, bias, O_hi, O_lo, nullptr, HP, bm0, bn0, tid);
}

// ---------------------------------------------------------------------------
// MERGED prep: blocks [0,2048) convert x->fp16 (+bias concat);
//              blocks [2048,5376) transpose+split the 5 weights.
// ---------------------------------------------------------------------------
__global__ void __launch_bounds__(256)
prep_kernel(const float* __restrict__ x, __half* __restrict__ xh,
            const float* __restrict__ pb1, const float* __restrict__ sb1,
            float* __restrict__ bias_l1,
            const float* __restrict__ pw1, const float* __restrict__ sw1,
            const float* __restrict__ pw2, const float* __restrict__ pw3,
            const float* __restrict__ pw4,
            __half* __restrict__ bt_hi, __half* __restrict__ bt_lo) {
    if (blockIdx.x < 2048) {
        const int t = blockIdx.x * 256 + threadIdx.x;
        const float4 a = *reinterpret_cast<const float4*>(x + (size_t)t * 8);
        const float4 b = *reinterpret_cast<const float4*>(x + (size_t)t * 8 + 4);
        __half2 o[4];
        o[0] = __halves2half2(__float2half_rn(a.x), __float2half_rn(a.y));
        o[1] = __halves2half2(__float2half_rn(a.z), __float2half_rn(a.w));
        o[2] = __halves2half2(__float2half_rn(b.x), __float2half_rn(b.y));
        o[3] = __halves2half2(__float2half_rn(b.z), __float2half_rn(b.w));
        *reinterpret_cast<uint4*>(xh + (size_t)t * 8) =
            *reinterpret_cast<uint4*>(o);
        if (t < HP + HS)
            bias_l1[t] = (t < HP) ? pb1[t] : sb1[t - HP];
        return;
    }

    const int b = blockIdx.x - 2048;
    const float* W;
    int off, K, N, lb;
    if (b < 512)        { W = pw1; off = OF_PW1; K = 512;  N = 1024; lb = b; }
    else if (b < 768)   { W = sw1; off = OF_SW1; K = 512;  N = 512;  lb = b - 512; }
    else if (b < 1792)  { W = pw2; off = OF_PW2; K = 1024; N = 1024; lb = b - 768; }
    else if (b < 2816)  { W = pw3; off = OF_PW3; K = 1024; N = 1024; lb = b - 1792; }
    else                { W = pw4; off = OF_PW4; K = 1024; N = 512;  lb = b - 2816; }
    const int kt = K >> 5;
    const int kb = (lb % kt) * 32;
    const int nb = (lb / kt) * 32;

    __shared__ float t[32][33];
    const int tx = threadIdx.x & 31;
    const int ty = threadIdx.x >> 5;
#pragma unroll
    for (int r = ty; r < 32; r += 8)
        t[r][tx] = W[(size_t)(kb + r) * N + nb + tx];
    __syncthreads();
#pragma unroll
    for (int r = ty; r < 32; r += 8) {
        float wv = t[tx][r];
        __half h, lo;
        split_h(wv, h, lo);
        size_t o = (size_t)off + (size_t)(nb + r) * K + kb + tx;
        bt_hi[o] = h;
        bt_lo[o] = lo;
    }
}

// ---------------------------------------------------------------------------
// Fused elementwise tail (+ truth_x passthrough)
// ---------------------------------------------------------------------------
__device__ __forceinline__ void gs8(const float* l, const float* g, float* xt) {
    float m = l[0];
#pragma unroll
    for (int c = 1; c < 8; c++) m = fmaxf(m, l[c]);
    float e[8], s = 0.0f;
#pragma unroll
    for (int c = 0; c < 8; c++) { e[c] = expf(l[c] - m); s += e[c]; }
    float t[8];
#pragma unroll
    for (int c = 0; c < 8; c++) {
        float pr = e[c] / s;
        pr = 0.9f * pr + 0.0125f;
        t[c] = (logf(pr) + g[c]) / 0.7f;
    }
    float m2 = t[0];
#pragma unroll
    for (int c = 1; c < 8; c++) m2 = fmaxf(m2, t[c]);
    float e2[8], s2 = 0.0f;
#pragma unroll
    for (int c = 0; c < 8; c++) { e2[c] = expf(t[c] - m2); s2 += e2[c]; }
#pragma unroll
    for (int c = 0; c < 8; c++) xt[c] = e2[c] / s2;
}

__global__ void finalize_kernel(const float* __restrict__ x,
                                const float* __restrict__ Pm,
                                const float* __restrict__ W,
                                const float* __restrict__ truth,
                                float* __restrict__ out_truth,
                                float* __restrict__ xcf) {
    const int b = blockIdx.x;
    const int n = threadIdx.x;
    __shared__ float sh_cst, sh_incr;

    const size_t base = (size_t)b * DD + n * CC;

    // truth_x passthrough (same indexing, saves a separate memcpy launch)
    *reinterpret_cast<float4*>(out_truth + base) =
        *reinterpret_cast<const float4*>(truth + base);
    *reinterpret_cast<float4*>(out_truth + base + 4) =
        *reinterpret_cast<const float4*>(truth + base + 4);

    float4 xa = *reinterpret_cast<const float4*>(x + base);
    float4 xb = *reinterpret_cast<const float4*>(x + base + 4);
    float4 wa = *reinterpret_cast<const float4*>(W + base);
    float4 wb = *reinterpret_cast<const float4*>(W + base + 4);
    float xv[8] = {xa.x, xa.y, xa.z, xa.w, xb.x, xb.y, xb.z, xb.w};
    float Wv[8] = {wa.x, wa.y, wa.z, wa.w, wb.x, wb.y, wb.z, wb.w};

    const unsigned i = (unsigned)(b * NN + n);
    const float P = Pm[i];

    float ua = jax_u01(KA0, KA1, i);
    float ub = jax_u01(KB0, KB1, i);
    float ea = expf(-logf(-logf(ua)));
    float eb = expf(-logf(-logf(ub)));
    float no = P * ea / 0.7f;
    float de = no + (1.0f - P) * eb / 0.7f;
    float probs = no / de;

    float g[8];
#pragma unroll
    for (int c = 0; c < 8; c++) {
        float u = jax_u01(KG0, KG1, i * 8u + (unsigned)c);
        g[c] = -logf(-logf(u));
    }

    int curr = 0;
    {
        float m = xv[0];
#pragma unroll
        for (int c = 1; c < 8; c++)
            if (xv[c] > m) { m = xv[c]; curr = c; }
    }

    if (n == 2) {
        float xt_par[8];
        gs8(Wv, g, xt_par);
        int am = 0;
        float m = probs * xt_par[0] + (1.0f - probs) * xv[0];
#pragma unroll
        for (int c = 1; c < 8; c++) {
            float v = probs * xt_par[c] + (1.0f - probs) * xv[c];
            if (v > m) { m = v; am = c; }
        }
        int diff = am - curr;
        sh_cst  = (diff == 0) ? 1.0f : 0.0f;
        sh_incr = (diff >  0) ? 1.0f : 0.0f;
    }
    __syncthreads();
    const float cst = sh_cst;
    const float incr = sh_incr;

    float l[8];
    if (n == 0 || n == 5 || n == 10) {
#pragma unroll
        for (int c = 0; c < 8; c++) l[c] = Wv[c] + ((c < curr) ? -100.0f : 1.0f);
    } else if (n == 7) {
        const int thr = curr + 1;
        const bool inc = (incr > 0.5f);
#pragma unroll
        for (int c = 0; c < 8; c++)
            l[c] = Wv[c] + ((inc && c < thr) ? -100.0f : 1.0f);
    } else {
#pragma unroll
        for (int c = 0; c < 8; c++) l[c] = Wv[c];
    }

    float xt[8];
    gs8(l, g, xt);

    float p2 = probs;
    if (n == 7) {
        float pc = probs * (1.0f - cst);
        pc = pc + incr;
        p2 = fminf(fmaxf(pc, 0.0f), 1.0f);
    }

    float4 oa, ob;
    float* op = &oa.x;
#pragma unroll
    for (int c = 0; c < 4; c++) op[c] = p2 * xt[c] + (1.0f - p2) * xv[c];
    op = &ob.x;
#pragma unroll
    for (int c = 0; c < 4; c++) op[c] = p2 * xt[c + 4] + (1.0f - p2) * xv[c + 4];
    *reinterpret_cast<float4*>(xcf + base) = oa;
    *reinterpret_cast<float4*>(xcf + base + 4) = ob;
}

// ---------------------------------------------------------------------------
// Launch
// ---------------------------------------------------------------------------
extern "C" void kernel_launch(void* const* d_in, const int* in_sizes, int n_in,
                              void* d_out, int out_size) {
    const float* x     = (const float*)d_in[0];
    const float* truth = (const float*)d_in[1];
    const float* sw1   = (const float*)d_in[2];
    const float* sb1   = (const float*)d_in[3];
    const float* sw2   = (const float*)d_in[4];
    const float* sb2   = (const float*)d_in[5];
    const float* pw1   = (const float*)d_in[6];
    const float* pb1   = (const float*)d_in[7];
    const float* pw2   = (const float*)d_in[8];
    const float* pb2   = (const float*)d_in[9];
    const float* pw3   = (const float*)d_in[10];
    const float* pb3   = (const float*)d_in[11];
    const float* pw4   = (const float*)d_in[12];
    const float* pb4   = (const float*)d_in[13];

    float* out       = (float*)d_out;
    float* out_truth = out;
    float* out_xcf   = out + BD_ELEMS;
    float* out_P     = out + 2 * (size_t)BD_ELEMS;
    float* out_W     = out + 2 * (size_t)BD_ELEMS + BN_ELEMS;

    __half *a_hi, *a_lo, *b_hi, *b_lo, *xh, *wt_hi, *wt_lo;
    float *s1, *bias_l1;
    cudaGetSymbolAddress((void**)&a_hi, g_a_hi);
    cudaGetSymbolAddress((void**)&a_lo, g_a_lo);
    cudaGetSymbolAddress((void**)&b_hi, g_b_hi);
    cudaGetSymbolAddress((void**)&b_lo, g_b_lo);
    cudaGetSymbolAddress((void**)&xh,   g_xh);
    cudaGetSymbolAddress((void**)&s1,   g_s1);
    cudaGetSymbolAddress((void**)&wt_hi, g_wt_hi);
    cudaGetSymbolAddress((void**)&wt_lo, g_wt_lo);
    cudaGetSymbolAddress((void**)&bias_l1, g_bias_l1);

    cudaFuncSetAttribute(gemm_h<true, 2>,
                         cudaFuncAttributeMaxDynamicSharedMemorySize, GEMM_SMEM);
    cudaFuncSetAttribute(gemm_h<false, 0>,
                         cudaFuncAttributeMaxDynamicSharedMemorySize, GEMM_SMEM);
    cudaFuncSetAttribute(gemm_h<false, 1>,
                         cudaFuncAttributeMaxDynamicSharedMemorySize, GEMM_SMEM);
    cudaFuncSetAttribute(gemm2_head_kernel,
                         cudaFuncAttributeMaxDynamicSharedMemorySize, GEMM_SMEM);

    // Prep: x->fp16 + bias concat + all weight splits, one launch
    prep_kernel<<<5376, 256>>>(x, xh, pb1, sb1, bias_l1,
                               pw1, sw1, pw2, pw3, pw4, wt_hi, wt_lo);

    // L1 (pw1 + sw1 merged, AEX, mixed epilogue)
    gemm_h<true, 2><<<dim3((HP + HS) / 128, BB / 128), 256, GEMM_SMEM>>>(
        xh, nullptr, wt_hi, wt_lo, bias_l1, a_hi, a_lo, s1, DD, HP);

    // gemm2 FUSED with selector head (head fills tail waves)
    gemm2_head_kernel<<<dim3(HP / 128, BB / 128 + 32), 256, GEMM_SMEM>>>(
        a_hi, a_lo, wt_hi + OF_PW2, wt_lo + OF_PW2, pb2, b_hi, b_lo,
        s1, sw2, sb2, out_P);

    // gemm3, gemm4
    gemm_h<false, 0><<<dim3(HP / 128, BB / 128), 256, GEMM_SMEM>>>(
        b_hi, b_lo, wt_hi + OF_PW3, wt_lo + OF_PW3, pb3, a_hi, a_lo, nullptr,
        HP, HP);
    gemm_h<false, 1><<<dim3(DD / 128, BB / 128), 256, GEMM_SMEM>>>(
        a_hi, a_lo, wt_hi + OF_PW4, wt_lo + OF_PW4, pb4, nullptr, nullptr,
        out_W, HP, DD);

    // Fused tail (+ truth passthrough)
    finalize_kernel<<<BB, NN>>>(x, out_P, out_W, truth, out_truth, out_xcf);
}

// round 11
// speedup vs baseline: 2.9526x; 1.1056x over previous
#include <cuda_runtime.h>
#include <cuda_fp16.h>
#include <cstdint>
#include <math.h>

// ---------------------------------------------------------------------------
// Problem constants
// ---------------------------------------------------------------------------
#define BB 8192
#define NN 64
#define CC 8
#define DD (NN * CC)        // 512
#define HP 1024
#define HS 512
#define BD_ELEMS (BB * DD)  // 4,194,304
#define BN_ELEMS (BB * NN)  // 524,288

// ---------------------------------------------------------------------------
// Scratch (allocation-free: __device__ globals)
// ---------------------------------------------------------------------------
__device__ __half g_a_hi[BB * HP];
__device__ __half g_a_lo[BB * HP];
__device__ __half g_b_hi[BB * HP];
__device__ __half g_b_lo[BB * HP];
__device__ __half g_xh[BB * DD];
__device__ float  g_s1[BB * HS];
__device__ float  g_bias_l1[HP + HS];   // pb1 ++ sb1

// Transposed + split weights, packed (Bt[n][k] layout), fp16 hi/lo.
#define OF_PW1 0
#define OF_SW1 524288
#define OF_PW2 786432
#define OF_PW3 1835008
#define OF_PW4 2883584
#define WT_TOTAL 3407872
__device__ __half g_wt_hi[WT_TOTAL];
__device__ __half g_wt_lo[WT_TOTAL];

// ---------------------------------------------------------------------------
// Threefry-2x32-20 (JAX)
// ---------------------------------------------------------------------------
struct TFK { unsigned a, b; };

__host__ __device__ constexpr unsigned tf_rotl(unsigned v, int r) {
    return (v << r) | (v >> (32 - r));
}

__host__ __device__ constexpr TFK tf2x32(unsigned k0, unsigned k1,
                                         unsigned x0, unsigned x1) {
    unsigned k2 = k0 ^ k1 ^ 0x1BD11BDAu;
    x0 += k0; x1 += k1;
    x0 += x1; x1 = tf_rotl(x1, 13); x1 ^= x0;
    x0 += x1; x1 = tf_rotl(x1, 15); x1 ^= x0;
    x0 += x1; x1 = tf_rotl(x1, 26); x1 ^= x0;
    x0 += x1; x1 = tf_rotl(x1,  6); x1 ^= x0;
    x0 += k1; x1 += k2 + 1u;
    x0 += x1; x1 = tf_rotl(x1, 17); x1 ^= x0;
    x0 += x1; x1 = tf_rotl(x1, 29); x1 ^= x0;
    x0 += x1; x1 = tf_rotl(x1, 16); x1 ^= x0;
    x0 += x1; x1 = tf_rotl(x1, 24); x1 ^= x0;
    x0 += k2; x1 += k0 + 2u;
    x0 += x1; x1 = tf_rotl(x1, 13); x1 ^= x0;
    x0 += x1; x1 = tf_rotl(x1, 15); x1 ^= x0;
    x0 += x1; x1 = tf_rotl(x1, 26); x1 ^= x0;
    x0 += x1; x1 = tf_rotl(x1,  6); x1 ^= x0;
    x0 += k0; x1 += k1 + 3u;
    x0 += x1; x1 = tf_rotl(x1, 17); x1 ^= x0;
    x0 += x1; x1 = tf_rotl(x1, 29); x1 ^= x0;
    x0 += x1; x1 = tf_rotl(x1, 16); x1 ^= x0;
    x0 += x1; x1 = tf_rotl(x1, 24); x1 ^= x0;
    x0 += k1; x1 += k2 + 4u;
    x0 += x1; x1 = tf_rotl(x1, 13); x1 ^= x0;
    x0 += x1; x1 = tf_rotl(x1, 15); x1 ^= x0;
    x0 += x1; x1 = tf_rotl(x1, 26); x1 ^= x0;
    x0 += x1; x1 = tf_rotl(x1,  6); x1 ^= x0;
    x0 += k2; x1 += k0 + 5u;
    return TFK{x0, x1};
}

constexpr unsigned KA0 = tf2x32(0u, 42u, 0u, 0u).a;
constexpr unsigned KA1 = tf2x32(0u, 42u, 0u, 0u).b;
constexpr unsigned KB0 = tf2x32(0u, 42u, 0u, 1u).a;
constexpr unsigned KB1 = tf2x32(0u, 42u, 0u, 1u).b;
constexpr unsigned KG0 = tf2x32(0u, 42u, 0u, 2u).a;
constexpr unsigned KG1 = tf2x32(0u, 42u, 0u, 2u).b;

__device__ __forceinline__ float jax_u01(unsigned k0, unsigned k1, unsigned idx) {
    TFK r = tf2x32(k0, k1, 0u, idx);
    unsigned bits = r.a ^ r.b;
    float f = __uint_as_float((bits >> 9) | 0x3f800000u) - 1.0f;
    f = f + 1e-8f;
    return fmaxf(1e-8f, f);
}

// ---------------------------------------------------------------------------
// Helpers
// ---------------------------------------------------------------------------
__device__ __forceinline__ uint32_t smem_u32(const void* p) {
    uint32_t a;
    asm("{ .reg .u64 t; cvta.to.shared.u64 t, %1; cvt.u32.u64 %0, t; }"
        : "=r"(a) : "l"(p));
    return a;
}

#define CP16(dst_u32, src_ptr) \
    asm volatile("cp.async.cg.shared.global [%0], [%1], 16;" \
                 :: "r"(dst_u32), "l"(src_ptr) : "memory")
#define CP_COMMIT() asm volatile("cp.async.commit_group;" ::: "memory")
#define CP_WAIT(n)  asm volatile("cp.async.wait_group %0;" :: "n"(n) : "memory")

__device__ __forceinline__ void mma16(float* d, const uint32_t* a,
                                      const uint32_t* b) {
    asm volatile(
        "mma.sync.aligned.m16n8k16.row.col.f32.f16.f16.f32 "
        "{%0,%1,%2,%3}, {%4,%5,%6,%7}, {%8,%9}, {%0,%1,%2,%3};"
        : "+f"(d[0]), "+f"(d[1]), "+f"(d[2]), "+f"(d[3])
        : "r"(a[0]), "r"(a[1]), "r"(a[2]), "r"(a[3]), "r"(b[0]), "r"(b[1]));
}

__device__ __forceinline__ void ldsm_x4(uint32_t* r, uint32_t addr) {
    asm volatile(
        "ldmatrix.sync.aligned.m8n8.x4.shared.b16 {%0,%1,%2,%3}, [%4];"
        : "=r"(r[0]), "=r"(r[1]), "=r"(r[2]), "=r"(r[3]) : "r"(addr));
}

__device__ __forceinline__ void split_h(float y, __half& h, __half& l) {
    h = __float2half_rn(y);
    l = __float2half_rn(y - __half2float(h));
}

// ---------------------------------------------------------------------------
// fp16-split GEMM mainloop. BM=128, BN=128, BK=32, 256 thr, warps 2x4.
// Packed 64B rows + XOR swizzle (chunk' = chunk ^ ((row>>1)&3)), 3 stages,
// prefetch distance 2.
// ---------------------------------------------------------------------------
#define TILE_B 8192                     // 128 rows x 64 bytes
#define T_AH 0
#define T_AL TILE_B
#define T_BH (2 * TILE_B)
#define T_BL (3 * TILE_B)
#define STAGE_B (4 * TILE_B)            // 32768 bytes / stage
#define GEMM_SMEM (3 * STAGE_B)         // 98304 bytes

template <bool AEX>
__device__ __forceinline__ void issue_chunk_h(
    uint32_t smb, int c,
    const __half* __restrict__ A_hi, const __half* __restrict__ A_lo,
    const __half* __restrict__ B_hi, const __half* __restrict__ B_lo,
    int K, int bm0, int bn0, int tid) {
    const int k0 = c * 32;
    const uint32_t sb = smb + (uint32_t)((c % 3) * STAGE_B);
#pragma unroll
    for (int i = 0; i < 2; i++) {
        const int f = tid + i * 256;
        const int row = f >> 2;
        const int q = f & 3;
        const uint32_t doff =
            (uint32_t)(row * 64 + ((q ^ ((row >> 1) & 3)) * 16));
        CP16(sb + T_AH + doff, A_hi + (size_t)(bm0 + row) * K + k0 + q * 8);
        if (!AEX)
            CP16(sb + T_AL + doff,
                 A_lo + (size_t)(bm0 + row) * K + k0 + q * 8);
        CP16(sb + T_BH + doff, B_hi + (size_t)(bn0 + row) * K + k0 + q * 8);
        CP16(sb + T_BL + doff, B_lo + (size_t)(bn0 + row) * K + k0 + q * 8);
    }
    CP_COMMIT();
}

template <bool AEX>
__device__ __forceinline__ void gemm_mainloop(
    uint32_t smb, const __half* __restrict__ A_hi,
    const __half* __restrict__ A_lo, const __half* __restrict__ Bt_hi,
    const __half* __restrict__ Bt_lo, int K, int bm0, int bn0, int tid,
    float acc[4][4][4]) {
    const int l = tid & 31;
    const int warp = tid >> 5;
    const int wm = warp >> 2;
    const int wn = warp & 3;
    const int NC = K >> 5;

    issue_chunk_h<AEX>(smb, 0, A_hi, A_lo, Bt_hi, Bt_lo, K, bm0, bn0, tid);
    if (NC > 1)
        issue_chunk_h<AEX>(smb, 1, A_hi, A_lo, Bt_hi, Bt_lo, K, bm0, bn0, tid);

    // Lane-level fragment addressing (swizzle term is lane-only: (l>>1)&3)
    const int swz = (l >> 1) & 3;
    // A: row-within-tile = wm*64 + mf*16 + (l&15); base chunk = (l>>4)
    const uint32_t arow = (uint32_t)((wm * 64 + (l & 15)) * 64);
    const int acb = l >> 4;            // 0 or 1
    // B: row = wn*32 + j*16 + ((l>>4)&1)*8 + (l&7); base chunk = (l>>3)&1
    const uint32_t brow =
        (uint32_t)((wn * 32 + ((l >> 4) & 1) * 8 + (l & 7)) * 64);
    const int bcb = (l >> 3) & 1;

    for (int c = 0; c < NC; c++) {
        if (c + 2 < NC) {
            issue_chunk_h<AEX>(smb, c + 2, A_hi, A_lo, Bt_hi, Bt_lo, K, bm0,
                               bn0, tid);
            CP_WAIT(2);
        } else if (c + 1 < NC) {
            CP_WAIT(1);
        } else {
            CP_WAIT(0);
        }
        __syncthreads();

        const uint32_t stage = smb + (uint32_t)((c % 3) * STAGE_B);
        const uint32_t baseAh = stage + T_AH + arow;
        const uint32_t baseAl = stage + T_AL + arow;
        const uint32_t baseBh = stage + T_BH + brow;
        const uint32_t baseBl = stage + T_BL + brow;

#pragma unroll
        for (int ks = 0; ks < 2; ks++) {
            const uint32_t aco = (uint32_t)(((ks * 2 + acb) ^ swz) * 16);
            const uint32_t bco = (uint32_t)(((ks * 2 + bcb) ^ swz) * 16);
            uint32_t bh[4][2], bl[4][2];
#pragma unroll
            for (int j = 0; j < 2; j++) {
                uint32_t t[4];
                ldsm_x4(t, baseBh + (uint32_t)(j * 16 * 64) + bco);
                bh[2 * j][0] = t[0]; bh[2 * j][1] = t[1];
                bh[2 * j + 1][0] = t[2]; bh[2 * j + 1][1] = t[3];
                ldsm_x4(t, baseBl + (uint32_t)(j * 16 * 64) + bco);
                bl[2 * j][0] = t[0]; bl[2 * j][1] = t[1];
                bl[2 * j + 1][0] = t[2]; bl[2 * j + 1][1] = t[3];
            }
#pragma unroll
            for (int mf = 0; mf < 4; mf++) {
                uint32_t ah[4], al[4];
                ldsm_x4(ah, baseAh + (uint32_t)(mf * 16 * 64) + aco);
                if (!AEX)
                    ldsm_x4(al, baseAl + (uint32_t)(mf * 16 * 64) + aco);
#pragma unroll
                for (int nf = 0; nf < 4; nf++) {
                    mma16(acc[mf][nf], ah, bh[nf]);
                    mma16(acc[mf][nf], ah, bl[nf]);
                    if (!AEX) mma16(acc[mf][nf], al, bh[nf]);
                }
            }
        }
        __syncthreads();
    }
}

// Epilogue for relu+split / fp32 outputs
template <int OMODE>   // 0 = relu+split, 1 = fp32, 2 = mixed L1
__device__ __forceinline__ void gemm_epilogue(
    float acc[4][4][4], const float* __restrict__ bias,
    __half* __restrict__ O_hi, __half* __restrict__ O_lo,
    float* __restrict__ Of, int Nout, int bm0, int bn0, int tid) {
    const int l = tid & 31;
    const int warp = tid >> 5;
    const int wm = warp >> 2;
    const int wn = warp & 3;
    const int rA = l >> 2;
    const int cK = l & 3;
    const bool f32_region = (OMODE == 1) || (OMODE == 2 && bn0 >= HP);
    const int ow = (OMODE == 2) ? (f32_region ? HS : HP) : Nout;
    const int cbase = (OMODE == 2 && f32_region) ? (bn0 - HP) : bn0;

#pragma unroll
    for (int nf = 0; nf < 4; nf++) {
        const int gcol = bn0 + wn * 32 + nf * 8 + 2 * cK;
        const int col = cbase + wn * 32 + nf * 8 + 2 * cK;
        const float2 bv = *reinterpret_cast<const float2*>(bias + gcol);
#pragma unroll
        for (int mf = 0; mf < 4; mf++) {
            const int ra = bm0 + wm * 64 + mf * 16 + rA;
            float y[4];
            y[0] = acc[mf][nf][0] + bv.x;
            y[1] = acc[mf][nf][1] + bv.y;
            y[2] = acc[mf][nf][2] + bv.x;
            y[3] = acc[mf][nf][3] + bv.y;
            if (OMODE != 1) {
#pragma unroll
                for (int r = 0; r < 4; r++) y[r] = fmaxf(y[r], 0.0f);
            }
            if (!f32_region && OMODE != 1) {
                __half h[4], lo[4];
#pragma unroll
                for (int r = 0; r < 4; r++) split_h(y[r], h[r], lo[r]);
                *reinterpret_cast<__half2*>(O_hi + (size_t)ra * ow + col) =
                    __halves2half2(h[0], h[1]);
                *reinterpret_cast<__half2*>(O_hi + (size_t)(ra + 8) * ow + col) =
                    __halves2half2(h[2], h[3]);
                *reinterpret_cast<__half2*>(O_lo + (size_t)ra * ow + col) =
                    __halves2half2(lo[0], lo[1]);
                *reinterpret_cast<__half2*>(O_lo + (size_t)(ra + 8) * ow + col) =
                    __halves2half2(lo[2], lo[3]);
            } else {
                *reinterpret_cast<float2*>(Of + (size_t)ra * ow + col) =
                    make_float2(y[0], y[1]);
                *reinterpret_cast<float2*>(Of + (size_t)(ra + 8) * ow + col) =
                    make_float2(y[2], y[3]);
            }
        }
    }
}

// Plain GEMM kernels (L1 mixed, L3 split, L4 fp32)
template <bool AEX, int OMODE>
__global__ void __launch_bounds__(256, 2)
gemm_h(const __half* __restrict__ A_hi, const __half* __restrict__ A_lo,
       const __half* __restrict__ Bt_hi, const __half* __restrict__ Bt_lo,
       const float* __restrict__ bias,
       __half* __restrict__ O_hi, __half* __restrict__ O_lo,
       float* __restrict__ Of,
       int K, int Nout) {
    extern __shared__ __half smh[];
    const uint32_t smb = smem_u32(smh);
    const int tid = threadIdx.x;
    const int bm0 = blockIdx.y * 128;
    const int bn0 = blockIdx.x * 128;

    float acc[4][4][4];
#pragma unroll
    for (int mf = 0; mf < 4; mf++)
#pragma unroll
        for (int nf = 0; nf < 4; nf++)
#pragma unroll
            for (int r = 0; r < 4; r++) acc[mf][nf][r] = 0.0f;

    gemm_mainloop<AEX>(smb, A_hi, A_lo, Bt_hi, Bt_lo, K, bm0, bn0, tid, acc);
    gemm_epilogue<OMODE>(acc, bias, O_hi, O_lo, Of, Nout, bm0, bn0, tid);
}

// ---------------------------------------------------------------------------
// Selector head body (3-stage cp.async pipeline) — runs inside fused kernel.
// ---------------------------------------------------------------------------
__device__ __forceinline__ void sel_head_body(
    char* smc, int bm0, int tid,
    const float* __restrict__ A, const float* __restrict__ B,
    const float* __restrict__ bias, float* __restrict__ C) {
    float (*As)[32][20] = reinterpret_cast<float (*)[32][20]>(smc);
    float (*Bs)[16][64] = reinterpret_cast<float (*)[16][64]>(smc + 3 * 32 * 20 * 4);

    const int tx = tid & 15;
    const int ty = tid >> 4;
    const int K = HS, N = NN;
    const int NC = K / 16;

    const uint32_t asb = smem_u32(As);
    const uint32_t bsb = smem_u32(Bs);

    auto issue = [&](int c) {
        const int s = c % 3;
        const int k0 = c * 16;
        if (tid < 128) {
            const int row = tid >> 2;
            const int q = tid & 3;
            CP16(asb + (uint32_t)(((s * 32 + row) * 20 + q * 4) * 4),
                 A + (size_t)(bm0 + row) * K + k0 + q * 4);
        }
        {
            const int kr = tid >> 4;
            const int q = tid & 15;
            CP16(bsb + (uint32_t)(((s * 16 + kr) * 64 + q * 4) * 4),
                 B + (size_t)(k0 + kr) * N + q * 4);
        }
        CP_COMMIT();
    };

    float acc[2][4] = {{0.f, 0.f, 0.f, 0.f}, {0.f, 0.f, 0.f, 0.f}};

    issue(0);
    issue(1);
    issue(2);

    for (int c = 0; c < NC; c++) {
        const int s = c % 3;
        CP_WAIT(2);
        __syncthreads();

#pragma unroll
        for (int k = 0; k < 16; k++) {
            float a0 = As[s][ty * 2][k];
            float a1 = As[s][ty * 2 + 1][k];
            float4 bv = *reinterpret_cast<const float4*>(&Bs[s][k][tx * 4]);
            acc[0][0] = fmaf(a0, bv.x, acc[0][0]);
            acc[0][1] = fmaf(a0, bv.y, acc[0][1]);
            acc[0][2] = fmaf(a0, bv.z, acc[0][2]);
            acc[0][3] = fmaf(a0, bv.w, acc[0][3]);
            acc[1][0] = fmaf(a1, bv.x, acc[1][0]);
            acc[1][1] = fmaf(a1, bv.y, acc[1][1]);
            acc[1][2] = fmaf(a1, bv.z, acc[1][2]);
            acc[1][3] = fmaf(a1, bv.w, acc[1][3]);
        }
        __syncthreads();
        if (c + 3 < NC) issue(c + 3);
    }

    float4 bvec = *reinterpret_cast<const float4*>(bias + tx * 4);
    float bias4[4] = {bvec.x, bvec.y, bvec.z, bvec.w};
#pragma unroll
    for (int i = 0; i < 2; i++) {
        float4 v;
        float* vp = &v.x;
#pragma unroll
        for (int j = 0; j < 4; j++) {
            float cv = acc[i][j] + bias4[j];
            vp[j] = 1.0f / (1.0f + expf(-cv));
        }
        *reinterpret_cast<float4*>(
            C + (size_t)(bm0 + ty * 2 + i) * N + tx * 4) = v;
    }
}

// ---------------------------------------------------------------------------
// FUSED gemm2 + selector head. grid = (8, 64 + 32)
// ---------------------------------------------------------------------------
__global__ void __launch_bounds__(256, 2)
gemm2_head_kernel(const __half* __restrict__ A_hi,
                  const __half* __restrict__ A_lo,
                  const __half* __restrict__ Bt_hi,
                  const __half* __restrict__ Bt_lo,
                  const float* __restrict__ bias,
                  __half* __restrict__ O_hi, __half* __restrict__ O_lo,
                  const float* __restrict__ s1, const float* __restrict__ sw2,
                  const float* __restrict__ sb2, float* __restrict__ P) {
    extern __shared__ char smc[];
    const int tid = threadIdx.x;

    if (blockIdx.y >= 64) {
        const int hb = (blockIdx.y - 64) * 8 + blockIdx.x;   // 0..255
        sel_head_body(smc, hb * 32, tid, s1, sw2, sb2, P);
        return;
    }

    const uint32_t smb = smem_u32(smc);
    const int bm0 = blockIdx.y * 128;
    const int bn0 = blockIdx.x * 128;

    float acc[4][4][4];
#pragma unroll
    for (int mf = 0; mf < 4; mf++)
#pragma unroll
        for (int nf = 0; nf < 4; nf++)
#pragma unroll
            for (int r = 0; r < 4; r++) acc[mf][nf][r] = 0.0f;

    gemm_mainloop<false>(smb, A_hi, A_lo, Bt_hi, Bt_lo, HP, bm0, bn0, tid, acc);
    gemm_epilogue<0>(acc, bias, O_hi, O_lo, nullptr, HP, bm0, bn0, tid);
}

// ---------------------------------------------------------------------------
// MERGED prep kernel
// ---------------------------------------------------------------------------
__global__ void __launch_bounds__(256)
prep_kernel(const float* __restrict__ x, __half* __restrict__ xh,
            const float* __restrict__ pb1, const float* __restrict__ sb1,
            float* __restrict__ bias_l1,
            const float* __restrict__ pw1, const float* __restrict__ sw1,
            const float* __restrict__ pw2, const float* __restrict__ pw3,
            const float* __restrict__ pw4,
            __half* __restrict__ bt_hi, __half* __restrict__ bt_lo) {
    if (blockIdx.x < 2048) {
        const int t = blockIdx.x * 256 + threadIdx.x;
        const float4 a = *reinterpret_cast<const float4*>(x + (size_t)t * 8);
        const float4 b = *reinterpret_cast<const float4*>(x + (size_t)t * 8 + 4);
        __half2 o[4];
        o[0] = __halves2half2(__float2half_rn(a.x), __float2half_rn(a.y));
        o[1] = __halves2half2(__float2half_rn(a.z), __float2half_rn(a.w));
        o[2] = __halves2half2(__float2half_rn(b.x), __float2half_rn(b.y));
        o[3] = __halves2half2(__float2half_rn(b.z), __float2half_rn(b.w));
        *reinterpret_cast<uint4*>(xh + (size_t)t * 8) =
            *reinterpret_cast<uint4*>(o);
        if (t < HP + HS)
            bias_l1[t] = (t < HP) ? pb1[t] : sb1[t - HP];
        return;
    }

    const int b = blockIdx.x - 2048;
    const float* W;
    int off, K, N, lb;
    if (b < 512)        { W = pw1; off = OF_PW1; K = 512;  N = 1024; lb = b; }
    else if (b < 768)   { W = sw1; off = OF_SW1; K = 512;  N = 512;  lb = b - 512; }
    else if (b < 1792)  { W = pw2; off = OF_PW2; K = 1024; N = 1024; lb = b - 768; }
    else if (b < 2816)  { W = pw3; off = OF_PW3; K = 1024; N = 1024; lb = b - 1792; }
    else                { W = pw4; off = OF_PW4; K = 1024; N = 512;  lb = b - 2816; }
    const int kt = K >> 5;
    const int kb = (lb % kt) * 32;
    const int nb = (lb / kt) * 32;

    __shared__ float t[32][33];
    const int tx = threadIdx.x & 31;
    const int ty = threadIdx.x >> 5;
#pragma unroll
    for (int r = ty; r < 32; r += 8)
        t[r][tx] = W[(size_t)(kb + r) * N + nb + tx];
    __syncthreads();
#pragma unroll
    for (int r = ty; r < 32; r += 8) {
        float wv = t[tx][r];
        __half h, lo;
        split_h(wv, h, lo);
        size_t o = (size_t)off + (size_t)(nb + r) * K + kb + tx;
        bt_hi[o] = h;
        bt_lo[o] = lo;
    }
}

// ---------------------------------------------------------------------------
// Fused elementwise tail (+ truth_x passthrough)
// ---------------------------------------------------------------------------
__device__ __forceinline__ void gs8(const float* l, const float* g, float* xt) {
    float m = l[0];
#pragma unroll
    for (int c = 1; c < 8; c++) m = fmaxf(m, l[c]);
    float e[8], s = 0.0f;
#pragma unroll
    for (int c = 0; c < 8; c++) { e[c] = expf(l[c] - m); s += e[c]; }
    float t[8];
#pragma unroll
    for (int c = 0; c < 8; c++) {
        float pr = e[c] / s;
        pr = 0.9f * pr + 0.0125f;
        t[c] = (logf(pr) + g[c]) / 0.7f;
    }
    float m2 = t[0];
#pragma unroll
    for (int c = 1; c < 8; c++) m2 = fmaxf(m2, t[c]);
    float e2[8], s2 = 0.0f;
#pragma unroll
    for (int c = 0; c < 8; c++) { e2[c] = expf(t[c] - m2); s2 += e2[c]; }
#pragma unroll
    for (int c = 0; c < 8; c++) xt[c] = e2[c] / s2;
}

__global__ void finalize_kernel(const float* __restrict__ x,
                                const float* __restrict__ Pm,
                                const float* __restrict__ W,
                                const float* __restrict__ truth,
                                float* __restrict__ out_truth,
                                float* __restrict__ xcf) {
    const int b = blockIdx.x;
    const int n = threadIdx.x;
    __shared__ float sh_cst, sh_incr;

    const size_t base = (size_t)b * DD + n * CC;

    *reinterpret_cast<float4*>(out_truth + base) =
        *reinterpret_cast<const float4*>(truth + base);
    *reinterpret_cast<float4*>(out_truth + base + 4) =
        *reinterpret_cast<const float4*>(truth + base + 4);

    float4 xa = *reinterpret_cast<const float4*>(x + base);
    float4 xb = *reinterpret_cast<const float4*>(x + base + 4);
    float4 wa = *reinterpret_cast<const float4*>(W + base);
    float4 wb = *reinterpret_cast<const float4*>(W + base + 4);
    float xv[8] = {xa.x, xa.y, xa.z, xa.w, xb.x, xb.y, xb.z, xb.w};
    float Wv[8] = {wa.x, wa.y, wa.z, wa.w, wb.x, wb.y, wb.z, wb.w};

    const unsigned i = (unsigned)(b * NN + n);
    const float P = Pm[i];

    float ua = jax_u01(KA0, KA1, i);
    float ub = jax_u01(KB0, KB1, i);
    float ea = expf(-logf(-logf(ua)));
    float eb = expf(-logf(-logf(ub)));
    float no = P * ea / 0.7f;
    float de = no + (1.0f - P) * eb / 0.7f;
    float probs = no / de;

    float g[8];
#pragma unroll
    for (int c = 0; c < 8; c++) {
        float u = jax_u01(KG0, KG1, i * 8u + (unsigned)c);
        g[c] = -logf(-logf(u));
    }

    int curr = 0;
    {
        float m = xv[0];
#pragma unroll
        for (int c = 1; c < 8; c++)
            if (xv[c] > m) { m = xv[c]; curr = c; }
    }

    if (n == 2) {
        float xt_par[8];
        gs8(Wv, g, xt_par);
        int am = 0;
        float m = probs * xt_par[0] + (1.0f - probs) * xv[0];
#pragma unroll
        for (int c = 1; c < 8; c++) {
            float v = probs * xt_par[c] + (1.0f - probs) * xv[c];
            if (v > m) { m = v; am = c; }
        }
        int diff = am - curr;
        sh_cst  = (diff == 0) ? 1.0f : 0.0f;
        sh_incr = (diff >  0) ? 1.0f : 0.0f;
    }
    __syncthreads();
    const float cst = sh_cst;
    const float incr = sh_incr;

    float l[8];
    if (n == 0 || n == 5 || n == 10) {
#pragma unroll
        for (int c = 0; c < 8; c++) l[c] = Wv[c] + ((c < curr) ? -100.0f : 1.0f);
    } else if (n == 7) {
        const int thr = curr + 1;
        const bool inc = (incr > 0.5f);
#pragma unroll
        for (int c = 0; c < 8; c++)
            l[c] = Wv[c] + ((inc && c < thr) ? -100.0f : 1.0f);
    } else {
#pragma unroll
        for (int c = 0; c < 8; c++) l[c] = Wv[c];
    }

    float xt[8];
    gs8(l, g, xt);

    float p2 = probs;
    if (n == 7) {
        float pc = probs * (1.0f - cst);
        pc = pc + incr;
        p2 = fminf(fmaxf(pc, 0.0f), 1.0f);
    }

    float4 oa, ob;
    float* op = &oa.x;
#pragma unroll
    for (int c = 0; c < 4; c++) op[c] = p2 * xt[c] + (1.0f - p2) * xv[c];
    op = &ob.x;
#pragma unroll
    for (int c = 0; c < 4; c++) op[c] = p2 * xt[c + 4] + (1.0f - p2) * xv[c + 4];
    *reinterpret_cast<float4*>(xcf + base) = oa;
    *reinterpret_cast<float4*>(xcf + base + 4) = ob;
}

// ---------------------------------------------------------------------------
// Launch
// ---------------------------------------------------------------------------
extern "C" void kernel_launch(void* const* d_in, const int* in_sizes, int n_in,
                              void* d_out, int out_size) {
    const float* x     = (const float*)d_in[0];
    const float* truth = (const float*)d_in[1];
    const float* sw1   = (const float*)d_in[2];
    const float* sb1   = (const float*)d_in[3];
    const float* sw2   = (const float*)d_in[4];
    const float* sb2   = (const float*)d_in[5];
    const float* pw1   = (const float*)d_in[6];
    const float* pb1   = (const float*)d_in[7];
    const float* pw2   = (const float*)d_in[8];
    const float* pb2   = (const float*)d_in[9];
    const float* pw3   = (const float*)d_in[10];
    const float* pb3   = (const float*)d_in[11];
    const float* pw4   = (const float*)d_in[12];
    const float* pb4   = (const float*)d_in[13];

    float* out       = (float*)d_out;
    float* out_truth = out;
    float* out_xcf   = out + BD_ELEMS;
    float* out_P     = out + 2 * (size_t)BD_ELEMS;
    float* out_W     = out + 2 * (size_t)BD_ELEMS + BN_ELEMS;

    __half *a_hi, *a_lo, *b_hi, *b_lo, *xh, *wt_hi, *wt_lo;
    float *s1, *bias_l1;
    cudaGetSymbolAddress((void**)&a_hi, g_a_hi);
    cudaGetSymbolAddress((void**)&a_lo, g_a_lo);
    cudaGetSymbolAddress((void**)&b_hi, g_b_hi);
    cudaGetSymbolAddress((void**)&b_lo, g_b_lo);
    cudaGetSymbolAddress((void**)&xh,   g_xh);
    cudaGetSymbolAddress((void**)&s1,   g_s1);
    cudaGetSymbolAddress((void**)&wt_hi, g_wt_hi);
    cudaGetSymbolAddress((void**)&wt_lo, g_wt_lo);
    cudaGetSymbolAddress((void**)&bias_l1, g_bias_l1);

    cudaFuncSetAttribute(gemm_h<true, 2>,
                         cudaFuncAttributeMaxDynamicSharedMemorySize, GEMM_SMEM);
    cudaFuncSetAttribute(gemm_h<false, 0>,
                         cudaFuncAttributeMaxDynamicSharedMemorySize, GEMM_SMEM);
    cudaFuncSetAttribute(gemm_h<false, 1>,
                         cudaFuncAttributeMaxDynamicSharedMemorySize, GEMM_SMEM);
    cudaFuncSetAttribute(gemm2_head_kernel,
                         cudaFuncAttributeMaxDynamicSharedMemorySize, GEMM_SMEM);

    // Prep: x->fp16 + bias concat + all weight splits, one launch
    prep_kernel<<<5376, 256>>>(x, xh, pb1, sb1, bias_l1,
                               pw1, sw1, pw2, pw3, pw4, wt_hi, wt_lo);

    // L1 (pw1 + sw1 merged, AEX, mixed epilogue)
    gemm_h<true, 2><<<dim3((HP + HS) / 128, BB / 128), 256, GEMM_SMEM>>>(
        xh, nullptr, wt_hi, wt_lo, bias_l1, a_hi, a_lo, s1, DD, HP);

    // gemm2 FUSED with selector head (head fills tail waves)
    gemm2_head_kernel<<<dim3(HP / 128, BB / 128 + 32), 256, GEMM_SMEM>>>(
        a_hi, a_lo, wt_hi + OF_PW2, wt_lo + OF_PW2, pb2, b_hi, b_lo,
        s1, sw2, sb2, out_P);

    // gemm3, gemm4
    gemm_h<false, 0><<<dim3(HP / 128, BB / 128), 256, GEMM_SMEM>>>(
        b_hi, b_lo, wt_hi + OF_PW3, wt_lo + OF_PW3, pb3, a_hi, a_lo, nullptr,
        HP, HP);
    gemm_h<false, 1><<<dim3(DD / 128, BB / 128), 256, GEMM_SMEM>>>(
        a_hi, a_lo, wt_hi + OF_PW4, wt_lo + OF_PW4, pb4, nullptr, nullptr,
        out_W, HP, DD);

    // Fused tail (+ truth passthrough)
    finalize_kernel<<<BB, NN>>>(x, out_P, out_W, truth, out_truth, out_xcf);
}

// round 12
// speedup vs baseline: 2.9599x; 1.0025x over previous
#include <cuda_runtime.h>
#include <cuda_fp16.h>
#include <cstdint>
#include <math.h>

// ---------------------------------------------------------------------------
// Problem constants
// ---------------------------------------------------------------------------
#define BB 8192
#define NN 64
#define CC 8
#define DD (NN * CC)        // 512
#define HP 1024
#define HS 512
#define BD_ELEMS (BB * DD)  // 4,194,304
#define BN_ELEMS (BB * NN)  // 524,288

// ---------------------------------------------------------------------------
// Scratch (allocation-free: __device__ globals)
// ---------------------------------------------------------------------------
__device__ __half g_a_hi[BB * HP];
__device__ __half g_a_lo[BB * HP];
__device__ __half g_b_hi[BB * HP];
__device__ __half g_b_lo[BB * HP];
__device__ __half g_xh[BB * DD];
__device__ float  g_s1[BB * HS];
__device__ float  g_bias_l1[HP + HS];   // pb1 ++ sb1

// Transposed + split weights, packed (Bt[n][k] layout), fp16 hi/lo.
#define OF_PW1 0
#define OF_SW1 524288
#define OF_PW2 786432
#define OF_PW3 1835008
#define OF_PW4 2883584
#define WT_TOTAL 3407872
__device__ __half g_wt_hi[WT_TOTAL];
__device__ __half g_wt_lo[WT_TOTAL];

// ---------------------------------------------------------------------------
// Threefry-2x32-20 (JAX)
// ---------------------------------------------------------------------------
struct TFK { unsigned a, b; };

__host__ __device__ constexpr unsigned tf_rotl(unsigned v, int r) {
    return (v << r) | (v >> (32 - r));
}

__host__ __device__ constexpr TFK tf2x32(unsigned k0, unsigned k1,
                                         unsigned x0, unsigned x1) {
    unsigned k2 = k0 ^ k1 ^ 0x1BD11BDAu;
    x0 += k0; x1 += k1;
    x0 += x1; x1 = tf_rotl(x1, 13); x1 ^= x0;
    x0 += x1; x1 = tf_rotl(x1, 15); x1 ^= x0;
    x0 += x1; x1 = tf_rotl(x1, 26); x1 ^= x0;
    x0 += x1; x1 = tf_rotl(x1,  6); x1 ^= x0;
    x0 += k1; x1 += k2 + 1u;
    x0 += x1; x1 = tf_rotl(x1, 17); x1 ^= x0;
    x0 += x1; x1 = tf_rotl(x1, 29); x1 ^= x0;
    x0 += x1; x1 = tf_rotl(x1, 16); x1 ^= x0;
    x0 += x1; x1 = tf_rotl(x1, 24); x1 ^= x0;
    x0 += k2; x1 += k0 + 2u;
    x0 += x1; x1 = tf_rotl(x1, 13); x1 ^= x0;
    x0 += x1; x1 = tf_rotl(x1, 15); x1 ^= x0;
    x0 += x1; x1 = tf_rotl(x1, 26); x1 ^= x0;
    x0 += x1; x1 = tf_rotl(x1,  6); x1 ^= x0;
    x0 += k0; x1 += k1 + 3u;
    x0 += x1; x1 = tf_rotl(x1, 17); x1 ^= x0;
    x0 += x1; x1 = tf_rotl(x1, 29); x1 ^= x0;
    x0 += x1; x1 = tf_rotl(x1, 16); x1 ^= x0;
    x0 += x1; x1 = tf_rotl(x1, 24); x1 ^= x0;
    x0 += k1; x1 += k2 + 4u;
    x0 += x1; x1 = tf_rotl(x1, 13); x1 ^= x0;
    x0 += x1; x1 = tf_rotl(x1, 15); x1 ^= x0;
    x0 += x1; x1 = tf_rotl(x1, 26); x1 ^= x0;
    x0 += x1; x1 = tf_rotl(x1,  6); x1 ^= x0;
    x0 += k2; x1 += k0 + 5u;
    return TFK{x0, x1};
}

constexpr unsigned KA0 = tf2x32(0u, 42u, 0u, 0u).a;
constexpr unsigned KA1 = tf2x32(0u, 42u, 0u, 0u).b;
constexpr unsigned KB0 = tf2x32(0u, 42u, 0u, 1u).a;
constexpr unsigned KB1 = tf2x32(0u, 42u, 0u, 1u).b;
constexpr unsigned KG0 = tf2x32(0u, 42u, 0u, 2u).a;
constexpr unsigned KG1 = tf2x32(0u, 42u, 0u, 2u).b;

__device__ __forceinline__ float jax_u01(unsigned k0, unsigned k1, unsigned idx) {
    TFK r = tf2x32(k0, k1, 0u, idx);
    unsigned bits = r.a ^ r.b;
    float f = __uint_as_float((bits >> 9) | 0x3f800000u) - 1.0f;
    f = f + 1e-8f;
    return fmaxf(1e-8f, f);
}

// ---------------------------------------------------------------------------
// Helpers
// ---------------------------------------------------------------------------
__device__ __forceinline__ uint32_t smem_u32(const void* p) {
    uint32_t a;
    asm("{ .reg .u64 t; cvta.to.shared.u64 t, %1; cvt.u32.u64 %0, t; }"
        : "=r"(a) : "l"(p));
    return a;
}

#define CP16(dst_u32, src_ptr) \
    asm volatile("cp.async.cg.shared.global [%0], [%1], 16;" \
                 :: "r"(dst_u32), "l"(src_ptr) : "memory")
#define CP_COMMIT() asm volatile("cp.async.commit_group;" ::: "memory")
#define CP_WAIT(n)  asm volatile("cp.async.wait_group %0;" :: "n"(n) : "memory")

__device__ __forceinline__ void mma16(float* d, const uint32_t* a,
                                      const uint32_t* b) {
    asm volatile(
        "mma.sync.aligned.m16n8k16.row.col.f32.f16.f16.f32 "
        "{%0,%1,%2,%3}, {%4,%5,%6,%7}, {%8,%9}, {%0,%1,%2,%3};"
        : "+f"(d[0]), "+f"(d[1]), "+f"(d[2]), "+f"(d[3])
        : "r"(a[0]), "r"(a[1]), "r"(a[2]), "r"(a[3]), "r"(b[0]), "r"(b[1]));
}

__device__ __forceinline__ void ldsm_x4(uint32_t* r, uint32_t addr) {
    asm volatile(
        "ldmatrix.sync.aligned.m8n8.x4.shared.b16 {%0,%1,%2,%3}, [%4];"
        : "=r"(r[0]), "=r"(r[1]), "=r"(r[2]), "=r"(r[3]) : "r"(addr));
}

__device__ __forceinline__ void split_h(float y, __half& h, __half& l) {
    h = __float2half_rn(y);
    l = __float2half_rn(y - __half2float(h));
}

// ---------------------------------------------------------------------------
// fp16-split GEMM mainloop. BM=128, BN=128, BK=32, 256 thr, warps 2x4.
// Packed 64B rows + XOR swizzle, 3 stages, ONE barrier per chunk:
//   wait(chunk c) ; barrier ; issue(c+2) ; compute(c)
// issue(c+2) overwrites the stage last read in compute(c-1), which every
// thread finished before this iteration's barrier -> safe without a second
// barrier.
// ---------------------------------------------------------------------------
#define TILE_B 8192                     // 128 rows x 64 bytes
#define T_AH 0
#define T_AL TILE_B
#define T_BH (2 * TILE_B)
#define T_BL (3 * TILE_B)
#define STAGE_B (4 * TILE_B)            // 32768 bytes / stage
#define GEMM_SMEM (3 * STAGE_B)         // 98304 bytes

template <bool AEX>
__device__ __forceinline__ void issue_chunk_h(
    uint32_t smb, int c,
    const __half* __restrict__ A_hi, const __half* __restrict__ A_lo,
    const __half* __restrict__ B_hi, const __half* __restrict__ B_lo,
    int K, int bm0, int bn0, int tid) {
    const int k0 = c * 32;
    const uint32_t sb = smb + (uint32_t)((c % 3) * STAGE_B);
#pragma unroll
    for (int i = 0; i < 2; i++) {
        const int f = tid + i * 256;
        const int row = f >> 2;
        const int q = f & 3;
        const uint32_t doff =
            (uint32_t)(row * 64 + ((q ^ ((row >> 1) & 3)) * 16));
        CP16(sb + T_AH + doff, A_hi + (size_t)(bm0 + row) * K + k0 + q * 8);
        if (!AEX)
            CP16(sb + T_AL + doff,
                 A_lo + (size_t)(bm0 + row) * K + k0 + q * 8);
        CP16(sb + T_BH + doff, B_hi + (size_t)(bn0 + row) * K + k0 + q * 8);
        CP16(sb + T_BL + doff, B_lo + (size_t)(bn0 + row) * K + k0 + q * 8);
    }
    CP_COMMIT();
}

template <bool AEX>
__device__ __forceinline__ void gemm_mainloop(
    uint32_t smb, const __half* __restrict__ A_hi,
    const __half* __restrict__ A_lo, const __half* __restrict__ Bt_hi,
    const __half* __restrict__ Bt_lo, int K, int bm0, int bn0, int tid,
    float acc[4][4][4]) {
    const int l = tid & 31;
    const int warp = tid >> 5;
    const int wm = warp >> 2;
    const int wn = warp & 3;
    const int NC = K >> 5;

    issue_chunk_h<AEX>(smb, 0, A_hi, A_lo, Bt_hi, Bt_lo, K, bm0, bn0, tid);
    if (NC > 1)
        issue_chunk_h<AEX>(smb, 1, A_hi, A_lo, Bt_hi, Bt_lo, K, bm0, bn0, tid);

    // Lane-level fragment addressing (swizzle term is lane-only: (l>>1)&3)
    const int swz = (l >> 1) & 3;
    const uint32_t arow = (uint32_t)((wm * 64 + (l & 15)) * 64);
    const int acb = l >> 4;            // 0 or 1
    const uint32_t brow =
        (uint32_t)((wn * 32 + ((l >> 4) & 1) * 8 + (l & 7)) * 64);
    const int bcb = (l >> 3) & 1;

    for (int c = 0; c < NC; c++) {
        if (c + 1 < NC) {
            CP_WAIT(1);               // pending = {c, c+1}; chunk c complete
        } else {
            CP_WAIT(0);
        }
        __syncthreads();
        if (c + 2 < NC)
            issue_chunk_h<AEX>(smb, c + 2, A_hi, A_lo, Bt_hi, Bt_lo, K, bm0,
                               bn0, tid);

        const uint32_t stage = smb + (uint32_t)((c % 3) * STAGE_B);
        const uint32_t baseAh = stage + T_AH + arow;
        const uint32_t baseAl = stage + T_AL + arow;
        const uint32_t baseBh = stage + T_BH + brow;
        const uint32_t baseBl = stage + T_BL + brow;

#pragma unroll
        for (int ks = 0; ks < 2; ks++) {
            const uint32_t aco = (uint32_t)(((ks * 2 + acb) ^ swz) * 16);
            const uint32_t bco = (uint32_t)(((ks * 2 + bcb) ^ swz) * 16);
            uint32_t bh[4][2], bl[4][2];
#pragma unroll
            for (int j = 0; j < 2; j++) {
                uint32_t t[4];
                ldsm_x4(t, baseBh + (uint32_t)(j * 16 * 64) + bco);
                bh[2 * j][0] = t[0]; bh[2 * j][1] = t[1];
                bh[2 * j + 1][0] = t[2]; bh[2 * j + 1][1] = t[3];
                ldsm_x4(t, baseBl + (uint32_t)(j * 16 * 64) + bco);
                bl[2 * j][0] = t[0]; bl[2 * j][1] = t[1];
                bl[2 * j + 1][0] = t[2]; bl[2 * j + 1][1] = t[3];
            }
#pragma unroll
            for (int mf = 0; mf < 4; mf++) {
                uint32_t ah[4], al[4];
                ldsm_x4(ah, baseAh + (uint32_t)(mf * 16 * 64) + aco);
                if (!AEX)
                    ldsm_x4(al, baseAl + (uint32_t)(mf * 16 * 64) + aco);
#pragma unroll
                for (int nf = 0; nf < 4; nf++) {
                    mma16(acc[mf][nf], ah, bh[nf]);
                    mma16(acc[mf][nf], ah, bl[nf]);
                    if (!AEX) mma16(acc[mf][nf], al, bh[nf]);
                }
            }
        }
    }
    __syncthreads();   // protect smem before any epilogue staging/reuse
}

// Epilogue for relu+split / fp32 outputs
template <int OMODE>   // 0 = relu+split, 1 = fp32, 2 = mixed L1
__device__ __forceinline__ void gemm_epilogue(
    float acc[4][4][4], const float* __restrict__ bias,
    __half* __restrict__ O_hi, __half* __restrict__ O_lo,
    float* __restrict__ Of, int Nout, int bm0, int bn0, int tid) {
    const int l = tid & 31;
    const int warp = tid >> 5;
    const int wm = warp >> 2;
    const int wn = warp & 3;
    const int rA = l >> 2;
    const int cK = l & 3;
    const bool f32_region = (OMODE == 1) || (OMODE == 2 && bn0 >= HP);
    const int ow = (OMODE == 2) ? (f32_region ? HS : HP) : Nout;
    const int cbase = (OMODE == 2 && f32_region) ? (bn0 - HP) : bn0;

#pragma unroll
    for (int nf = 0; nf < 4; nf++) {
        const int gcol = bn0 + wn * 32 + nf * 8 + 2 * cK;
        const int col = cbase + wn * 32 + nf * 8 + 2 * cK;
        const float2 bv = *reinterpret_cast<const float2*>(bias + gcol);
#pragma unroll
        for (int mf = 0; mf < 4; mf++) {
            const int ra = bm0 + wm * 64 + mf * 16 + rA;
            float y[4];
            y[0] = acc[mf][nf][0] + bv.x;
            y[1] = acc[mf][nf][1] + bv.y;
            y[2] = acc[mf][nf][2] + bv.x;
            y[3] = acc[mf][nf][3] + bv.y;
            if (OMODE != 1) {
#pragma unroll
                for (int r = 0; r < 4; r++) y[r] = fmaxf(y[r], 0.0f);
            }
            if (!f32_region && OMODE != 1) {
                __half h[4], lo[4];
#pragma unroll
                for (int r = 0; r < 4; r++) split_h(y[r], h[r], lo[r]);
                *reinterpret_cast<__half2*>(O_hi + (size_t)ra * ow + col) =
                    __halves2half2(h[0], h[1]);
                *reinterpret_cast<__half2*>(O_hi + (size_t)(ra + 8) * ow + col) =
                    __halves2half2(h[2], h[3]);
                *reinterpret_cast<__half2*>(O_lo + (size_t)ra * ow + col) =
                    __halves2half2(lo[0], lo[1]);
                *reinterpret_cast<__half2*>(O_lo + (size_t)(ra + 8) * ow + col) =
                    __halves2half2(lo[2], lo[3]);
            } else {
                *reinterpret_cast<float2*>(Of + (size_t)ra * ow + col) =
                    make_float2(y[0], y[1]);
                *reinterpret_cast<float2*>(Of + (size_t)(ra + 8) * ow + col) =
                    make_float2(y[2], y[3]);
            }
        }
    }
}

// Plain GEMM kernels (L1 mixed, L3 split, L4 fp32)
template <bool AEX, int OMODE>
__global__ void __launch_bounds__(256, 2)
gemm_h(const __half* __restrict__ A_hi, const __half* __restrict__ A_lo,
       const __half* __restrict__ Bt_hi, const __half* __restrict__ Bt_lo,
       const float* __restrict__ bias,
       __half* __restrict__ O_hi, __half* __restrict__ O_lo,
       float* __restrict__ Of,
       int K, int Nout) {
    extern __shared__ __half smh[];
    const uint32_t smb = smem_u32(smh);
    const int tid = threadIdx.x;
    const int bm0 = blockIdx.y * 128;
    const int bn0 = blockIdx.x * 128;

    float acc[4][4][4];
#pragma unroll
    for (int mf = 0; mf < 4; mf++)
#pragma unroll
        for (int nf = 0; nf < 4; nf++)
#pragma unroll
            for (int r = 0; r < 4; r++) acc[mf][nf][r] = 0.0f;

    gemm_mainloop<AEX>(smb, A_hi, A_lo, Bt_hi, Bt_lo, K, bm0, bn0, tid, acc);
    gemm_epilogue<OMODE>(acc, bias, O_hi, O_lo, Of, Nout, bm0, bn0, tid);
}

// ---------------------------------------------------------------------------
// Selector head body (3-stage cp.async pipeline) — runs inside fused kernel.
// ---------------------------------------------------------------------------
__device__ __forceinline__ void sel_head_body(
    char* smc, int bm0, int tid,
    const float* __restrict__ A, const float* __restrict__ B,
    const float* __restrict__ bias, float* __restrict__ C) {
    float (*As)[32][20] = reinterpret_cast<float (*)[32][20]>(smc);
    float (*Bs)[16][64] = reinterpret_cast<float (*)[16][64]>(smc + 3 * 32 * 20 * 4);

    const int tx = tid & 15;
    const int ty = tid >> 4;
    const int K = HS, N = NN;
    const int NC = K / 16;

    const uint32_t asb = smem_u32(As);
    const uint32_t bsb = smem_u32(Bs);

    auto issue = [&](int c) {
        const int s = c % 3;
        const int k0 = c * 16;
        if (tid < 128) {
            const int row = tid >> 2;
            const int q = tid & 3;
            CP16(asb + (uint32_t)(((s * 32 + row) * 20 + q * 4) * 4),
                 A + (size_t)(bm0 + row) * K + k0 + q * 4);
        }
        {
            const int kr = tid >> 4;
            const int q = tid & 15;
            CP16(bsb + (uint32_t)(((s * 16 + kr) * 64 + q * 4) * 4),
                 B + (size_t)(k0 + kr) * N + q * 4);
        }
        CP_COMMIT();
    };

    float acc[2][4] = {{0.f, 0.f, 0.f, 0.f}, {0.f, 0.f, 0.f, 0.f}};

    issue(0);
    issue(1);

    for (int c = 0; c < NC; c++) {
        const int s = c % 3;
        if (c + 1 < NC) CP_WAIT(1); else CP_WAIT(0);
        __syncthreads();
        if (c + 2 < NC) issue(c + 2);

#pragma unroll
        for (int k = 0; k < 16; k++) {
            float a0 = As[s][ty * 2][k];
            float a1 = As[s][ty * 2 + 1][k];
            float4 bv = *reinterpret_cast<const float4*>(&Bs[s][k][tx * 4]);
            acc[0][0] = fmaf(a0, bv.x, acc[0][0]);
            acc[0][1] = fmaf(a0, bv.y, acc[0][1]);
            acc[0][2] = fmaf(a0, bv.z, acc[0][2]);
            acc[0][3] = fmaf(a0, bv.w, acc[0][3]);
            acc[1][0] = fmaf(a1, bv.x, acc[1][0]);
            acc[1][1] = fmaf(a1, bv.y, acc[1][1]);
            acc[1][2] = fmaf(a1, bv.z, acc[1][2]);
            acc[1][3] = fmaf(a1, bv.w, acc[1][3]);
        }
    }

    float4 bvec = *reinterpret_cast<const float4*>(bias + tx * 4);
    float bias4[4] = {bvec.x, bvec.y, bvec.z, bvec.w};
#pragma unroll
    for (int i = 0; i < 2; i++) {
        float4 v;
        float* vp = &v.x;
#pragma unroll
        for (int j = 0; j < 4; j++) {
            float cv = acc[i][j] + bias4[j];
            vp[j] = 1.0f / (1.0f + expf(-cv));
        }
        *reinterpret_cast<float4*>(
            C + (size_t)(bm0 + ty * 2 + i) * N + tx * 4) = v;
    }
}

// ---------------------------------------------------------------------------
// FUSED gemm2 + selector head. grid = (8, 64 + 32)
// ---------------------------------------------------------------------------
__global__ void __launch_bounds__(256, 2)
gemm2_head_kernel(const __half* __restrict__ A_hi,
                  const __half* __restrict__ A_lo,
                  const __half* __restrict__ Bt_hi,
                  const __half* __restrict__ Bt_lo,
                  const float* __restrict__ bias,
                  __half* __restrict__ O_hi, __half* __restrict__ O_lo,
                  const float* __restrict__ s1, const float* __restrict__ sw2,
                  const float* __restrict__ sb2, float* __restrict__ P) {
    extern __shared__ char smc[];
    const int tid = threadIdx.x;

    if (blockIdx.y >= 64) {
        const int hb = (blockIdx.y - 64) * 8 + blockIdx.x;   // 0..255
        sel_head_body(smc, hb * 32, tid, s1, sw2, sb2, P);
        return;
    }

    const uint32_t smb = smem_u32(smc);
    const int bm0 = blockIdx.y * 128;
    const int bn0 = blockIdx.x * 128;

    float acc[4][4][4];
#pragma unroll
    for (int mf = 0; mf < 4; mf++)
#pragma unroll
        for (int nf = 0; nf < 4; nf++)
#pragma unroll
            for (int r = 0; r < 4; r++) acc[mf][nf][r] = 0.0f;

    gemm_mainloop<false>(smb, A_hi, A_lo, Bt_hi, Bt_lo, HP, bm0, bn0, tid, acc);
    gemm_epilogue<0>(acc, bias, O_hi, O_lo, nullptr, HP, bm0, bn0, tid);
}

// ---------------------------------------------------------------------------
// MERGED prep kernel
// ---------------------------------------------------------------------------
__global__ void __launch_bounds__(256)
prep_kernel(const float* __restrict__ x, __half* __restrict__ xh,
            const float* __restrict__ pb1, const float* __restrict__ sb1,
            float* __restrict__ bias_l1,
            const float* __restrict__ pw1, const float* __restrict__ sw1,
            const float* __restrict__ pw2, const float* __restrict__ pw3,
            const float* __restrict__ pw4,
            __half* __restrict__ bt_hi, __half* __restrict__ bt_lo) {
    if (blockIdx.x < 2048) {
        const int t = blockIdx.x * 256 + threadIdx.x;
        const float4 a = *reinterpret_cast<const float4*>(x + (size_t)t * 8);
        const float4 b = *reinterpret_cast<const float4*>(x + (size_t)t * 8 + 4);
        __half2 o[4];
        o[0] = __halves2half2(__float2half_rn(a.x), __float2half_rn(a.y));
        o[1] = __halves2half2(__float2half_rn(a.z), __float2half_rn(a.w));
        o[2] = __halves2half2(__float2half_rn(b.x), __float2half_rn(b.y));
        o[3] = __halves2half2(__float2half_rn(b.z), __float2half_rn(b.w));
        *reinterpret_cast<uint4*>(xh + (size_t)t * 8) =
            *reinterpret_cast<uint4*>(o);
        if (t < HP + HS)
            bias_l1[t] = (t < HP) ? pb1[t] : sb1[t - HP];
        return;
    }

    const int b = blockIdx.x - 2048;
    const float* W;
    int off, K, N, lb;
    if (b < 512)        { W = pw1; off = OF_PW1; K = 512;  N = 1024; lb = b; }
    else if (b < 768)   { W = sw1; off = OF_SW1; K = 512;  N = 512;  lb = b - 512; }
    else if (b < 1792)  { W = pw2; off = OF_PW2; K = 1024; N = 1024; lb = b - 768; }
    else if (b < 2816)  { W = pw3; off = OF_PW3; K = 1024; N = 1024; lb = b - 1792; }
    else                { W = pw4; off = OF_PW4; K = 1024; N = 512;  lb = b - 2816; }
    const int kt = K >> 5;
    const int kb = (lb % kt) * 32;
    const int nb = (lb / kt) * 32;

    __shared__ float t[32][33];
    const int tx = threadIdx.x & 31;
    const int ty = threadIdx.x >> 5;
#pragma unroll
    for (int r = ty; r < 32; r += 8)
        t[r][tx] = W[(size_t)(kb + r) * N + nb + tx];
    __syncthreads();
#pragma unroll
    for (int r = ty; r < 32; r += 8) {
        float wv = t[tx][r];
        __half h, lo;
        split_h(wv, h, lo);
        size_t o = (size_t)off + (size_t)(nb + r) * K + kb + tx;
        bt_hi[o] = h;
        bt_lo[o] = lo;
    }
}

// ---------------------------------------------------------------------------
// Fused elementwise tail (+ truth_x passthrough)
// ---------------------------------------------------------------------------
__device__ __forceinline__ void gs8(const float* l, const float* g, float* xt) {
    float m = l[0];
#pragma unroll
    for (int c = 1; c < 8; c++) m = fmaxf(m, l[c]);
    float e[8], s = 0.0f;
#pragma unroll
    for (int c = 0; c < 8; c++) { e[c] = expf(l[c] - m); s += e[c]; }
    float t[8];
#pragma unroll
    for (int c = 0; c < 8; c++) {
        float pr = e[c] / s;
        pr = 0.9f * pr + 0.0125f;
        t[c] = (logf(pr) + g[c]) / 0.7f;
    }
    float m2 = t[0];
#pragma unroll
    for (int c = 1; c < 8; c++) m2 = fmaxf(m2, t[c]);
    float e2[8], s2 = 0.0f;
#pragma unroll
    for (int c = 0; c < 8; c++) { e2[c] = expf(t[c] - m2); s2 += e2[c]; }
#pragma unroll
    for (int c = 0; c < 8; c++) xt[c] = e2[c] / s2;
}

__global__ void finalize_kernel(const float* __restrict__ x,
                                const float* __restrict__ Pm,
                                const float* __restrict__ W,
                                const float* __restrict__ truth,
                                float* __restrict__ out_truth,
                                float* __restrict__ xcf) {
    const int b = blockIdx.x;
    const int n = threadIdx.x;
    __shared__ float sh_cst, sh_incr;

    const size_t base = (size_t)b * DD + n * CC;

    *reinterpret_cast<float4*>(out_truth + base) =
        *reinterpret_cast<const float4*>(truth + base);
    *reinterpret_cast<float4*>(out_truth + base + 4) =
        *reinterpret_cast<const float4*>(truth + base + 4);

    float4 xa = *reinterpret_cast<const float4*>(x + base);
    float4 xb = *reinterpret_cast<const float4*>(x + base + 4);
    float4 wa = *reinterpret_cast<const float4*>(W + base);
    float4 wb = *reinterpret_cast<const float4*>(W + base + 4);
    float xv[8] = {xa.x, xa.y, xa.z, xa.w, xb.x, xb.y, xb.z, xb.w};
    float Wv[8] = {wa.x, wa.y, wa.z, wa.w, wb.x, wb.y, wb.z, wb.w};

    const unsigned i = (unsigned)(b * NN + n);
    const float P = Pm[i];

    float ua = jax_u01(KA0, KA1, i);
    float ub = jax_u01(KB0, KB1, i);
    float ea = expf(-logf(-logf(ua)));
    float eb = expf(-logf(-logf(ub)));
    float no = P * ea / 0.7f;
    float de = no + (1.0f - P) * eb / 0.7f;
    float probs = no / de;

    float g[8];
#pragma unroll
    for (int c = 0; c < 8; c++) {
        float u = jax_u01(KG0, KG1, i * 8u + (unsigned)c);
        g[c] = -logf(-logf(u));
    }

    int curr = 0;
    {
        float m = xv[0];
#pragma unroll
        for (int c = 1; c < 8; c++)
            if (xv[c] > m) { m = xv[c]; curr = c; }
    }

    if (n == 2) {
        float xt_par[8];
        gs8(Wv, g, xt_par);
        int am = 0;
        float m = probs * xt_par[0] + (1.0f - probs) * xv[0];
#pragma unroll
        for (int c = 1; c < 8; c++) {
            float v = probs * xt_par[c] + (1.0f - probs) * xv[c];
            if (v > m) { m = v; am = c; }
        }
        int diff = am - curr;
        sh_cst  = (diff == 0) ? 1.0f : 0.0f;
        sh_incr = (diff >  0) ? 1.0f : 0.0f;
    }
    __syncthreads();
    const float cst = sh_cst;
    const float incr = sh_incr;

    float l[8];
    if (n == 0 || n == 5 || n == 10) {
#pragma unroll
        for (int c = 0; c < 8; c++) l[c] = Wv[c] + ((c < curr) ? -100.0f : 1.0f);
    } else if (n == 7) {
        const int thr = curr + 1;
        const bool inc = (incr > 0.5f);
#pragma unroll
        for (int c = 0; c < 8; c++)
            l[c] = Wv[c] + ((inc && c < thr) ? -100.0f : 1.0f);
    } else {
#pragma unroll
        for (int c = 0; c < 8; c++) l[c] = Wv[c];
    }

    float xt[8];
    gs8(l, g, xt);

    float p2 = probs;
    if (n == 7) {
        float pc = probs * (1.0f - cst);
        pc = pc + incr;
        p2 = fminf(fmaxf(pc, 0.0f), 1.0f);
    }

    float4 oa, ob;
    float* op = &oa.x;
#pragma unroll
    for (int c = 0; c < 4; c++) op[c] = p2 * xt[c] + (1.0f - p2) * xv[c];
    op = &ob.x;
#pragma unroll
    for (int c = 0; c < 4; c++) op[c] = p2 * xt[c + 4] + (1.0f - p2) * xv[c + 4];
    *reinterpret_cast<float4*>(xcf + base) = oa;
    *reinterpret_cast<float4*>(xcf + base + 4) = ob;
}

// ---------------------------------------------------------------------------
// Launch
// ---------------------------------------------------------------------------
extern "C" void kernel_launch(void* const* d_in, const int* in_sizes, int n_in,
                              void* d_out, int out_size) {
    const float* x     = (const float*)d_in[0];
    const float* truth = (const float*)d_in[1];
    const float* sw1   = (const float*)d_in[2];
    const float* sb1   = (const float*)d_in[3];
    const float* sw2   = (const float*)d_in[4];
    const float* sb2   = (const float*)d_in[5];
    const float* pw1   = (const float*)d_in[6];
    const float* pb1   = (const float*)d_in[7];
    const float* pw2   = (const float*)d_in[8];
    const float* pb2   = (const float*)d_in[9];
    const float* pw3   = (const float*)d_in[10];
    const float* pb3   = (const float*)d_in[11];
    const float* pw4   = (const float*)d_in[12];
    const float* pb4   = (const float*)d_in[13];

    float* out       = (float*)d_out;
    float* out_truth = out;
    float* out_xcf   = out + BD_ELEMS;
    float* out_P     = out + 2 * (size_t)BD_ELEMS;
    float* out_W     = out + 2 * (size_t)BD_ELEMS + BN_ELEMS;

    __half *a_hi, *a_lo, *b_hi, *b_lo, *xh, *wt_hi, *wt_lo;
    float *s1, *bias_l1;
    cudaGetSymbolAddress((void**)&a_hi, g_a_hi);
    cudaGetSymbolAddress((void**)&a_lo, g_a_lo);
    cudaGetSymbolAddress((void**)&b_hi, g_b_hi);
    cudaGetSymbolAddress((void**)&b_lo, g_b_lo);
    cudaGetSymbolAddress((void**)&xh,   g_xh);
    cudaGetSymbolAddress((void**)&s1,   g_s1);
    cudaGetSymbolAddress((void**)&wt_hi, g_wt_hi);
    cudaGetSymbolAddress((void**)&wt_lo, g_wt_lo);
    cudaGetSymbolAddress((void**)&bias_l1, g_bias_l1);

    cudaFuncSetAttribute(gemm_h<true, 2>,
                         cudaFuncAttributeMaxDynamicSharedMemorySize, GEMM_SMEM);
    cudaFuncSetAttribute(gemm_h<false, 0>,
                         cudaFuncAttributeMaxDynamicSharedMemorySize, GEMM_SMEM);
    cudaFuncSetAttribute(gemm_h<false, 1>,
                         cudaFuncAttributeMaxDynamicSharedMemorySize, GEMM_SMEM);
    cudaFuncSetAttribute(gemm2_head_kernel,
                         cudaFuncAttributeMaxDynamicSharedMemorySize, GEMM_SMEM);

    // Prep: x->fp16 + bias concat + all weight splits, one launch
    prep_kernel<<<5376, 256>>>(x, xh, pb1, sb1, bias_l1,
                               pw1, sw1, pw2, pw3, pw4, wt_hi, wt_lo);

    // L1 (pw1 + sw1 merged, AEX, mixed epilogue)
    gemm_h<true, 2><<<dim3((HP + HS) / 128, BB / 128), 256, GEMM_SMEM>>>(
        xh, nullptr, wt_hi, wt_lo, bias_l1, a_hi, a_lo, s1, DD, HP);

    // gemm2 FUSED with selector head (head fills tail waves)
    gemm2_head_kernel<<<dim3(HP / 128, BB / 128 + 32), 256, GEMM_SMEM>>>(
        a_hi, a_lo, wt_hi + OF_PW2, wt_lo + OF_PW2, pb2, b_hi, b_lo,
        s1, sw2, sb2, out_P);

    // gemm3, gemm4
    gemm_h<false, 0><<<dim3(HP / 128, BB / 128), 256, GEMM_SMEM>>>(
        b_hi, b_lo, wt_hi + OF_PW3, wt_lo + OF_PW3, pb3, a_hi, a_lo, nullptr,
        HP, HP);
    gemm_h<false, 1><<<dim3(DD / 128, BB / 128), 256, GEMM_SMEM>>>(
        a_hi, a_lo, wt_hi + OF_PW4, wt_lo + OF_PW4, pb4, nullptr, nullptr,
        out_W, HP, DD);

    // Fused tail (+ truth passthrough)
    finalize_kernel<<<BB, NN>>>(x, out_P, out_W, truth, out_truth, out_xcf);
}